// round 2
// baseline (speedup 1.0000x reference)
#include <cuda_runtime.h>
#include <cuda_bf16.h>
#include <mma.h>

using namespace nvcuda;

#define Bb 8
#define Hh 4
#define LQ 1024
#define LK 4096
#define Dm 256
#define HD 1024

// ---------------- scratch (device globals; no allocations) ----------------
__device__ float g_Xq[Bb * LQ * Dm];                      //  8 MB
__device__ float g_Xk[Bb * LK * Dm];                      // 32 MB
__device__ float g_Xv[Bb * LK * Dm];                      // 32 MB
__device__ float g_Qh[Bb * Hh * LQ * Dm];                 // 32 MB
__device__ float g_Kh[Bb * Hh * LK * Dm];                 // 128 MB
__device__ float g_Vh[Bb * Hh * LK * Dm];                 // 128 MB
__device__ __nv_bfloat16 g_S[(size_t)Bb * Hh * LQ * LK];  // 268 MB
__device__ __nv_bfloat16 g_O[(size_t)Bb * LQ * HD];       // 16 MB

// ---------------- prep: [L,B,D] -> [B,L,D], optional add ----------------
__global__ void prep_kernel(const float* __restrict__ in1,
                            const float* __restrict__ in2, int L, int sel) {
    float* out = (sel == 0) ? g_Xq : (sel == 1) ? g_Xk : g_Xv;
    int idx = blockIdx.x * blockDim.x + threadIdx.x;  // float4 index
    int d4 = idx & 63;          // D/4 = 64
    int m = idx >> 6;           // b*L + l
    int b = m / L;
    int l = m - b * L;
    float4 v = ((const float4*)in1)[((size_t)l * Bb + b) * 64 + d4];
    if (in2) {
        float4 w = ((const float4*)in2)[((size_t)l * Bb + b) * 64 + d4];
        v.x += w.x; v.y += w.y; v.z += w.z; v.w += w.w;
    }
    ((float4*)out)[idx] = v;
}

// ---------------- projection GEMM (tf32): Out[b,h,l,e] = X[b,l,:] . W[h*256+e,:]
__global__ __launch_bounds__(256) void proj_tf32(int sel, int L,
                                                 const float* __restrict__ W) {
    const float* X = (sel == 0) ? g_Xq : (sel == 1) ? g_Xk : g_Xv;
    float* Out = (sel == 0) ? g_Qh : (sel == 1) ? g_Kh : g_Vh;

    __shared__ float As[128][36];
    __shared__ float Bs[128][36];

    int m0 = blockIdx.x * 128, n0 = blockIdx.y * 128;
    int tid = threadIdx.x, wid = tid >> 5;
    int wm = wid & 1, wn = wid >> 1;

    wmma::fragment<wmma::accumulator, 16, 16, 8, float> c[4][2];
#pragma unroll
    for (int i = 0; i < 4; i++)
#pragma unroll
        for (int j = 0; j < 2; j++) wmma::fill_fragment(c[i][j], 0.0f);

    for (int kc = 0; kc < 256; kc += 32) {
        int r = tid >> 3, c4 = (tid & 7) << 2;
#pragma unroll
        for (int p = 0; p < 4; p++) {
            *(float4*)&As[r + p * 32][c4] =
                *(const float4*)&X[(size_t)(m0 + r + p * 32) * 256 + kc + c4];
            *(float4*)&Bs[r + p * 32][c4] =
                *(const float4*)&W[(size_t)(n0 + r + p * 32) * 256 + kc + c4];
        }
        __syncthreads();
#pragma unroll
        for (int ks = 0; ks < 4; ks++) {
            wmma::fragment<wmma::matrix_b, 16, 16, 8, wmma::precision::tf32,
                           wmma::col_major> bf[2];
#pragma unroll
            for (int j = 0; j < 2; j++) {
                wmma::load_matrix_sync(bf[j], &Bs[wn * 32 + j * 16][ks * 8], 36);
#pragma unroll
                for (int t = 0; t < bf[j].num_elements; t++)
                    bf[j].x[t] = wmma::__float_to_tf32(bf[j].x[t]);
            }
#pragma unroll
            for (int i = 0; i < 4; i++) {
                wmma::fragment<wmma::matrix_a, 16, 16, 8, wmma::precision::tf32,
                               wmma::row_major> af;
                wmma::load_matrix_sync(af, &As[wm * 64 + i * 16][ks * 8], 36);
#pragma unroll
                for (int t = 0; t < af.num_elements; t++)
                    af.x[t] = wmma::__float_to_tf32(af.x[t]);
#pragma unroll
                for (int j = 0; j < 2; j++)
                    wmma::mma_sync(c[i][j], af, bf[j], c[i][j]);
            }
        }
        __syncthreads();
    }

    int b = m0 / L, l0 = m0 % L, h = n0 >> 8, e0 = n0 & 255;
    float* Op = Out + (((size_t)(b * Hh + h) * L + l0) * 256 + e0);
#pragma unroll
    for (int i = 0; i < 4; i++)
#pragma unroll
        for (int j = 0; j < 2; j++)
            wmma::store_matrix_sync(
                Op + (size_t)(wm * 64 + i * 16) * 256 + wn * 32 + j * 16,
                c[i][j], 256, wmma::mem_row_major);
}

// ---------------- S = scale * Qh Kh^T  (tf32), + fp32 head-mean ----------------
__global__ __launch_bounds__(256) void attn_s_kernel(float* __restrict__ attn_mean) {
    __shared__ float As[128][36];
    __shared__ float Bs[128][36];
    __shared__ float stage[8][16][20];

    int q0 = blockIdx.x * 128, k0 = blockIdx.y * 128, bb = blockIdx.z;
    int tid = threadIdx.x, wid = tid >> 5, lane = tid & 31;
    int wm = wid & 1, wn = wid >> 1;

    const float SC = 0.0625f;         // 1/sqrt(256)
    const float MSC = 0.015625f;      // SC / 4 heads

    wmma::fragment<wmma::accumulator, 16, 16, 8, float> c[4][2], mn[4][2];
#pragma unroll
    for (int i = 0; i < 4; i++)
#pragma unroll
        for (int j = 0; j < 2; j++) wmma::fill_fragment(mn[i][j], 0.0f);

    for (int h = 0; h < Hh; h++) {
#pragma unroll
        for (int i = 0; i < 4; i++)
#pragma unroll
            for (int j = 0; j < 2; j++) wmma::fill_fragment(c[i][j], 0.0f);

        const float* Qp = g_Qh + (size_t)(bb * Hh + h) * LQ * 256;
        const float* Kp = g_Kh + (size_t)(bb * Hh + h) * LK * 256;

        for (int kc = 0; kc < 256; kc += 32) {
            int r = tid >> 3, c4 = (tid & 7) << 2;
#pragma unroll
            for (int p = 0; p < 4; p++) {
                *(float4*)&As[r + p * 32][c4] =
                    *(const float4*)&Qp[(size_t)(q0 + r + p * 32) * 256 + kc + c4];
                *(float4*)&Bs[r + p * 32][c4] =
                    *(const float4*)&Kp[(size_t)(k0 + r + p * 32) * 256 + kc + c4];
            }
            __syncthreads();
#pragma unroll
            for (int ks = 0; ks < 4; ks++) {
                wmma::fragment<wmma::matrix_b, 16, 16, 8, wmma::precision::tf32,
                               wmma::col_major> bf[2];
#pragma unroll
                for (int j = 0; j < 2; j++) {
                    wmma::load_matrix_sync(bf[j], &Bs[wn * 32 + j * 16][ks * 8], 36);
#pragma unroll
                    for (int t = 0; t < bf[j].num_elements; t++)
                        bf[j].x[t] = wmma::__float_to_tf32(bf[j].x[t]);
                }
#pragma unroll
                for (int i = 0; i < 4; i++) {
                    wmma::fragment<wmma::matrix_a, 16, 16, 8, wmma::precision::tf32,
                                   wmma::row_major> af;
                    wmma::load_matrix_sync(af, &As[wm * 64 + i * 16][ks * 8], 36);
#pragma unroll
                    for (int t = 0; t < af.num_elements; t++)
                        af.x[t] = wmma::__float_to_tf32(af.x[t]);
#pragma unroll
                    for (int j = 0; j < 2; j++)
                        wmma::mma_sync(c[i][j], af, bf[j], c[i][j]);
                }
            }
            __syncthreads();
        }

        // write S (bf16) + accumulate mean
        __nv_bfloat16* Sp = g_S + ((size_t)(bb * Hh + h) * LQ + q0) * LK + k0;
#pragma unroll
        for (int i = 0; i < 4; i++)
#pragma unroll
            for (int j = 0; j < 2; j++) {
#pragma unroll
                for (int t = 0; t < c[i][j].num_elements; t++)
                    mn[i][j].x[t] += c[i][j].x[t];
                wmma::store_matrix_sync(&stage[wid][0][0], c[i][j], 20,
                                        wmma::mem_row_major);
                __syncwarp();
                int r = lane >> 1, cb = (lane & 1) * 8;
                __nv_bfloat162* dst = (__nv_bfloat162*)(Sp +
                    (size_t)(wm * 64 + i * 16 + r) * LK + wn * 32 + j * 16 + cb);
#pragma unroll
                for (int t = 0; t < 4; t++)
                    dst[t] = __floats2bfloat162_rn(stage[wid][r][cb + 2 * t] * SC,
                                                   stage[wid][r][cb + 2 * t + 1] * SC);
                __syncwarp();
            }
    }

    // write attn_mean (fp32, direct output)
    float* Mp = attn_mean + ((size_t)bb * LQ + q0) * LK + k0;
#pragma unroll
    for (int i = 0; i < 4; i++)
#pragma unroll
        for (int j = 0; j < 2; j++) {
            wmma::store_matrix_sync(&stage[wid][0][0], mn[i][j], 20,
                                    wmma::mem_row_major);
            __syncwarp();
            int r = lane >> 1, cb = (lane & 1) * 8;
            float* dd = Mp + (size_t)(wm * 64 + i * 16 + r) * LK +
                        wn * 32 + j * 16 + cb;
            float4 u0, u1;
            u0.x = stage[wid][r][cb + 0] * MSC; u0.y = stage[wid][r][cb + 1] * MSC;
            u0.z = stage[wid][r][cb + 2] * MSC; u0.w = stage[wid][r][cb + 3] * MSC;
            u1.x = stage[wid][r][cb + 4] * MSC; u1.y = stage[wid][r][cb + 5] * MSC;
            u1.z = stage[wid][r][cb + 6] * MSC; u1.w = stage[wid][r][cb + 7] * MSC;
            *(float4*)dd = u0;
            *(float4*)(dd + 4) = u1;
            __syncwarp();
        }
}

// ---------------- row softmax over k (4096), bf16 in-place ----------------
__global__ void softmax_kernel() {
    size_t row = blockIdx.x;
    __nv_bfloat162* p = (__nv_bfloat162*)(g_S + row * LK);
    int tid = threadIdx.x, wid = tid >> 5, lane = tid & 31;

    float2 v[16];
    float mx = -1e30f;
#pragma unroll
    for (int i = 0; i < 16; i++) {
        __nv_bfloat162 t = p[tid + i * 128];
        v[i].x = __bfloat162float(t.x);
        v[i].y = __bfloat162float(t.y);
        mx = fmaxf(mx, fmaxf(v[i].x, v[i].y));
    }
#pragma unroll
    for (int o = 16; o > 0; o >>= 1) mx = fmaxf(mx, __shfl_xor_sync(~0u, mx, o));
    __shared__ float rm[4], rs[4];
    if (lane == 0) rm[wid] = mx;
    __syncthreads();
    mx = fmaxf(fmaxf(rm[0], rm[1]), fmaxf(rm[2], rm[3]));

    float s = 0.f;
#pragma unroll
    for (int i = 0; i < 16; i++) {
        v[i].x = __expf(v[i].x - mx);
        v[i].y = __expf(v[i].y - mx);
        s += v[i].x + v[i].y;
    }
#pragma unroll
    for (int o = 16; o > 0; o >>= 1) s += __shfl_xor_sync(~0u, s, o);
    if (lane == 0) rs[wid] = s;
    __syncthreads();
    s = rs[0] + rs[1] + rs[2] + rs[3];
    float inv = 1.0f / s;
#pragma unroll
    for (int i = 0; i < 16; i++)
        p[tid + i * 128] = __floats2bfloat162_rn(v[i].x * inv, v[i].y * inv);
}

// ---------------- O = P @ Vh  (bf16), store to O_cat[b*LQ+q][h*256+e] ----------------
__global__ __launch_bounds__(256) void pv_kernel() {
    __shared__ __nv_bfloat16 As[128][48];
    __shared__ __nv_bfloat16 Bs[32][136];
    __shared__ float stage[8][16][20];

    int q0 = blockIdx.x * 128, n0 = blockIdx.y * 128, bh = blockIdx.z;
    int tid = threadIdx.x, wid = tid >> 5, lane = tid & 31;
    int wm = wid & 1, wn = wid >> 1;

    const __nv_bfloat16* Pp = g_S + (size_t)bh * LQ * LK + (size_t)q0 * LK;
    const float* Vp = g_Vh + (size_t)bh * LK * 256;

    wmma::fragment<wmma::accumulator, 16, 16, 16, float> c[4][2];
#pragma unroll
    for (int i = 0; i < 4; i++)
#pragma unroll
        for (int j = 0; j < 2; j++) wmma::fill_fragment(c[i][j], 0.0f);

    for (int kc = 0; kc < LK; kc += 32) {
        int r = tid >> 2, cb = (tid & 3) << 3;
#pragma unroll
        for (int p = 0; p < 2; p++)
            *(uint4*)&As[r + p * 64][cb] =
                *(const uint4*)&Pp[(size_t)(r + p * 64) * LK + kc + cb];
        int r2 = tid >> 5, c4 = (tid & 31) << 2;
#pragma unroll
        for (int p = 0; p < 4; p++) {
            float4 w = *(const float4*)&Vp[(size_t)(kc + r2 + p * 8) * 256 + n0 + c4];
            *(__nv_bfloat162*)&Bs[r2 + p * 8][c4] = __floats2bfloat162_rn(w.x, w.y);
            *(__nv_bfloat162*)&Bs[r2 + p * 8][c4 + 2] = __floats2bfloat162_rn(w.z, w.w);
        }
        __syncthreads();
#pragma unroll
        for (int ks = 0; ks < 2; ks++) {
            wmma::fragment<wmma::matrix_b, 16, 16, 16, __nv_bfloat16,
                           wmma::row_major> bf[2];
#pragma unroll
            for (int j = 0; j < 2; j++)
                wmma::load_matrix_sync(bf[j], &Bs[ks * 16][wn * 32 + j * 16], 136);
#pragma unroll
            for (int i = 0; i < 4; i++) {
                wmma::fragment<wmma::matrix_a, 16, 16, 16, __nv_bfloat16,
                               wmma::row_major> af;
                wmma::load_matrix_sync(af, &As[wm * 64 + i * 16][ks * 16], 48);
#pragma unroll
                for (int j = 0; j < 2; j++)
                    wmma::mma_sync(c[i][j], af, bf[j], c[i][j]);
            }
        }
        __syncthreads();
    }

    int b = bh >> 2, h = bh & 3;
    __nv_bfloat16* Op = g_O + (size_t)(b * LQ + q0) * HD + h * 256 + n0;
#pragma unroll
    for (int i = 0; i < 4; i++)
#pragma unroll
        for (int j = 0; j < 2; j++) {
            wmma::store_matrix_sync(&stage[wid][0][0], c[i][j], 20,
                                    wmma::mem_row_major);
            __syncwarp();
            int r = lane >> 1, cb = (lane & 1) * 8;
            __nv_bfloat162* dst = (__nv_bfloat162*)(Op +
                (size_t)(wm * 64 + i * 16 + r) * HD + wn * 32 + j * 16 + cb);
#pragma unroll
            for (int t = 0; t < 4; t++)
                dst[t] = __floats2bfloat162_rn(stage[wid][r][cb + 2 * t],
                                               stage[wid][r][cb + 2 * t + 1]);
            __syncwarp();
        }
}

// ---------------- fc + residual + LayerNorm ----------------
__global__ __launch_bounds__(256) void fc_ln_kernel(const float* __restrict__ Wfc,
                                                    const float* __restrict__ tgt,
                                                    const float* __restrict__ gamma,
                                                    const float* __restrict__ beta,
                                                    float* __restrict__ Y) {
    __shared__ __align__(16) unsigned char smraw[33280];
    __nv_bfloat16* As = (__nv_bfloat16*)smraw;             // [32][48]
    __nv_bfloat16* Bsh = (__nv_bfloat16*)(smraw + 3072);   // [256][48]
    float* stage = (float*)smraw;                          // [32][260]

    int m0 = blockIdx.x * 32;
    int tid = threadIdx.x, wid = tid >> 5, lane = tid & 31;
    int wm = wid & 1, wn = wid >> 1;

    wmma::fragment<wmma::accumulator, 16, 16, 16, float> c[4];
#pragma unroll
    for (int j = 0; j < 4; j++) wmma::fill_fragment(c[j], 0.0f);

    for (int kc = 0; kc < HD; kc += 32) {
        int r = tid >> 3, cb = (tid & 7) << 2;
        *(uint2*)&As[r * 48 + cb] =
            *(const uint2*)&g_O[(size_t)(m0 + r) * HD + kc + cb];
#pragma unroll
        for (int p = 0; p < 8; p++) {
            int rr = r + p * 32;  // 0..255
            float4 w = *(const float4*)&Wfc[(size_t)rr * HD + kc + cb];
            *(__nv_bfloat162*)&Bsh[rr * 48 + cb] = __floats2bfloat162_rn(w.x, w.y);
            *(__nv_bfloat162*)&Bsh[rr * 48 + cb + 2] = __floats2bfloat162_rn(w.z, w.w);
        }
        __syncthreads();
#pragma unroll
        for (int ks = 0; ks < 2; ks++) {
            wmma::fragment<wmma::matrix_a, 16, 16, 16, __nv_bfloat16,
                           wmma::row_major> af;
            wmma::load_matrix_sync(af, &As[(wm * 16) * 48 + ks * 16], 48);
#pragma unroll
            for (int j = 0; j < 4; j++) {
                wmma::fragment<wmma::matrix_b, 16, 16, 16, __nv_bfloat16,
                               wmma::col_major> bfr;
                wmma::load_matrix_sync(bfr, &Bsh[(wn * 64 + j * 16) * 48 + ks * 16], 48);
                wmma::mma_sync(c[j], af, bfr, c[j]);
            }
        }
        __syncthreads();
    }

    // stage accumulators (reuses load smem; protected by final __syncthreads above)
#pragma unroll
    for (int j = 0; j < 4; j++)
        wmma::store_matrix_sync(&stage[(wm * 16) * 260 + wn * 64 + j * 16], c[j],
                                260, wmma::mem_row_major);
    __syncthreads();

    // residual + LayerNorm: each warp handles 4 rows
#pragma unroll
    for (int s = 0; s < 4; s++) {
        int row = wid * 4 + s;
        int m = m0 + row;
        int b = m >> 10, l = m & 1023;
        const float* trow = tgt + ((size_t)l * Bb + b) * 256;
        float v[8], sum = 0.f, sq = 0.f;
#pragma unroll
        for (int t = 0; t < 8; t++) {
            v[t] = stage[row * 260 + lane * 8 + t] + trow[lane * 8 + t];
            sum += v[t];
            sq += v[t] * v[t];
        }
#pragma unroll
        for (int o = 16; o > 0; o >>= 1) {
            sum += __shfl_xor_sync(~0u, sum, o);
            sq += __shfl_xor_sync(~0u, sq, o);
        }
        float mu = sum * (1.0f / 256.0f);
        float var = sq * (1.0f / 256.0f) - mu * mu;
        float rsg = rsqrtf(var + 1e-5f);
        float* yr = Y + ((size_t)l * Bb + b) * 256;
#pragma unroll
        for (int t = 0; t < 8; t++) {
            int d = lane * 8 + t;
            yr[d] = (v[t] - mu) * rsg * gamma[d] + beta[d];
        }
    }
}

// ---------------- launch ----------------
extern "C" void kernel_launch(void* const* d_in, const int* in_sizes, int n_in,
                              void* d_out, int out_size) {
    const float* tgt   = (const float*)d_in[0];
    const float* mem   = (const float*)d_in[1];
    const float* pos   = (const float*)d_in[2];
    const float* qpos  = (const float*)d_in[3];
    const float* Wq    = (const float*)d_in[4];
    const float* Wk    = (const float*)d_in[5];
    const float* Wv    = (const float*)d_in[6];
    const float* Wfc   = (const float*)d_in[7];
    const float* ln_g  = (const float*)d_in[8];
    const float* ln_b  = (const float*)d_in[9];

    float* y_out    = (float*)d_out;                       // [LQ,B,D]
    float* attn_out = (float*)d_out + (size_t)LQ * Bb * Dm;  // [B,1,LQ,LK]

    // prep: transpose(+add) into [B,L,D]
    prep_kernel<<<(Bb * LQ * 64) / 256, 256>>>(tgt, qpos, LQ, 0);
    prep_kernel<<<(Bb * LK * 64) / 256, 256>>>(mem, pos, LK, 1);
    prep_kernel<<<(Bb * LK * 64) / 256, 256>>>(mem, nullptr, LK, 2);

    // projections (tf32)
    proj_tf32<<<dim3(Bb * LQ / 128, HD / 128), 256>>>(0, LQ, Wq);
    proj_tf32<<<dim3(Bb * LK / 128, HD / 128), 256>>>(1, LK, Wk);
    proj_tf32<<<dim3(Bb * LK / 128, HD / 128), 256>>>(2, LK, Wv);

    // logits + head-mean
    attn_s_kernel<<<dim3(LQ / 128, LK / 128, Bb), 256>>>(attn_out);

    // softmax over k
    softmax_kernel<<<Bb * Hh * LQ, 128>>>();

    // attention output
    pv_kernel<<<dim3(LQ / 128, Dm / 128, Bb * Hh), 256>>>();

    // fc + residual + layernorm
    fc_ln_kernel<<<(Bb * LQ) / 32, 256>>>(Wfc, tgt, ln_g, ln_b, y_out);
}

// round 6
// speedup vs baseline: 1.1187x; 1.1187x over previous
#include <cuda_runtime.h>
#include <cuda_bf16.h>
#include <cuda_fp16.h>
#include <cstdint>
#include <cstddef>
#include <mma.h>

using namespace nvcuda;

#define Bb 8
#define Hh 4
#define LQ 1024
#define LK 4096
#define Dm 256
#define HD 1024

// ---------------- scratch (device globals; no allocations) ----------------
__device__ float g_Qf[(size_t)Bb * LQ * HD];          //  32 MB  [B,Lq,1024]
__device__ float g_Kf[(size_t)Bb * LK * HD];          // 128 MB  [B,Lk,1024]
__device__ __half g_Q16[(size_t)Bb * Hh * LQ * Dm];   //  16 MB  [B,H,Lq,256]
__device__ __half g_K16[(size_t)Bb * Hh * LK * Dm];   //  64 MB
__device__ __half g_V16[(size_t)Bb * Hh * LK * Dm];   //  64 MB
__device__ __half g_O[(size_t)Bb * LQ * HD];          //  16 MB  [B*Lq, H*256]

// ---------------- PTX helpers ----------------
__device__ __forceinline__ float ex2f(float x) {
    float r;
    asm("ex2.approx.ftz.f32 %0, %1;" : "=f"(r) : "f"(x));
    return r;
}
__device__ __forceinline__ void ldsm4(uint32_t& a0, uint32_t& a1, uint32_t& a2,
                                      uint32_t& a3, uint32_t addr) {
    asm volatile("ldmatrix.sync.aligned.m8n8.x4.shared.b16 {%0,%1,%2,%3},[%4];"
                 : "=r"(a0), "=r"(a1), "=r"(a2), "=r"(a3) : "r"(addr));
}
__device__ __forceinline__ void ldsm2(uint32_t& a0, uint32_t& a1, uint32_t addr) {
    asm volatile("ldmatrix.sync.aligned.m8n8.x2.shared.b16 {%0,%1},[%2];"
                 : "=r"(a0), "=r"(a1) : "r"(addr));
}
__device__ __forceinline__ void ldsm2t(uint32_t& a0, uint32_t& a1, uint32_t addr) {
    asm volatile("ldmatrix.sync.aligned.m8n8.x2.trans.shared.b16 {%0,%1},[%2];"
                 : "=r"(a0), "=r"(a1) : "r"(addr));
}
__device__ __forceinline__ void mma16816(float* d, uint32_t a0, uint32_t a1,
                                         uint32_t a2, uint32_t a3, uint32_t b0,
                                         uint32_t b1) {
    asm volatile(
        "mma.sync.aligned.m16n8k16.row.col.f32.f16.f16.f32 "
        "{%0,%1,%2,%3},{%4,%5,%6,%7},{%8,%9},{%0,%1,%2,%3};"
        : "+f"(d[0]), "+f"(d[1]), "+f"(d[2]), "+f"(d[3])
        : "r"(a0), "r"(a1), "r"(a2), "r"(a3), "r"(b0), "r"(b1));
}
__device__ __forceinline__ void cp16(uint32_t dst, const void* src) {
    asm volatile("cp.async.cg.shared.global [%0],[%1],16;" ::"r"(dst), "l"(src)
                 : "memory");
}
#define CP_COMMIT asm volatile("cp.async.commit_group;" ::: "memory")

// ---------------- proj (tf32): fused transpose+add input, dual output ----------------
__global__ __launch_bounds__(256) void proj_kernel(const float* __restrict__ in1,
                                                   const float* __restrict__ in2,
                                                   int L,
                                                   const float* __restrict__ W,
                                                   int sel) {
    float* f32out = (sel == 0) ? g_Qf : (sel == 1) ? g_Kf : (float*)0;
    __half* f16out = (sel == 0) ? g_Q16 : (sel == 1) ? g_K16 : g_V16;

    __shared__ float As[128][36];
    __shared__ float Bs[128][36];
    __shared__ float stage[8][16][20];

    int m0 = blockIdx.x * 128, n0 = blockIdx.y * 128;
    int b = m0 / L, l0 = m0 % L;
    int tid = threadIdx.x, wid = tid >> 5, lane = tid & 31;
    int wm = wid & 1, wn = wid >> 1;

    wmma::fragment<wmma::accumulator, 16, 16, 8, float> c[4][2];
#pragma unroll
    for (int i = 0; i < 4; i++)
#pragma unroll
        for (int j = 0; j < 2; j++) wmma::fill_fragment(c[i][j], 0.0f);

    for (int kc = 0; kc < 256; kc += 32) {
        int r = tid >> 3, c4 = (tid & 7) << 2;
#pragma unroll
        for (int p = 0; p < 4; p++) {
            int l = l0 + r + p * 32;
            float4 v = *(const float4*)&in1[((size_t)l * Bb + b) * 256 + kc + c4];
            if (in2) {
                float4 w = *(const float4*)&in2[((size_t)l * Bb + b) * 256 + kc + c4];
                v.x += w.x; v.y += w.y; v.z += w.z; v.w += w.w;
            }
            *(float4*)&As[r + p * 32][c4] = v;
            *(float4*)&Bs[r + p * 32][c4] =
                *(const float4*)&W[(size_t)(n0 + r + p * 32) * 256 + kc + c4];
        }
        __syncthreads();
#pragma unroll
        for (int ks = 0; ks < 4; ks++) {
            wmma::fragment<wmma::matrix_b, 16, 16, 8, wmma::precision::tf32,
                           wmma::col_major> bf[2];
#pragma unroll
            for (int j = 0; j < 2; j++) {
                wmma::load_matrix_sync(bf[j], &Bs[wn * 32 + j * 16][ks * 8], 36);
#pragma unroll
                for (int t = 0; t < bf[j].num_elements; t++)
                    bf[j].x[t] = wmma::__float_to_tf32(bf[j].x[t]);
            }
#pragma unroll
            for (int i = 0; i < 4; i++) {
                wmma::fragment<wmma::matrix_a, 16, 16, 8, wmma::precision::tf32,
                               wmma::row_major> af;
                wmma::load_matrix_sync(af, &As[wm * 64 + i * 16][ks * 8], 36);
#pragma unroll
                for (int t = 0; t < af.num_elements; t++)
                    af.x[t] = wmma::__float_to_tf32(af.x[t]);
#pragma unroll
                for (int j = 0; j < 2; j++)
                    wmma::mma_sync(c[i][j], af, bf[j], c[i][j]);
            }
        }
        __syncthreads();
    }

    int h = n0 >> 8, e0 = n0 & 255;
#pragma unroll
    for (int i = 0; i < 4; i++)
#pragma unroll
        for (int j = 0; j < 2; j++) {
            if (f32out)
                wmma::store_matrix_sync(
                    f32out + ((size_t)b * L + l0 + wm * 64 + i * 16) * HD + n0 +
                        wn * 32 + j * 16,
                    c[i][j], HD, wmma::mem_row_major);
            wmma::store_matrix_sync(&stage[wid][0][0], c[i][j], 20,
                                    wmma::mem_row_major);
            __syncwarp();
            int rr = lane >> 1, cb = (lane & 1) * 8;
            __half2* dst = (__half2*)(f16out +
                ((size_t)(b * Hh + h) * L + l0 + wm * 64 + i * 16 + rr) * 256 +
                e0 + wn * 32 + j * 16 + cb);
#pragma unroll
            for (int t = 0; t < 4; t++)
                dst[t] = __floats2half2_rn(stage[wid][rr][cb + 2 * t],
                                           stage[wid][rr][cb + 2 * t + 1]);
            __syncwarp();
        }
}

// ---------------- attn_mean = (scale/H) Qf Kf^T  (tf32, K=1024, cp.async 2-stage) ----
#define MEAN_SMEM 73728
__global__ __launch_bounds__(256) void mean_kernel(float* __restrict__ out) {
    extern __shared__ __align__(16) char dynsm[];
    float* ms = (float*)dynsm;  // [2 buf][As 4608 | Bs 4608] floats
    int q0 = blockIdx.x * 128, k0 = blockIdx.y * 128, b = blockIdx.z;
    const float* Qp = g_Qf + ((size_t)b * LQ + q0) * HD;
    const float* Kp = g_Kf + ((size_t)b * LK + k0) * HD;
    int tid = threadIdx.x, wid = tid >> 5;
    int wm = wid & 1, wn = wid >> 1;
    uint32_t sb = (uint32_t)__cvta_generic_to_shared(ms);

    wmma::fragment<wmma::accumulator, 16, 16, 8, float> c[4][2];
#pragma unroll
    for (int i = 0; i < 4; i++)
#pragma unroll
        for (int j = 0; j < 2; j++) wmma::fill_fragment(c[i][j], 0.0f);

    int r = tid >> 3, c4 = (tid & 7) << 2;
#pragma unroll
    for (int pre = 0; pre < 2; pre++) {
        int kc = pre * 32;
#pragma unroll
        for (int p = 0; p < 4; p++) {
            int row = r + p * 32;
            cp16(sb + (pre * 9216 + row * 36 + c4) * 4,
                 Qp + (size_t)row * HD + kc + c4);
            cp16(sb + (pre * 9216 + 4608 + row * 36 + c4) * 4,
                 Kp + (size_t)row * HD + kc + c4);
        }
        CP_COMMIT;
    }

    for (int ic = 0; ic < 32; ic++) {
        int cur = ic & 1;
        if (ic < 31)
            asm volatile("cp.async.wait_group 1;" ::: "memory");
        else
            asm volatile("cp.async.wait_group 0;" ::: "memory");
        __syncthreads();
        float* Asb = ms + cur * 9216;
        float* Bsb = Asb + 4608;
#pragma unroll
        for (int ks = 0; ks < 4; ks++) {
            wmma::fragment<wmma::matrix_b, 16, 16, 8, wmma::precision::tf32,
                           wmma::col_major> bf[2];
#pragma unroll
            for (int j = 0; j < 2; j++) {
                wmma::load_matrix_sync(bf[j], &Bsb[(wn * 32 + j * 16) * 36 + ks * 8], 36);
#pragma unroll
                for (int t = 0; t < bf[j].num_elements; t++)
                    bf[j].x[t] = wmma::__float_to_tf32(bf[j].x[t]);
            }
#pragma unroll
            for (int i = 0; i < 4; i++) {
                wmma::fragment<wmma::matrix_a, 16, 16, 8, wmma::precision::tf32,
                               wmma::row_major> af;
                wmma::load_matrix_sync(af, &Asb[(wm * 64 + i * 16) * 36 + ks * 8], 36);
#pragma unroll
                for (int t = 0; t < af.num_elements; t++)
                    af.x[t] = wmma::__float_to_tf32(af.x[t]);
#pragma unroll
                for (int j = 0; j < 2; j++)
                    wmma::mma_sync(c[i][j], af, bf[j], c[i][j]);
            }
        }
        __syncthreads();
        if (ic + 2 < 32) {
            int kc = (ic + 2) * 32;
#pragma unroll
            for (int p = 0; p < 4; p++) {
                int row = r + p * 32;
                cp16(sb + (cur * 9216 + row * 36 + c4) * 4,
                     Qp + (size_t)row * HD + kc + c4);
                cp16(sb + (cur * 9216 + 4608 + row * 36 + c4) * 4,
                     Kp + (size_t)row * HD + kc + c4);
            }
        }
        CP_COMMIT;
    }

    const float MSC = 0.015625f;  // (1/16)/4
#pragma unroll
    for (int i = 0; i < 4; i++)
#pragma unroll
        for (int j = 0; j < 2; j++) {
#pragma unroll
            for (int t = 0; t < c[i][j].num_elements; t++) c[i][j].x[t] *= MSC;
            wmma::store_matrix_sync(
                out + ((size_t)b * LQ + q0 + wm * 64 + i * 16) * LK + k0 +
                    wn * 32 + j * 16,
                c[i][j], LK, wmma::mem_row_major);
        }
}

// ---------------- flash attention (f16 mma, QT=64, KT=64, 2-stage cp.async) --------
#define FLASH_SMEM 179200
#define OF_Q 0
#define OF_K 33792
#define OF_V 101376
#define OF_P 168960
#define OF_RM 178176
#define OF_RL 178688
#define KROW 528  // bytes per 256-half row (+16B pad)

__device__ __forceinline__ void load_tile64(uint32_t dst, const __half* src,
                                            int tid) {
#pragma unroll
    for (int i = 0; i < 8; i++) {
        int t = tid + i * 256;
        int row = t >> 5, cc = t & 31;
        cp16(dst + row * KROW + cc * 16, src + (size_t)row * 256 + cc * 8);
    }
}

__global__ __launch_bounds__(256, 1) void flash_kernel() {
    extern __shared__ __align__(16) char dynsm[];
    char* sm = dynsm;
    int tid = threadIdx.x, lane = tid & 31, wid = tid >> 5;
    int wm = wid >> 1, wn = wid & 1;
    int q0 = blockIdx.x * 64;
    int bh = blockIdx.y;
    int b = bh >> 2, h = bh & 3;
    const __half* Qg = g_Q16 + ((size_t)bh * LQ + q0) * 256;
    const __half* Kg = g_K16 + (size_t)bh * LK * 256;
    const __half* Vg = g_V16 + (size_t)bh * LK * 256;

    uint32_t sb = (uint32_t)__cvta_generic_to_shared(sm);
    const uint32_t QB = sb + OF_Q, KB = sb + OF_K, VB = sb + OF_V, PB = sb + OF_P;
    float* redm = (float*)(sm + OF_RM);
    float* redl = (float*)(sm + OF_RL);

    load_tile64(QB, Qg, tid);
    load_tile64(KB, Kg, tid);
    load_tile64(VB, Vg, tid);
    CP_COMMIT;
    load_tile64(KB + 33792, Kg + 64 * 256, tid);
    load_tile64(VB + 33792, Vg + 64 * 256, tid);
    CP_COMMIT;

    float o[16][4];
#pragma unroll
    for (int j = 0; j < 16; j++) o[j][0] = o[j][1] = o[j][2] = o[j][3] = 0.f;
    float mr0 = -1e30f, mr1 = -1e30f, l0 = 0.f, l1 = 0.f;
    const float SLOG = 0.0901699438f;  // (1/16)*log2(e)
    int r0 = lane >> 2;
    int row0 = wm * 16 + r0, row1 = row0 + 8;

    const uint32_t Aq = QB + ((wm * 16 + (lane & 15)) * 264 + ((lane >> 4) << 3)) * 2;
    const uint32_t Ap = PB + ((wm * 16 + (lane & 15)) * 72 + ((lane >> 4) << 3)) * 2;
    const uint32_t KbOff = (wn * 32 + (lane & 7)) * KROW + (((lane >> 3) & 1) << 4);

    for (int it = 0; it < LK / 64; it++) {
        int cur = it & 1;
        if (it < LK / 64 - 1)
            asm volatile("cp.async.wait_group 1;" ::: "memory");
        else
            asm volatile("cp.async.wait_group 0;" ::: "memory");
        __syncthreads();

        uint32_t kb = KB + cur * 33792;
        float s[4][4];
#pragma unroll
        for (int j = 0; j < 4; j++) s[j][0] = s[j][1] = s[j][2] = s[j][3] = 0.f;
#pragma unroll
        for (int dk = 0; dk < 16; dk++) {
            uint32_t a0, a1, a2, a3;
            ldsm4(a0, a1, a2, a3, Aq + dk * 32);
#pragma unroll
            for (int j = 0; j < 4; j++) {
                uint32_t b0, b1;
                ldsm2(b0, b1, kb + KbOff + j * 8 * KROW + dk * 32);
                mma16816(s[j], a0, a1, a2, a3, b0, b1);
            }
        }

        // online softmax
        float pm0 = -1e30f, pm1 = -1e30f;
#pragma unroll
        for (int j = 0; j < 4; j++) {
            s[j][0] *= SLOG; s[j][1] *= SLOG; s[j][2] *= SLOG; s[j][3] *= SLOG;
            pm0 = fmaxf(pm0, fmaxf(s[j][0], s[j][1]));
            pm1 = fmaxf(pm1, fmaxf(s[j][2], s[j][3]));
        }
        pm0 = fmaxf(pm0, __shfl_xor_sync(~0u, pm0, 1));
        pm0 = fmaxf(pm0, __shfl_xor_sync(~0u, pm0, 2));
        pm1 = fmaxf(pm1, __shfl_xor_sync(~0u, pm1, 1));
        pm1 = fmaxf(pm1, __shfl_xor_sync(~0u, pm1, 2));
        if ((lane & 3) == 0) {
            redm[wn * 64 + row0] = pm0;
            redm[wn * 64 + row1] = pm1;
        }
        __syncthreads();
        float mn0 = fmaxf(mr0, fmaxf(redm[row0], redm[64 + row0]));
        float mn1 = fmaxf(mr1, fmaxf(redm[row1], redm[64 + row1]));
        float al0 = ex2f(mr0 - mn0), al1 = ex2f(mr1 - mn1);
        mr0 = mn0; mr1 = mn1;

        float ps0 = 0.f, ps1 = 0.f;
        __half2* Pp = (__half2*)(sm + OF_P);
#pragma unroll
        for (int j = 0; j < 4; j++) {
            float p0 = ex2f(s[j][0] - mn0), p1 = ex2f(s[j][1] - mn0);
            float p2 = ex2f(s[j][2] - mn1), p3 = ex2f(s[j][3] - mn1);
            ps0 += p0 + p1;
            ps1 += p2 + p3;
            int cb = wn * 32 + j * 8 + ((lane & 3) << 1);
            Pp[(row0 * 72 + cb) >> 1] = __floats2half2_rn(p0, p1);
            Pp[(row1 * 72 + cb) >> 1] = __floats2half2_rn(p2, p3);
        }
        ps0 += __shfl_xor_sync(~0u, ps0, 1);
        ps0 += __shfl_xor_sync(~0u, ps0, 2);
        ps1 += __shfl_xor_sync(~0u, ps1, 1);
        ps1 += __shfl_xor_sync(~0u, ps1, 2);
        if ((lane & 3) == 0) {
            redl[wn * 64 + row0] = ps0;
            redl[wn * 64 + row1] = ps1;
        }
#pragma unroll
        for (int j = 0; j < 16; j++) {
            o[j][0] *= al0; o[j][1] *= al0; o[j][2] *= al1; o[j][3] *= al1;
        }
        __syncthreads();
        l0 = al0 * l0 + redl[row0] + redl[64 + row0];
        l1 = al1 * l1 + redl[row1] + redl[64 + row1];

        // O += P @ V
        uint32_t vb = VB + cur * 33792;
#pragma unroll
        for (int kc = 0; kc < 4; kc++) {
            uint32_t a0, a1, a2, a3;
            ldsm4(a0, a1, a2, a3, Ap + kc * 32);
#pragma unroll
            for (int j = 0; j < 16; j++) {
                uint32_t b0, b1;
                ldsm2t(b0, b1, vb + (kc * 16 + (lane & 15)) * KROW +
                                   (wn * 128 + j * 8) * 2);
                mma16816(o[j], a0, a1, a2, a3, b0, b1);
            }
        }
        __syncthreads();
        if (it + 2 < LK / 64) {
            load_tile64(KB + cur * 33792, Kg + (size_t)(it + 2) * 64 * 256, tid);
            load_tile64(VB + cur * 33792, Vg + (size_t)(it + 2) * 64 * 256, tid);
        }
        CP_COMMIT;
    }

    float inv0 = 1.f / l0, inv1 = 1.f / l1;
    size_t ob0 = ((size_t)b * LQ + q0 + row0) * HD + h * 256 + wn * 128 +
                 ((lane & 3) << 1);
    size_t ob1 = ob0 + (size_t)8 * HD;
#pragma unroll
    for (int j = 0; j < 16; j++) {
        *(__half2*)(g_O + ob0 + j * 8) =
            __floats2half2_rn(o[j][0] * inv0, o[j][1] * inv0);
        *(__half2*)(g_O + ob1 + j * 8) =
            __floats2half2_rn(o[j][2] * inv1, o[j][3] * inv1);
    }
}

// ---------------- fc + residual + LayerNorm (f16 GEMM) ----------------
__global__ __launch_bounds__(256) void fc_ln_kernel(const float* __restrict__ Wfc,
                                                    const float* __restrict__ tgt,
                                                    const float* __restrict__ gamma,
                                                    const float* __restrict__ beta,
                                                    float* __restrict__ Y) {
    __shared__ __align__(16) unsigned char smraw[33280];
    __half* As = (__half*)smraw;             // [32][48]
    __half* Bsh = (__half*)(smraw + 3072);   // [256][48]
    float* stage = (float*)smraw;            // [32][260]

    int m0 = blockIdx.x * 32;
    int tid = threadIdx.x, wid = tid >> 5, lane = tid & 31;
    int wm = wid & 1, wn = wid >> 1;

    wmma::fragment<wmma::accumulator, 16, 16, 16, float> c[4];
#pragma unroll
    for (int j = 0; j < 4; j++) wmma::fill_fragment(c[j], 0.0f);

    for (int kc = 0; kc < HD; kc += 32) {
        int r = tid >> 3, cb = (tid & 7) << 2;
        *(uint2*)&As[r * 48 + cb] =
            *(const uint2*)&g_O[(size_t)(m0 + r) * HD + kc + cb];
#pragma unroll
        for (int p = 0; p < 8; p++) {
            int rr = r + p * 32;
            float4 w = *(const float4*)&Wfc[(size_t)rr * HD + kc + cb];
            *(__half2*)&Bsh[rr * 48 + cb] = __floats2half2_rn(w.x, w.y);
            *(__half2*)&Bsh[rr * 48 + cb + 2] = __floats2half2_rn(w.z, w.w);
        }
        __syncthreads();
#pragma unroll
        for (int ks = 0; ks < 2; ks++) {
            wmma::fragment<wmma::matrix_a, 16, 16, 16, __half, wmma::row_major> af;
            wmma::load_matrix_sync(af, &As[(wm * 16) * 48 + ks * 16], 48);
#pragma unroll
            for (int j = 0; j < 4; j++) {
                wmma::fragment<wmma::matrix_b, 16, 16, 16, __half,
                               wmma::col_major> bfr;
                wmma::load_matrix_sync(bfr, &Bsh[(wn * 64 + j * 16) * 48 + ks * 16],
                                       48);
                wmma::mma_sync(c[j], af, bfr, c[j]);
            }
        }
        __syncthreads();
    }

#pragma unroll
    for (int j = 0; j < 4; j++)
        wmma::store_matrix_sync(&stage[(wm * 16) * 260 + wn * 64 + j * 16], c[j],
                                260, wmma::mem_row_major);
    __syncthreads();

#pragma unroll
    for (int s = 0; s < 4; s++) {
        int row = wid * 4 + s;
        int m = m0 + row;
        int b = m >> 10, l = m & 1023;
        const float* trow = tgt + ((size_t)l * Bb + b) * 256;
        float v[8], sum = 0.f, sq = 0.f;
#pragma unroll
        for (int t = 0; t < 8; t++) {
            v[t] = stage[row * 260 + lane * 8 + t] + trow[lane * 8 + t];
            sum += v[t];
            sq += v[t] * v[t];
        }
#pragma unroll
        for (int oo = 16; oo > 0; oo >>= 1) {
            sum += __shfl_xor_sync(~0u, sum, oo);
            sq += __shfl_xor_sync(~0u, sq, oo);
        }
        float mu = sum * (1.0f / 256.0f);
        float var = sq * (1.0f / 256.0f) - mu * mu;
        float rsg = rsqrtf(var + 1e-5f);
        float* yr = Y + ((size_t)l * Bb + b) * 256;
#pragma unroll
        for (int t = 0; t < 8; t++) {
            int d = lane * 8 + t;
            yr[d] = (v[t] - mu) * rsg * gamma[d] + beta[d];
        }
    }
}

// ---------------- launch ----------------
extern "C" void kernel_launch(void* const* d_in, const int* in_sizes, int n_in,
                              void* d_out, int out_size) {
    const float* tgt  = (const float*)d_in[0];
    const float* mem  = (const float*)d_in[1];
    const float* pos  = (const float*)d_in[2];
    const float* qpos = (const float*)d_in[3];
    const float* Wq   = (const float*)d_in[4];
    const float* Wk   = (const float*)d_in[5];
    const float* Wv   = (const float*)d_in[6];
    const float* Wfc  = (const float*)d_in[7];
    const float* ln_g = (const float*)d_in[8];
    const float* ln_b = (const float*)d_in[9];

    float* y_out    = (float*)d_out;                         // [LQ,B,D]
    float* attn_out = (float*)d_out + (size_t)LQ * Bb * Dm;  // [B,1,LQ,LK]

    cudaFuncSetAttribute(flash_kernel,
                         cudaFuncAttributeMaxDynamicSharedMemorySize, FLASH_SMEM);
    cudaFuncSetAttribute(mean_kernel,
                         cudaFuncAttributeMaxDynamicSharedMemorySize, MEAN_SMEM);

    // projections (tf32) with fused transpose+add
    proj_kernel<<<dim3(Bb * LQ / 128, HD / 128), 256>>>(tgt, qpos, LQ, Wq, 0);
    proj_kernel<<<dim3(Bb * LK / 128, HD / 128), 256>>>(mem, pos, LK, Wk, 1);
    proj_kernel<<<dim3(Bb * LK / 128, HD / 128), 256>>>(mem, (const float*)0, LK,
                                                        Wv, 2);

    // attn_mean as single tf32 GEMM over concat heads (K=1024)
    mean_kernel<<<dim3(LQ / 128, LK / 128, Bb), 256, MEAN_SMEM>>>(attn_out);

    // flash attention (f16), writes g_O
    flash_kernel<<<dim3(LQ / 64, Bb * Hh), 256, FLASH_SMEM>>>();

    // fc + residual + layernorm
    fc_ln_kernel<<<(Bb * LQ) / 32, 256>>>(Wfc, tgt, ln_g, ln_b, y_out);
}

// round 8
// speedup vs baseline: 2.0626x; 1.8438x over previous
#include <cuda_runtime.h>
#include <cuda_bf16.h>
#include <cuda_fp16.h>
#include <cstdint>
#include <cstddef>
#include <mma.h>

using namespace nvcuda;

#define Bb 8
#define Hh 4
#define LQ 1024
#define LK 4096
#define Dm 256
#define HD 1024

// ---------------- scratch (device globals; no allocations) ----------------
__device__ __half g_Xq16[(size_t)Bb * LQ * Dm];       //  4 MB [B,Lq,256]
__device__ __half g_Xk16[(size_t)Bb * LK * Dm];       // 16 MB [B,Lk,256]
__device__ __half g_Xv16[(size_t)Bb * LK * Dm];       // 16 MB
__device__ __half g_W16[(size_t)3 * HD * Dm];         // 1.5 MB (Wq,Wk,Wv f16)
__device__ __half g_Q16[(size_t)Bb * Hh * LQ * Dm];   // 16 MB [B,H,Lq,256]
__device__ __half g_K16[(size_t)Bb * Hh * LK * Dm];   // 64 MB
__device__ __half g_V16[(size_t)Bb * Hh * LK * Dm];   // 64 MB
__device__ __half g_O[(size_t)Bb * LQ * HD];          // 16 MB [B*Lq, H*256]

// ---------------- PTX helpers ----------------
__device__ __forceinline__ float ex2f(float x) {
    float r;
    asm("ex2.approx.ftz.f32 %0, %1;" : "=f"(r) : "f"(x));
    return r;
}
__device__ __forceinline__ void ldsm4(uint32_t& a0, uint32_t& a1, uint32_t& a2,
                                      uint32_t& a3, uint32_t addr) {
    asm volatile("ldmatrix.sync.aligned.m8n8.x4.shared.b16 {%0,%1,%2,%3},[%4];"
                 : "=r"(a0), "=r"(a1), "=r"(a2), "=r"(a3) : "r"(addr));
}
__device__ __forceinline__ void ldsm2(uint32_t& a0, uint32_t& a1, uint32_t addr) {
    asm volatile("ldmatrix.sync.aligned.m8n8.x2.shared.b16 {%0,%1},[%2];"
                 : "=r"(a0), "=r"(a1) : "r"(addr));
}
__device__ __forceinline__ void ldsm2t(uint32_t& a0, uint32_t& a1, uint32_t addr) {
    asm volatile("ldmatrix.sync.aligned.m8n8.x2.trans.shared.b16 {%0,%1},[%2];"
                 : "=r"(a0), "=r"(a1) : "r"(addr));
}
__device__ __forceinline__ void mma16816(float* d, uint32_t a0, uint32_t a1,
                                         uint32_t a2, uint32_t a3, uint32_t b0,
                                         uint32_t b1) {
    asm volatile(
        "mma.sync.aligned.m16n8k16.row.col.f32.f16.f16.f32 "
        "{%0,%1,%2,%3},{%4,%5,%6,%7},{%8,%9},{%0,%1,%2,%3};"
        : "+f"(d[0]), "+f"(d[1]), "+f"(d[2]), "+f"(d[3])
        : "r"(a0), "r"(a1), "r"(a2), "r"(a3), "r"(b0), "r"(b1));
}
__device__ __forceinline__ void cp16(uint32_t dst, const void* src) {
    asm volatile("cp.async.cg.shared.global [%0],[%1],16;" ::"r"(dst), "l"(src)
                 : "memory");
}
#define CP_COMMIT asm volatile("cp.async.commit_group;" ::: "memory")
// 32 bytes (16 halves) from gmem row into smem
__device__ __forceinline__ void ldpair(void* sdst, const __half* g) {
    uint32_t d = (uint32_t)__cvta_generic_to_shared(sdst);
    cp16(d, g);
    cp16(d + 16, g + 8);
}

// ---------------- input converts: [L,B,D]->(+add)->[B,L,D] f16 ----------------
__global__ void cvtx_kernel(const float* __restrict__ in1,
                            const float* __restrict__ in2, int L, int sel) {
    __half* out = (sel == 0) ? g_Xq16 : (sel == 1) ? g_Xk16 : g_Xv16;
    int idx = blockIdx.x * blockDim.x + threadIdx.x;  // one float4
    int d4 = idx & 63;
    int m = idx >> 6;
    int b = m / L;
    int l = m - b * L;
    float4 v = ((const float4*)in1)[((size_t)l * Bb + b) * 64 + d4];
    if (in2) {
        float4 w = ((const float4*)in2)[((size_t)l * Bb + b) * 64 + d4];
        v.x += w.x; v.y += w.y; v.z += w.z; v.w += w.w;
    }
    __half2 h0 = __floats2half2_rn(v.x, v.y);
    __half2 h1 = __floats2half2_rn(v.z, v.w);
    uint2 u;
    u.x = *(uint32_t*)&h0;
    u.y = *(uint32_t*)&h1;
    ((uint2*)out)[idx] = u;
}

__global__ void cvtw_kernel(const float* __restrict__ src, int sel) {
    __half* out = g_W16 + (size_t)sel * HD * Dm;
    int idx = blockIdx.x * blockDim.x + threadIdx.x;  // one float4
    float4 v = ((const float4*)src)[idx];
    __half2 h0 = __floats2half2_rn(v.x, v.y);
    __half2 h1 = __floats2half2_rn(v.z, v.w);
    uint2 u;
    u.x = *(uint32_t*)&h0;
    u.y = *(uint32_t*)&h1;
    ((uint2*)out)[idx] = u;
}

// ---------------- projection GEMM (f16, cp.async 2-stage) ----------------
// Out[b,h,l,e] = X[b,l,:] . W[h*256+e,:], f32 accum, f16 store
__global__ __launch_bounds__(256, 2) void proj_kernel(int sel, int L) {
    const __half* X = (sel == 0) ? g_Xq16 : (sel == 1) ? g_Xk16 : g_Xv16;
    const __half* W = g_W16 + (size_t)sel * HD * Dm;
    __half* out = (sel == 0) ? g_Q16 : (sel == 1) ? g_K16 : g_V16;

    __shared__ __half As[2][128][40];
    __shared__ __half Bs[2][128][40];
    __shared__ float stage[8][16][20];

    int m0 = blockIdx.x * 128, n0 = blockIdx.y * 128;
    int b = m0 / L, l0 = m0 % L;
    int tid = threadIdx.x, wid = tid >> 5, lane = tid & 31;
    int wm = wid & 1, wn = wid >> 1;
    int r = tid >> 1, cseg = (tid & 1) * 16;

    wmma::fragment<wmma::accumulator, 16, 16, 16, float> c[4][2];
#pragma unroll
    for (int i = 0; i < 4; i++)
#pragma unroll
        for (int j = 0; j < 2; j++) wmma::fill_fragment(c[i][j], 0.0f);

#pragma unroll
    for (int pre = 0; pre < 2; pre++) {
        int kc = pre * 32;
        ldpair(&As[pre][r][cseg], X + (size_t)(m0 + r) * 256 + kc + cseg);
        ldpair(&Bs[pre][r][cseg], W + (size_t)(n0 + r) * 256 + kc + cseg);
        CP_COMMIT;
    }

    for (int ic = 0; ic < 8; ic++) {
        int cur = ic & 1;
        if (ic < 7)
            asm volatile("cp.async.wait_group 1;" ::: "memory");
        else
            asm volatile("cp.async.wait_group 0;" ::: "memory");
        __syncthreads();
#pragma unroll
        for (int ks = 0; ks < 2; ks++) {
            wmma::fragment<wmma::matrix_b, 16, 16, 16, __half, wmma::col_major> bf[2];
#pragma unroll
            for (int j = 0; j < 2; j++)
                wmma::load_matrix_sync(bf[j], &Bs[cur][wn * 32 + j * 16][ks * 16], 40);
#pragma unroll
            for (int i = 0; i < 4; i++) {
                wmma::fragment<wmma::matrix_a, 16, 16, 16, __half, wmma::row_major> af;
                wmma::load_matrix_sync(af, &As[cur][wm * 64 + i * 16][ks * 16], 40);
#pragma unroll
                for (int j = 0; j < 2; j++)
                    wmma::mma_sync(c[i][j], af, bf[j], c[i][j]);
            }
        }
        __syncthreads();
        if (ic + 2 < 8) {
            int kc = (ic + 2) * 32;
            ldpair(&As[cur][r][cseg], X + (size_t)(m0 + r) * 256 + kc + cseg);
            ldpair(&Bs[cur][r][cseg], W + (size_t)(n0 + r) * 256 + kc + cseg);
        }
        CP_COMMIT;
    }

    int h = n0 >> 8, e0 = n0 & 255;
#pragma unroll
    for (int i = 0; i < 4; i++)
#pragma unroll
        for (int j = 0; j < 2; j++) {
            wmma::store_matrix_sync(&stage[wid][0][0], c[i][j], 20,
                                    wmma::mem_row_major);
            __syncwarp();
            int rr = lane >> 1, cb = (lane & 1) * 8;
            __half2* dst = (__half2*)(out +
                ((size_t)(b * Hh + h) * L + l0 + wm * 64 + i * 16 + rr) * 256 +
                e0 + wn * 32 + j * 16 + cb);
#pragma unroll
            for (int t = 0; t < 4; t++)
                dst[t] = __floats2half2_rn(stage[wid][rr][cb + 2 * t],
                                           stage[wid][rr][cb + 2 * t + 1]);
            __syncwarp();
        }
}

// ---------------- attn_mean = (scale/H) * sum_h Q_h K_h^T  (f16, K=1024) ----------
__global__ __launch_bounds__(256, 2) void mean_kernel(float* __restrict__ out) {
    __shared__ __half As[2][128][40];
    __shared__ __half Bs[2][128][40];

    int q0 = blockIdx.x * 128, k0 = blockIdx.y * 128, b = blockIdx.z;
    int tid = threadIdx.x, wid = tid >> 5;
    int wm = wid & 1, wn = wid >> 1;
    int r = tid >> 1, cseg = (tid & 1) * 16;

    wmma::fragment<wmma::accumulator, 16, 16, 16, float> c[4][2];
#pragma unroll
    for (int i = 0; i < 4; i++)
#pragma unroll
        for (int j = 0; j < 2; j++) wmma::fill_fragment(c[i][j], 0.0f);

#pragma unroll
    for (int pre = 0; pre < 2; pre++) {
        int h = pre >> 3, kc = (pre & 7) * 32;
        ldpair(&As[pre][r][cseg],
               g_Q16 + ((size_t)(b * Hh + h) * LQ + q0 + r) * 256 + kc + cseg);
        ldpair(&Bs[pre][r][cseg],
               g_K16 + ((size_t)(b * Hh + h) * LK + k0 + r) * 256 + kc + cseg);
        CP_COMMIT;
    }

    for (int ic = 0; ic < 32; ic++) {
        int cur = ic & 1;
        if (ic < 31)
            asm volatile("cp.async.wait_group 1;" ::: "memory");
        else
            asm volatile("cp.async.wait_group 0;" ::: "memory");
        __syncthreads();
#pragma unroll
        for (int ks = 0; ks < 2; ks++) {
            wmma::fragment<wmma::matrix_b, 16, 16, 16, __half, wmma::col_major> bf[2];
#pragma unroll
            for (int j = 0; j < 2; j++)
                wmma::load_matrix_sync(bf[j], &Bs[cur][wn * 32 + j * 16][ks * 16], 40);
#pragma unroll
            for (int i = 0; i < 4; i++) {
                wmma::fragment<wmma::matrix_a, 16, 16, 16, __half, wmma::row_major> af;
                wmma::load_matrix_sync(af, &As[cur][wm * 64 + i * 16][ks * 16], 40);
#pragma unroll
                for (int j = 0; j < 2; j++)
                    wmma::mma_sync(c[i][j], af, bf[j], c[i][j]);
            }
        }
        __syncthreads();
        if (ic + 2 < 32) {
            int nc = ic + 2;
            int h = nc >> 3, kc = (nc & 7) * 32;
            ldpair(&As[cur][r][cseg],
                   g_Q16 + ((size_t)(b * Hh + h) * LQ + q0 + r) * 256 + kc + cseg);
            ldpair(&Bs[cur][r][cseg],
                   g_K16 + ((size_t)(b * Hh + h) * LK + k0 + r) * 256 + kc + cseg);
        }
        CP_COMMIT;
    }

    const float MSC = 0.015625f;  // (1/16)/4
#pragma unroll
    for (int i = 0; i < 4; i++)
#pragma unroll
        for (int j = 0; j < 2; j++) {
#pragma unroll
            for (int t = 0; t < c[i][j].num_elements; t++) c[i][j].x[t] *= MSC;
            wmma::store_matrix_sync(
                out + ((size_t)b * LQ + q0 + wm * 64 + i * 16) * LK + k0 +
                    wn * 32 + j * 16,
                c[i][j], LK, wmma::mem_row_major);
        }
}

// ---------------- flash attention (f16 mma, QT=64, KT=64, 2-stage cp.async) --------
#define FLASH_SMEM 179200
#define OF_Q 0
#define OF_K 33792
#define OF_V 101376
#define OF_P 168960
#define OF_RM 178176
#define OF_RL 178688
#define KROW 528  // bytes per 256-half row (+16B pad)

__device__ __forceinline__ void load_tile64(uint32_t dst, const __half* src,
                                            int tid) {
#pragma unroll
    for (int i = 0; i < 8; i++) {
        int t = tid + i * 256;
        int row = t >> 5, cc = t & 31;
        cp16(dst + row * KROW + cc * 16, src + (size_t)row * 256 + cc * 8);
    }
}

__global__ __launch_bounds__(256, 1) void flash_kernel() {
    extern __shared__ __align__(16) char dynsm[];
    char* sm = dynsm;
    int tid = threadIdx.x, lane = tid & 31, wid = tid >> 5;
    int wm = wid >> 1, wn = wid & 1;
    int q0 = blockIdx.x * 64;
    int bh = blockIdx.y;
    int b = bh >> 2, h = bh & 3;
    const __half* Qg = g_Q16 + ((size_t)bh * LQ + q0) * 256;
    const __half* Kg = g_K16 + (size_t)bh * LK * 256;
    const __half* Vg = g_V16 + (size_t)bh * LK * 256;

    uint32_t sb = (uint32_t)__cvta_generic_to_shared(sm);
    const uint32_t QB = sb + OF_Q, KB = sb + OF_K, VB = sb + OF_V, PB = sb + OF_P;
    float* redm = (float*)(sm + OF_RM);
    float* redl = (float*)(sm + OF_RL);

    load_tile64(QB, Qg, tid);
    load_tile64(KB, Kg, tid);
    load_tile64(VB, Vg, tid);
    CP_COMMIT;
    load_tile64(KB + 33792, Kg + 64 * 256, tid);
    load_tile64(VB + 33792, Vg + 64 * 256, tid);
    CP_COMMIT;

    float o[16][4];
#pragma unroll
    for (int j = 0; j < 16; j++) o[j][0] = o[j][1] = o[j][2] = o[j][3] = 0.f;
    float mr0 = -1e30f, mr1 = -1e30f, l0 = 0.f, l1 = 0.f;
    const float SLOG = 0.0901699438f;  // (1/16)*log2(e)
    int r0 = lane >> 2;
    int row0 = wm * 16 + r0, row1 = row0 + 8;

    const uint32_t Aq = QB + ((wm * 16 + (lane & 15)) * 264 + ((lane >> 4) << 3)) * 2;
    const uint32_t Ap = PB + ((wm * 16 + (lane & 15)) * 72 + ((lane >> 4) << 3)) * 2;
    const uint32_t KbOff = (wn * 32 + (lane & 7)) * KROW + (((lane >> 3) & 1) << 4);

    for (int it = 0; it < LK / 64; it++) {
        int cur = it & 1;
        if (it < LK / 64 - 1)
            asm volatile("cp.async.wait_group 1;" ::: "memory");
        else
            asm volatile("cp.async.wait_group 0;" ::: "memory");
        __syncthreads();

        uint32_t kb = KB + cur * 33792;
        float s[4][4];
#pragma unroll
        for (int j = 0; j < 4; j++) s[j][0] = s[j][1] = s[j][2] = s[j][3] = 0.f;
#pragma unroll
        for (int dk = 0; dk < 16; dk++) {
            uint32_t a0, a1, a2, a3;
            ldsm4(a0, a1, a2, a3, Aq + dk * 32);
#pragma unroll
            for (int j = 0; j < 4; j++) {
                uint32_t b0, b1;
                ldsm2(b0, b1, kb + KbOff + j * 8 * KROW + dk * 32);
                mma16816(s[j], a0, a1, a2, a3, b0, b1);
            }
        }

        // online softmax
        float pm0 = -1e30f, pm1 = -1e30f;
#pragma unroll
        for (int j = 0; j < 4; j++) {
            s[j][0] *= SLOG; s[j][1] *= SLOG; s[j][2] *= SLOG; s[j][3] *= SLOG;
            pm0 = fmaxf(pm0, fmaxf(s[j][0], s[j][1]));
            pm1 = fmaxf(pm1, fmaxf(s[j][2], s[j][3]));
        }
        pm0 = fmaxf(pm0, __shfl_xor_sync(~0u, pm0, 1));
        pm0 = fmaxf(pm0, __shfl_xor_sync(~0u, pm0, 2));
        pm1 = fmaxf(pm1, __shfl_xor_sync(~0u, pm1, 1));
        pm1 = fmaxf(pm1, __shfl_xor_sync(~0u, pm1, 2));
        if ((lane & 3) == 0) {
            redm[wn * 64 + row0] = pm0;
            redm[wn * 64 + row1] = pm1;
        }
        __syncthreads();
        float mn0 = fmaxf(mr0, fmaxf(redm[row0], redm[64 + row0]));
        float mn1 = fmaxf(mr1, fmaxf(redm[row1], redm[64 + row1]));
        float al0 = ex2f(mr0 - mn0), al1 = ex2f(mr1 - mn1);
        mr0 = mn0; mr1 = mn1;

        float ps0 = 0.f, ps1 = 0.f;
        __half2* Pp = (__half2*)(sm + OF_P);
#pragma unroll
        for (int j = 0; j < 4; j++) {
            float p0 = ex2f(s[j][0] - mn0), p1 = ex2f(s[j][1] - mn0);
            float p2 = ex2f(s[j][2] - mn1), p3 = ex2f(s[j][3] - mn1);
            ps0 += p0 + p1;
            ps1 += p2 + p3;
            int cb = wn * 32 + j * 8 + ((lane & 3) << 1);
            Pp[(row0 * 72 + cb) >> 1] = __floats2half2_rn(p0, p1);
            Pp[(row1 * 72 + cb) >> 1] = __floats2half2_rn(p2, p3);
        }
        ps0 += __shfl_xor_sync(~0u, ps0, 1);
        ps0 += __shfl_xor_sync(~0u, ps0, 2);
        ps1 += __shfl_xor_sync(~0u, ps1, 1);
        ps1 += __shfl_xor_sync(~0u, ps1, 2);
        if ((lane & 3) == 0) {
            redl[wn * 64 + row0] = ps0;
            redl[wn * 64 + row1] = ps1;
        }
#pragma unroll
        for (int j = 0; j < 16; j++) {
            o[j][0] *= al0; o[j][1] *= al0; o[j][2] *= al1; o[j][3] *= al1;
        }
        __syncthreads();
        l0 = al0 * l0 + redl[row0] + redl[64 + row0];
        l1 = al1 * l1 + redl[row1] + redl[64 + row1];

        // O += P @ V
        uint32_t vb = VB + cur * 33792;
#pragma unroll
        for (int kc = 0; kc < 4; kc++) {
            uint32_t a0, a1, a2, a3;
            ldsm4(a0, a1, a2, a3, Ap + kc * 32);
#pragma unroll
            for (int j = 0; j < 16; j++) {
                uint32_t b0, b1;
                ldsm2t(b0, b1, vb + (kc * 16 + (lane & 15)) * KROW +
                                   (wn * 128 + j * 8) * 2);
                mma16816(o[j], a0, a1, a2, a3, b0, b1);
            }
        }
        __syncthreads();
        if (it + 2 < LK / 64) {
            load_tile64(KB + cur * 33792, Kg + (size_t)(it + 2) * 64 * 256, tid);
            load_tile64(VB + cur * 33792, Vg + (size_t)(it + 2) * 64 * 256, tid);
        }
        CP_COMMIT;
    }

    float inv0 = 1.f / l0, inv1 = 1.f / l1;
    size_t ob0 = ((size_t)b * LQ + q0 + row0) * HD + h * 256 + wn * 128 +
                 ((lane & 3) << 1);
    size_t ob1 = ob0 + (size_t)8 * HD;
#pragma unroll
    for (int j = 0; j < 16; j++) {
        *(__half2*)(g_O + ob0 + j * 8) =
            __floats2half2_rn(o[j][0] * inv0, o[j][1] * inv0);
        *(__half2*)(g_O + ob1 + j * 8) =
            __floats2half2_rn(o[j][2] * inv1, o[j][3] * inv1);
    }
}

// ---------------- fc + residual + LayerNorm (f16 GEMM) ----------------
__global__ __launch_bounds__(256) void fc_ln_kernel(const float* __restrict__ Wfc,
                                                    const float* __restrict__ tgt,
                                                    const float* __restrict__ gamma,
                                                    const float* __restrict__ beta,
                                                    float* __restrict__ Y) {
    __shared__ __align__(16) unsigned char smraw[33280];
    __half* As = (__half*)smraw;             // [32][48]
    __half* Bsh = (__half*)(smraw + 3072);   // [256][48]
    float* stage = (float*)smraw;            // [32][260]

    int m0 = blockIdx.x * 32;
    int tid = threadIdx.x, wid = tid >> 5, lane = tid & 31;
    int wm = wid & 1, wn = wid >> 1;

    wmma::fragment<wmma::accumulator, 16, 16, 16, float> c[4];
#pragma unroll
    for (int j = 0; j < 4; j++) wmma::fill_fragment(c[j], 0.0f);

    for (int kc = 0; kc < HD; kc += 32) {
        int r = tid >> 3, cb = (tid & 7) << 2;
        *(uint2*)&As[r * 48 + cb] =
            *(const uint2*)&g_O[(size_t)(m0 + r) * HD + kc + cb];
#pragma unroll
        for (int p = 0; p < 8; p++) {
            int rr = r + p * 32;
            float4 w = *(const float4*)&Wfc[(size_t)rr * HD + kc + cb];
            *(__half2*)&Bsh[rr * 48 + cb] = __floats2half2_rn(w.x, w.y);
            *(__half2*)&Bsh[rr * 48 + cb + 2] = __floats2half2_rn(w.z, w.w);
        }
        __syncthreads();
#pragma unroll
        for (int ks = 0; ks < 2; ks++) {
            wmma::fragment<wmma::matrix_a, 16, 16, 16, __half, wmma::row_major> af;
            wmma::load_matrix_sync(af, &As[(wm * 16) * 48 + ks * 16], 48);
#pragma unroll
            for (int j = 0; j < 4; j++) {
                wmma::fragment<wmma::matrix_b, 16, 16, 16, __half,
                               wmma::col_major> bfr;
                wmma::load_matrix_sync(bfr, &Bsh[(wn * 64 + j * 16) * 48 + ks * 16],
                                       48);
                wmma::mma_sync(c[j], af, bfr, c[j]);
            }
        }
        __syncthreads();
    }

#pragma unroll
    for (int j = 0; j < 4; j++)
        wmma::store_matrix_sync(&stage[(wm * 16) * 260 + wn * 64 + j * 16], c[j],
                                260, wmma::mem_row_major);
    __syncthreads();

#pragma unroll
    for (int s = 0; s < 4; s++) {
        int row = wid * 4 + s;
        int m = m0 + row;
        int b = m >> 10, l = m & 1023;
        const float* trow = tgt + ((size_t)l * Bb + b) * 256;
        float v[8], sum = 0.f, sq = 0.f;
#pragma unroll
        for (int t = 0; t < 8; t++) {
            v[t] = stage[row * 260 + lane * 8 + t] + trow[lane * 8 + t];
            sum += v[t];
            sq += v[t] * v[t];
        }
#pragma unroll
        for (int oo = 16; oo > 0; oo >>= 1) {
            sum += __shfl_xor_sync(~0u, sum, oo);
            sq += __shfl_xor_sync(~0u, sq, oo);
        }
        float mu = sum * (1.0f / 256.0f);
        float var = sq * (1.0f / 256.0f) - mu * mu;
        float rsg = rsqrtf(var + 1e-5f);
        float* yr = Y + ((size_t)l * Bb + b) * 256;
#pragma unroll
        for (int t = 0; t < 8; t++) {
            int d = lane * 8 + t;
            yr[d] = (v[t] - mu) * rsg * gamma[d] + beta[d];
        }
    }
}

// ---------------- launch ----------------
extern "C" void kernel_launch(void* const* d_in, const int* in_sizes, int n_in,
                              void* d_out, int out_size) {
    const float* tgt  = (const float*)d_in[0];
    const float* mem  = (const float*)d_in[1];
    const float* pos  = (const float*)d_in[2];
    const float* qpos = (const float*)d_in[3];
    const float* Wq   = (const float*)d_in[4];
    const float* Wk   = (const float*)d_in[5];
    const float* Wv   = (const float*)d_in[6];
    const float* Wfc  = (const float*)d_in[7];
    const float* ln_g = (const float*)d_in[8];
    const float* ln_b = (const float*)d_in[9];

    float* y_out    = (float*)d_out;                         // [LQ,B,D]
    float* attn_out = (float*)d_out + (size_t)LQ * Bb * Dm;  // [B,1,LQ,LK]

    cudaFuncSetAttribute(flash_kernel,
                         cudaFuncAttributeMaxDynamicSharedMemorySize, FLASH_SMEM);

    // input + weight conversion to f16
    cvtx_kernel<<<(Bb * LQ * 64) / 256, 256>>>(tgt, qpos, LQ, 0);
    cvtx_kernel<<<(Bb * LK * 64) / 256, 256>>>(mem, pos, LK, 1);
    cvtx_kernel<<<(Bb * LK * 64) / 256, 256>>>(mem, (const float*)0, LK, 2);
    cvtw_kernel<<<(HD * Dm / 4) / 256, 256>>>(Wq, 0);
    cvtw_kernel<<<(HD * Dm / 4) / 256, 256>>>(Wk, 1);
    cvtw_kernel<<<(HD * Dm / 4) / 256, 256>>>(Wv, 2);

    // projections (f16)
    proj_kernel<<<dim3(Bb * LQ / 128, HD / 128), 256>>>(0, LQ);
    proj_kernel<<<dim3(Bb * LK / 128, HD / 128), 256>>>(1, LK);
    proj_kernel<<<dim3(Bb * LK / 128, HD / 128), 256>>>(2, LK);

    // attn_mean: f16 GEMM over concat heads (K=1024)
    mean_kernel<<<dim3(LQ / 128, LK / 128, Bb), 256>>>(attn_out);

    // flash attention (f16), writes g_O
    flash_kernel<<<dim3(LQ / 64, Bb * Hh), 256, FLASH_SMEM>>>();

    // fc + residual + layernorm
    fc_ln_kernel<<<(Bb * LQ) / 32, 256>>>(Wfc, tgt, ln_g, ln_b, y_out);
}

// round 9
// speedup vs baseline: 2.1626x; 1.0485x over previous
#include <cuda_runtime.h>
#include <cuda_bf16.h>
#include <cuda_fp16.h>
#include <cstdint>
#include <cstddef>
#include <mma.h>

using namespace nvcuda;

#define Bb 8
#define Hh 4
#define LQ 1024
#define LK 4096
#define Dm 256
#define HD 1024

// ---------------- scratch (device globals; no allocations) ----------------
__device__ __half g_Xq16[(size_t)Bb * LQ * Dm];       //  4 MB [B,Lq,256]
__device__ __half g_Xk16[(size_t)Bb * LK * Dm];       // 16 MB [B,Lk,256]
__device__ __half g_Xv16[(size_t)Bb * LK * Dm];       // 16 MB
__device__ __half g_W16[(size_t)3 * HD * Dm];         // 1.5 MB (Wq,Wk,Wv f16)
__device__ __half g_Q16[(size_t)Bb * Hh * LQ * Dm];   // 16 MB [B,H,Lq,256]
__device__ __half g_K16[(size_t)Bb * Hh * LK * Dm];   // 64 MB
__device__ __half g_V16[(size_t)Bb * Hh * LK * Dm];   // 64 MB
__device__ __half g_O[(size_t)Bb * LQ * HD];          // 16 MB [B*Lq, H*256]

// ---------------- PTX helpers ----------------
__device__ __forceinline__ float ex2f(float x) {
    float r;
    asm("ex2.approx.ftz.f32 %0, %1;" : "=f"(r) : "f"(x));
    return r;
}
__device__ __forceinline__ uint32_t packh2(float x, float y) {
    __half2 h = __floats2half2_rn(x, y);
    return *(uint32_t*)&h;
}
__device__ __forceinline__ void ldsm4(uint32_t& a0, uint32_t& a1, uint32_t& a2,
                                      uint32_t& a3, uint32_t addr) {
    asm volatile("ldmatrix.sync.aligned.m8n8.x4.shared.b16 {%0,%1,%2,%3},[%4];"
                 : "=r"(a0), "=r"(a1), "=r"(a2), "=r"(a3) : "r"(addr));
}
__device__ __forceinline__ void ldsm2(uint32_t& a0, uint32_t& a1, uint32_t addr) {
    asm volatile("ldmatrix.sync.aligned.m8n8.x2.shared.b16 {%0,%1},[%2];"
                 : "=r"(a0), "=r"(a1) : "r"(addr));
}
__device__ __forceinline__ void ldsm2t(uint32_t& a0, uint32_t& a1, uint32_t addr) {
    asm volatile("ldmatrix.sync.aligned.m8n8.x2.trans.shared.b16 {%0,%1},[%2];"
                 : "=r"(a0), "=r"(a1) : "r"(addr));
}
__device__ __forceinline__ void mma16816(float* d, uint32_t a0, uint32_t a1,
                                         uint32_t a2, uint32_t a3, uint32_t b0,
                                         uint32_t b1) {
    asm volatile(
        "mma.sync.aligned.m16n8k16.row.col.f32.f16.f16.f32 "
        "{%0,%1,%2,%3},{%4,%5,%6,%7},{%8,%9},{%0,%1,%2,%3};"
        : "+f"(d[0]), "+f"(d[1]), "+f"(d[2]), "+f"(d[3])
        : "r"(a0), "r"(a1), "r"(a2), "r"(a3), "r"(b0), "r"(b1));
}
__device__ __forceinline__ void cp16(uint32_t dst, const void* src) {
    asm volatile("cp.async.cg.shared.global [%0],[%1],16;" ::"r"(dst), "l"(src)
                 : "memory");
}
#define CP_COMMIT asm volatile("cp.async.commit_group;" ::: "memory")
__device__ __forceinline__ void ldpair(void* sdst, const __half* g) {
    uint32_t d = (uint32_t)__cvta_generic_to_shared(sdst);
    cp16(d, g);
    cp16(d + 16, g + 8);
}

// ---------------- input converts: [L,B,D]->(+add)->[B,L,D] f16 ----------------
__global__ void cvtx_kernel(const float* __restrict__ in1,
                            const float* __restrict__ in2, int L, int sel) {
    __half* out = (sel == 0) ? g_Xq16 : (sel == 1) ? g_Xk16 : g_Xv16;
    int idx = blockIdx.x * blockDim.x + threadIdx.x;  // one float4
    int d4 = idx & 63;
    int m = idx >> 6;
    int b = m / L;
    int l = m - b * L;
    float4 v = ((const float4*)in1)[((size_t)l * Bb + b) * 64 + d4];
    if (in2) {
        float4 w = ((const float4*)in2)[((size_t)l * Bb + b) * 64 + d4];
        v.x += w.x; v.y += w.y; v.z += w.z; v.w += w.w;
    }
    __half2 h0 = __floats2half2_rn(v.x, v.y);
    __half2 h1 = __floats2half2_rn(v.z, v.w);
    uint2 u;
    u.x = *(uint32_t*)&h0;
    u.y = *(uint32_t*)&h1;
    ((uint2*)out)[idx] = u;
}

__global__ void cvtw_kernel(const float* __restrict__ src, int sel) {
    __half* out = g_W16 + (size_t)sel * HD * Dm;
    int idx = blockIdx.x * blockDim.x + threadIdx.x;  // one float4
    float4 v = ((const float4*)src)[idx];
    __half2 h0 = __floats2half2_rn(v.x, v.y);
    __half2 h1 = __floats2half2_rn(v.z, v.w);
    uint2 u;
    u.x = *(uint32_t*)&h0;
    u.y = *(uint32_t*)&h1;
    ((uint2*)out)[idx] = u;
}

// ---------------- projection GEMM (f16, cp.async 2-stage) ----------------
__global__ __launch_bounds__(256, 2) void proj_kernel(int sel, int L) {
    const __half* X = (sel == 0) ? g_Xq16 : (sel == 1) ? g_Xk16 : g_Xv16;
    const __half* W = g_W16 + (size_t)sel * HD * Dm;
    __half* out = (sel == 0) ? g_Q16 : (sel == 1) ? g_K16 : g_V16;

    __shared__ __half As[2][128][40];
    __shared__ __half Bs[2][128][40];
    __shared__ float stage[8][16][20];

    int m0 = blockIdx.x * 128, n0 = blockIdx.y * 128;
    int b = m0 / L, l0 = m0 % L;
    int tid = threadIdx.x, wid = tid >> 5, lane = tid & 31;
    int wm = wid & 1, wn = wid >> 1;
    int r = tid >> 1, cseg = (tid & 1) * 16;

    wmma::fragment<wmma::accumulator, 16, 16, 16, float> c[4][2];
#pragma unroll
    for (int i = 0; i < 4; i++)
#pragma unroll
        for (int j = 0; j < 2; j++) wmma::fill_fragment(c[i][j], 0.0f);

#pragma unroll
    for (int pre = 0; pre < 2; pre++) {
        int kc = pre * 32;
        ldpair(&As[pre][r][cseg], X + (size_t)(m0 + r) * 256 + kc + cseg);
        ldpair(&Bs[pre][r][cseg], W + (size_t)(n0 + r) * 256 + kc + cseg);
        CP_COMMIT;
    }

    for (int ic = 0; ic < 8; ic++) {
        int cur = ic & 1;
        if (ic < 7)
            asm volatile("cp.async.wait_group 1;" ::: "memory");
        else
            asm volatile("cp.async.wait_group 0;" ::: "memory");
        __syncthreads();
#pragma unroll
        for (int ks = 0; ks < 2; ks++) {
            wmma::fragment<wmma::matrix_b, 16, 16, 16, __half, wmma::col_major> bf[2];
#pragma unroll
            for (int j = 0; j < 2; j++)
                wmma::load_matrix_sync(bf[j], &Bs[cur][wn * 32 + j * 16][ks * 16], 40);
#pragma unroll
            for (int i = 0; i < 4; i++) {
                wmma::fragment<wmma::matrix_a, 16, 16, 16, __half, wmma::row_major> af;
                wmma::load_matrix_sync(af, &As[cur][wm * 64 + i * 16][ks * 16], 40);
#pragma unroll
                for (int j = 0; j < 2; j++)
                    wmma::mma_sync(c[i][j], af, bf[j], c[i][j]);
            }
        }
        __syncthreads();
        if (ic + 2 < 8) {
            int kc = (ic + 2) * 32;
            ldpair(&As[cur][r][cseg], X + (size_t)(m0 + r) * 256 + kc + cseg);
            ldpair(&Bs[cur][r][cseg], W + (size_t)(n0 + r) * 256 + kc + cseg);
        }
        CP_COMMIT;
    }

    int h = n0 >> 8, e0 = n0 & 255;
#pragma unroll
    for (int i = 0; i < 4; i++)
#pragma unroll
        for (int j = 0; j < 2; j++) {
            wmma::store_matrix_sync(&stage[wid][0][0], c[i][j], 20,
                                    wmma::mem_row_major);
            __syncwarp();
            int rr = lane >> 1, cb = (lane & 1) * 8;
            __half2* dst = (__half2*)(out +
                ((size_t)(b * Hh + h) * L + l0 + wm * 64 + i * 16 + rr) * 256 +
                e0 + wn * 32 + j * 16 + cb);
#pragma unroll
            for (int t = 0; t < 4; t++)
                dst[t] = __floats2half2_rn(stage[wid][rr][cb + 2 * t],
                                           stage[wid][rr][cb + 2 * t + 1]);
            __syncwarp();
        }
}

// ---------------- attn_mean = (scale/H) * sum_h Q_h K_h^T  (f16, K=1024) ----------
__global__ __launch_bounds__(256, 2) void mean_kernel(float* __restrict__ out) {
    __shared__ __half As[2][128][40];
    __shared__ __half Bs[2][128][40];

    int q0 = blockIdx.x * 128, k0 = blockIdx.y * 128, b = blockIdx.z;
    int tid = threadIdx.x, wid = tid >> 5;
    int wm = wid & 1, wn = wid >> 1;
    int r = tid >> 1, cseg = (tid & 1) * 16;

    wmma::fragment<wmma::accumulator, 16, 16, 16, float> c[4][2];
#pragma unroll
    for (int i = 0; i < 4; i++)
#pragma unroll
        for (int j = 0; j < 2; j++) wmma::fill_fragment(c[i][j], 0.0f);

#pragma unroll
    for (int pre = 0; pre < 2; pre++) {
        int h = pre >> 3, kc = (pre & 7) * 32;
        ldpair(&As[pre][r][cseg],
               g_Q16 + ((size_t)(b * Hh + h) * LQ + q0 + r) * 256 + kc + cseg);
        ldpair(&Bs[pre][r][cseg],
               g_K16 + ((size_t)(b * Hh + h) * LK + k0 + r) * 256 + kc + cseg);
        CP_COMMIT;
    }

    for (int ic = 0; ic < 32; ic++) {
        int cur = ic & 1;
        if (ic < 31)
            asm volatile("cp.async.wait_group 1;" ::: "memory");
        else
            asm volatile("cp.async.wait_group 0;" ::: "memory");
        __syncthreads();
#pragma unroll
        for (int ks = 0; ks < 2; ks++) {
            wmma::fragment<wmma::matrix_b, 16, 16, 16, __half, wmma::col_major> bf[2];
#pragma unroll
            for (int j = 0; j < 2; j++)
                wmma::load_matrix_sync(bf[j], &Bs[cur][wn * 32 + j * 16][ks * 16], 40);
#pragma unroll
            for (int i = 0; i < 4; i++) {
                wmma::fragment<wmma::matrix_a, 16, 16, 16, __half, wmma::row_major> af;
                wmma::load_matrix_sync(af, &As[cur][wm * 64 + i * 16][ks * 16], 40);
#pragma unroll
                for (int j = 0; j < 2; j++)
                    wmma::mma_sync(c[i][j], af, bf[j], c[i][j]);
            }
        }
        __syncthreads();
        if (ic + 2 < 32) {
            int nc = ic + 2;
            int h = nc >> 3, kc = (nc & 7) * 32;
            ldpair(&As[cur][r][cseg],
                   g_Q16 + ((size_t)(b * Hh + h) * LQ + q0 + r) * 256 + kc + cseg);
            ldpair(&Bs[cur][r][cseg],
                   g_K16 + ((size_t)(b * Hh + h) * LK + k0 + r) * 256 + kc + cseg);
        }
        CP_COMMIT;
    }

    const float MSC = 0.015625f;  // (1/16)/4
#pragma unroll
    for (int i = 0; i < 4; i++)
#pragma unroll
        for (int j = 0; j < 2; j++) {
#pragma unroll
            for (int t = 0; t < c[i][j].num_elements; t++) c[i][j].x[t] *= MSC;
            wmma::store_matrix_sync(
                out + ((size_t)b * LQ + q0 + wm * 64 + i * 16) * LK + k0 +
                    wn * 32 + j * 16,
                c[i][j], LK, wmma::mem_row_major);
        }
}

// ---------------- flash attention v3: warp-private k-streams, register P ----------
// Warp w: wm = w>>1 (16 q-rows), wn = w&1 (k-substream: rows [wn*32,wn*32+32) of
// each 64-row K/V tile). No per-iteration cross-warp communication; the two
// streams are merged once at the epilogue (split-k flash combine).
#define FLASH_SMEM 179200
#define OF_Q 0
#define OF_K 33792
#define OF_V 101376
#define OF_RM 178176
#define OF_RL 178688
#define KROW 528  // bytes per 256-half row (+16B pad)

__device__ __forceinline__ void load_tile64(uint32_t dst, const __half* src,
                                            int tid) {
#pragma unroll
    for (int i = 0; i < 8; i++) {
        int t = tid + i * 256;
        int row = t >> 5, cc = t & 31;
        cp16(dst + row * KROW + cc * 16, src + (size_t)row * 256 + cc * 8);
    }
}

__global__ __launch_bounds__(256, 1) void flash_kernel() {
    extern __shared__ __align__(16) char dynsm[];
    char* sm = dynsm;
    int tid = threadIdx.x, lane = tid & 31, wid = tid >> 5;
    int wm = wid >> 1, wn = wid & 1;
    int q0 = blockIdx.x * 64;
    int bh = blockIdx.y;
    int b = bh >> 2, h = bh & 3;
    const __half* Qg = g_Q16 + ((size_t)bh * LQ + q0) * 256;
    const __half* Kg = g_K16 + (size_t)bh * LK * 256;
    const __half* Vg = g_V16 + (size_t)bh * LK * 256;

    uint32_t sb = (uint32_t)__cvta_generic_to_shared(sm);
    const uint32_t QB = sb + OF_Q, KB = sb + OF_K, VB = sb + OF_V;
    float* redm = (float*)(sm + OF_RM);   // [2][64] stream maxima
    float* redl = (float*)(sm + OF_RL);   // [2][64] stream sums
    float* Osm = (float*)(sm + OF_K);     // epilogue scratch [64][264] (reuses K)

    load_tile64(QB, Qg, tid);
    load_tile64(KB, Kg, tid);
    load_tile64(VB, Vg, tid);
    CP_COMMIT;
    load_tile64(KB + 33792, Kg + 64 * 256, tid);
    load_tile64(VB + 33792, Vg + 64 * 256, tid);
    CP_COMMIT;

    float o[32][4];
#pragma unroll
    for (int j = 0; j < 32; j++) o[j][0] = o[j][1] = o[j][2] = o[j][3] = 0.f;
    float mr0 = -1e30f, mr1 = -1e30f, l0 = 0.f, l1 = 0.f;
    const float SLOG = 0.0901699438f;  // (1/16)*log2(e)

    const uint32_t Aq = QB + ((wm * 16 + (lane & 15)) * 264 + ((lane >> 4) << 3)) * 2;
    const uint32_t KbOff = (wn * 32 + (lane & 7)) * KROW + (((lane >> 3) & 1) << 4);

    for (int it = 0; it < LK / 64; it++) {
        int cur = it & 1;
        if (it < LK / 64 - 1)
            asm volatile("cp.async.wait_group 1;" ::: "memory");
        else
            asm volatile("cp.async.wait_group 0;" ::: "memory");
        __syncthreads();

        // S = Q K^T over this warp's 32 k-rows
        uint32_t kb = KB + cur * 33792;
        float s[4][4];
#pragma unroll
        for (int j = 0; j < 4; j++) s[j][0] = s[j][1] = s[j][2] = s[j][3] = 0.f;
#pragma unroll
        for (int dk = 0; dk < 16; dk++) {
            uint32_t a0, a1, a2, a3;
            ldsm4(a0, a1, a2, a3, Aq + dk * 32);
#pragma unroll
            for (int j = 0; j < 4; j++) {
                uint32_t b0, b1;
                ldsm2(b0, b1, kb + KbOff + j * 8 * KROW + dk * 32);
                mma16816(s[j], a0, a1, a2, a3, b0, b1);
            }
        }

        // warp-private online softmax (quad shuffles only)
        float pm0 = -1e30f, pm1 = -1e30f;
#pragma unroll
        for (int j = 0; j < 4; j++) {
            s[j][0] *= SLOG; s[j][1] *= SLOG; s[j][2] *= SLOG; s[j][3] *= SLOG;
            pm0 = fmaxf(pm0, fmaxf(s[j][0], s[j][1]));
            pm1 = fmaxf(pm1, fmaxf(s[j][2], s[j][3]));
        }
        pm0 = fmaxf(pm0, __shfl_xor_sync(~0u, pm0, 1));
        pm0 = fmaxf(pm0, __shfl_xor_sync(~0u, pm0, 2));
        pm1 = fmaxf(pm1, __shfl_xor_sync(~0u, pm1, 1));
        pm1 = fmaxf(pm1, __shfl_xor_sync(~0u, pm1, 2));
        float mn0 = fmaxf(mr0, pm0), mn1 = fmaxf(mr1, pm1);
        float al0 = ex2f(mr0 - mn0), al1 = ex2f(mr1 - mn1);
        mr0 = mn0; mr1 = mn1;

        // P = exp(S - m), packed straight into A fragments (C->A layout identity)
        float ps0 = 0.f, ps1 = 0.f;
        uint32_t pa[2][4];
#pragma unroll
        for (int ks = 0; ks < 2; ks++)
#pragma unroll
            for (int tt = 0; tt < 2; tt++) {
                int j = 2 * ks + tt;
                float p0 = ex2f(s[j][0] - mn0), p1 = ex2f(s[j][1] - mn0);
                float p2 = ex2f(s[j][2] - mn1), p3 = ex2f(s[j][3] - mn1);
                ps0 += p0 + p1;
                ps1 += p2 + p3;
                pa[ks][tt * 2] = packh2(p0, p1);
                pa[ks][tt * 2 + 1] = packh2(p2, p3);
            }
        ps0 += __shfl_xor_sync(~0u, ps0, 1);
        ps0 += __shfl_xor_sync(~0u, ps0, 2);
        ps1 += __shfl_xor_sync(~0u, ps1, 1);
        ps1 += __shfl_xor_sync(~0u, ps1, 2);
        l0 = al0 * l0 + ps0;
        l1 = al1 * l1 + ps1;
#pragma unroll
        for (int j = 0; j < 32; j++) {
            o[j][0] *= al0; o[j][1] *= al0; o[j][2] *= al1; o[j][3] *= al1;
        }

        // O += P @ V over this warp's 32 k-rows (full 256-wide O)
        uint32_t vb = VB + cur * 33792;
#pragma unroll
        for (int ks = 0; ks < 2; ks++) {
            uint32_t vrow = vb + (wn * 32 + ks * 16 + (lane & 15)) * KROW;
#pragma unroll
            for (int j = 0; j < 32; j++) {
                uint32_t b0, b1;
                ldsm2t(b0, b1, vrow + j * 16);
                mma16816(o[j], pa[ks][0], pa[ks][1], pa[ks][2], pa[ks][3], b0, b1);
            }
        }
        __syncthreads();
        if (it + 2 < LK / 64) {
            load_tile64(KB + cur * 33792, Kg + (size_t)(it + 2) * 64 * 256, tid);
            load_tile64(VB + cur * 33792, Vg + (size_t)(it + 2) * 64 * 256, tid);
        }
        CP_COMMIT;
    }

    // ---- epilogue: combine the two k-streams (split-k flash merge) ----
    __syncthreads();  // loop fully done; K/V smem free for reuse
    int row0 = wm * 16 + (lane >> 2), row1 = row0 + 8;  // tile-local q rows
    int t2 = (lane & 3) * 2;
    if ((lane & 3) == 0) {
        redm[wn * 64 + row0] = mr0; redm[wn * 64 + row1] = mr1;
        redl[wn * 64 + row0] = l0;  redl[wn * 64 + row1] = l1;
    }
    __syncthreads();
    float ma0 = redm[row0], mb0 = redm[64 + row0];
    float ma1 = redm[row1], mb1 = redm[64 + row1];
    float mf0 = fmaxf(ma0, mb0), mf1 = fmaxf(ma1, mb1);
    float lf0 = redl[row0] * ex2f(ma0 - mf0) + redl[64 + row0] * ex2f(mb0 - mf0);
    float lf1 = redl[row1] * ex2f(ma1 - mf1) + redl[64 + row1] * ex2f(mb1 - mf1);
    float sc0 = ex2f((wn ? mb0 : ma0) - mf0);
    float sc1 = ex2f((wn ? mb1 : ma1) - mf1);

    if (wn == 1) {
#pragma unroll
        for (int j = 0; j < 32; j++) {
            Osm[row0 * 264 + j * 8 + t2]     = o[j][0] * sc0;
            Osm[row0 * 264 + j * 8 + t2 + 1] = o[j][1] * sc0;
            Osm[row1 * 264 + j * 8 + t2]     = o[j][2] * sc1;
            Osm[row1 * 264 + j * 8 + t2 + 1] = o[j][3] * sc1;
        }
    }
    __syncthreads();
    if (wn == 0) {
        float inv0 = 1.f / lf0, inv1 = 1.f / lf1;
        size_t ob0 = ((size_t)b * LQ + q0 + row0) * HD + h * 256 + t2;
        size_t ob1 = ((size_t)b * LQ + q0 + row1) * HD + h * 256 + t2;
#pragma unroll
        for (int j = 0; j < 32; j++) {
            float x0 = (o[j][0] * sc0 + Osm[row0 * 264 + j * 8 + t2]) * inv0;
            float x1 = (o[j][1] * sc0 + Osm[row0 * 264 + j * 8 + t2 + 1]) * inv0;
            float x2 = (o[j][2] * sc1 + Osm[row1 * 264 + j * 8 + t2]) * inv1;
            float x3 = (o[j][3] * sc1 + Osm[row1 * 264 + j * 8 + t2 + 1]) * inv1;
            *(__half2*)(g_O + ob0 + j * 8) = __floats2half2_rn(x0, x1);
            *(__half2*)(g_O + ob1 + j * 8) = __floats2half2_rn(x2, x3);
        }
    }
}

// ---------------- fc + residual + LayerNorm (f16 GEMM) ----------------
__global__ __launch_bounds__(256) void fc_ln_kernel(const float* __restrict__ Wfc,
                                                    const float* __restrict__ tgt,
                                                    const float* __restrict__ gamma,
                                                    const float* __restrict__ beta,
                                                    float* __restrict__ Y) {
    __shared__ __align__(16) unsigned char smraw[33280];
    __half* As = (__half*)smraw;             // [32][48]
    __half* Bsh = (__half*)(smraw + 3072);   // [256][48]
    float* stage = (float*)smraw;            // [32][260]

    int m0 = blockIdx.x * 32;
    int tid = threadIdx.x, wid = tid >> 5, lane = tid & 31;
    int wm = wid & 1, wn = wid >> 1;

    wmma::fragment<wmma::accumulator, 16, 16, 16, float> c[4];
#pragma unroll
    for (int j = 0; j < 4; j++) wmma::fill_fragment(c[j], 0.0f);

    for (int kc = 0; kc < HD; kc += 32) {
        int r = tid >> 3, cb = (tid & 7) << 2;
        *(uint2*)&As[r * 48 + cb] =
            *(const uint2*)&g_O[(size_t)(m0 + r) * HD + kc + cb];
#pragma unroll
        for (int p = 0; p < 8; p++) {
            int rr = r + p * 32;
            float4 w = *(const float4*)&Wfc[(size_t)rr * HD + kc + cb];
            *(__half2*)&Bsh[rr * 48 + cb] = __floats2half2_rn(w.x, w.y);
            *(__half2*)&Bsh[rr * 48 + cb + 2] = __floats2half2_rn(w.z, w.w);
        }
        __syncthreads();
#pragma unroll
        for (int ks = 0; ks < 2; ks++) {
            wmma::fragment<wmma::matrix_a, 16, 16, 16, __half, wmma::row_major> af;
            wmma::load_matrix_sync(af, &As[(wm * 16) * 48 + ks * 16], 48);
#pragma unroll
            for (int j = 0; j < 4; j++) {
                wmma::fragment<wmma::matrix_b, 16, 16, 16, __half,
                               wmma::col_major> bfr;
                wmma::load_matrix_sync(bfr, &Bsh[(wn * 64 + j * 16) * 48 + ks * 16],
                                       48);
                wmma::mma_sync(c[j], af, bfr, c[j]);
            }
        }
        __syncthreads();
    }

#pragma unroll
    for (int j = 0; j < 4; j++)
        wmma::store_matrix_sync(&stage[(wm * 16) * 260 + wn * 64 + j * 16], c[j],
                                260, wmma::mem_row_major);
    __syncthreads();

#pragma unroll
    for (int s = 0; s < 4; s++) {
        int row = wid * 4 + s;
        int m = m0 + row;
        int b = m >> 10, l = m & 1023;
        const float* trow = tgt + ((size_t)l * Bb + b) * 256;
        float v[8], sum = 0.f, sq = 0.f;
#pragma unroll
        for (int t = 0; t < 8; t++) {
            v[t] = stage[row * 260 + lane * 8 + t] + trow[lane * 8 + t];
            sum += v[t];
            sq += v[t] * v[t];
        }
#pragma unroll
        for (int oo = 16; oo > 0; oo >>= 1) {
            sum += __shfl_xor_sync(~0u, sum, oo);
            sq += __shfl_xor_sync(~0u, sq, oo);
        }
        float mu = sum * (1.0f / 256.0f);
        float var = sq * (1.0f / 256.0f) - mu * mu;
        float rsg = rsqrtf(var + 1e-5f);
        float* yr = Y + ((size_t)l * Bb + b) * 256;
#pragma unroll
        for (int t = 0; t < 8; t++) {
            int d = lane * 8 + t;
            yr[d] = (v[t] - mu) * rsg * gamma[d] + beta[d];
        }
    }
}

// ---------------- launch ----------------
extern "C" void kernel_launch(void* const* d_in, const int* in_sizes, int n_in,
                              void* d_out, int out_size) {
    const float* tgt  = (const float*)d_in[0];
    const float* mem  = (const float*)d_in[1];
    const float* pos  = (const float*)d_in[2];
    const float* qpos = (const float*)d_in[3];
    const float* Wq   = (const float*)d_in[4];
    const float* Wk   = (const float*)d_in[5];
    const float* Wv   = (const float*)d_in[6];
    const float* Wfc  = (const float*)d_in[7];
    const float* ln_g = (const float*)d_in[8];
    const float* ln_b = (const float*)d_in[9];

    float* y_out    = (float*)d_out;                         // [LQ,B,D]
    float* attn_out = (float*)d_out + (size_t)LQ * Bb * Dm;  // [B,1,LQ,LK]

    cudaFuncSetAttribute(flash_kernel,
                         cudaFuncAttributeMaxDynamicSharedMemorySize, FLASH_SMEM);

    // input + weight conversion to f16
    cvtx_kernel<<<(Bb * LQ * 64) / 256, 256>>>(tgt, qpos, LQ, 0);
    cvtx_kernel<<<(Bb * LK * 64) / 256, 256>>>(mem, pos, LK, 1);
    cvtx_kernel<<<(Bb * LK * 64) / 256, 256>>>(mem, (const float*)0, LK, 2);
    cvtw_kernel<<<(HD * Dm / 4) / 256, 256>>>(Wq, 0);
    cvtw_kernel<<<(HD * Dm / 4) / 256, 256>>>(Wk, 1);
    cvtw_kernel<<<(HD * Dm / 4) / 256, 256>>>(Wv, 2);

    // projections (f16)
    proj_kernel<<<dim3(Bb * LQ / 128, HD / 128), 256>>>(0, LQ);
    proj_kernel<<<dim3(Bb * LK / 128, HD / 128), 256>>>(1, LK);
    proj_kernel<<<dim3(Bb * LK / 128, HD / 128), 256>>>(2, LK);

    // attn_mean: f16 GEMM over concat heads (K=1024)
    mean_kernel<<<dim3(LQ / 128, LK / 128, Bb), 256>>>(attn_out);

    // flash attention v3 (f16, warp-private k-streams), writes g_O
    flash_kernel<<<dim3(LQ / 64, Bb * Hh), 256, FLASH_SMEM>>>();

    // fc + residual + layernorm
    fc_ln_kernel<<<(Bb * LQ) / 32, 256>>>(Wfc, tgt, ln_g, ln_b, y_out);
}

// round 10
// speedup vs baseline: 2.3188x; 1.0722x over previous
#include <cuda_runtime.h>
#include <cuda_bf16.h>
#include <cuda_fp16.h>
#include <cstdint>
#include <cstddef>
#include <mma.h>

using namespace nvcuda;

#define Bb 8
#define Hh 4
#define LQ 1024
#define LK 4096
#define Dm 256
#define HD 1024

// ---------------- scratch (device globals; no allocations) ----------------
__device__ __half g_Xq16[(size_t)Bb * LQ * Dm];       //  4 MB [B,Lq,256]
__device__ __half g_Xk16[(size_t)Bb * LK * Dm];       // 16 MB [B,Lk,256]
__device__ __half g_Xv16[(size_t)Bb * LK * Dm];       // 16 MB
__device__ __half g_W16[(size_t)3 * HD * Dm];         // 1.5 MB (Wq,Wk,Wv f16)
__device__ __half g_Q16[(size_t)Bb * Hh * LQ * Dm];   // 16 MB [B,H,Lq,256]
__device__ __half g_K16[(size_t)Bb * Hh * LK * Dm];   // 64 MB
__device__ __half g_V16[(size_t)Bb * Hh * LK * Dm];   // 64 MB
__device__ __half g_O[(size_t)Bb * LQ * HD];          // 16 MB [B*Lq, H*256]

// ---------------- PTX helpers ----------------
__device__ __forceinline__ float ex2f(float x) {
    float r;
    asm("ex2.approx.ftz.f32 %0, %1;" : "=f"(r) : "f"(x));
    return r;
}
__device__ __forceinline__ uint32_t packh2(float x, float y) {
    __half2 h = __floats2half2_rn(x, y);
    return *(uint32_t*)&h;
}
__device__ __forceinline__ void ldsm4(uint32_t& a0, uint32_t& a1, uint32_t& a2,
                                      uint32_t& a3, uint32_t addr) {
    asm volatile("ldmatrix.sync.aligned.m8n8.x4.shared.b16 {%0,%1,%2,%3},[%4];"
                 : "=r"(a0), "=r"(a1), "=r"(a2), "=r"(a3) : "r"(addr));
}
__device__ __forceinline__ void ldsm4t(uint32_t& a0, uint32_t& a1, uint32_t& a2,
                                       uint32_t& a3, uint32_t addr) {
    asm volatile("ldmatrix.sync.aligned.m8n8.x4.trans.shared.b16 {%0,%1,%2,%3},[%4];"
                 : "=r"(a0), "=r"(a1), "=r"(a2), "=r"(a3) : "r"(addr));
}
__device__ __forceinline__ void mma16816(float* d, uint32_t a0, uint32_t a1,
                                         uint32_t a2, uint32_t a3, uint32_t b0,
                                         uint32_t b1) {
    asm volatile(
        "mma.sync.aligned.m16n8k16.row.col.f32.f16.f16.f32 "
        "{%0,%1,%2,%3},{%4,%5,%6,%7},{%8,%9},{%0,%1,%2,%3};"
        : "+f"(d[0]), "+f"(d[1]), "+f"(d[2]), "+f"(d[3])
        : "r"(a0), "r"(a1), "r"(a2), "r"(a3), "r"(b0), "r"(b1));
}
__device__ __forceinline__ void cp16(uint32_t dst, const void* src) {
    asm volatile("cp.async.cg.shared.global [%0],[%1],16;" ::"r"(dst), "l"(src)
                 : "memory");
}
#define CP_COMMIT asm volatile("cp.async.commit_group;" ::: "memory")
__device__ __forceinline__ void ldpair(void* sdst, const __half* g) {
    uint32_t d = (uint32_t)__cvta_generic_to_shared(sdst);
    cp16(d, g);
    cp16(d + 16, g + 8);
}

// ---------------- input converts: [L,B,D]->(+add)->[B,L,D] f16 ----------------
__global__ void cvtx_kernel(const float* __restrict__ in1,
                            const float* __restrict__ in2, int L, int sel) {
    __half* out = (sel == 0) ? g_Xq16 : (sel == 1) ? g_Xk16 : g_Xv16;
    int idx = blockIdx.x * blockDim.x + threadIdx.x;  // one float4
    int d4 = idx & 63;
    int m = idx >> 6;
    int b = m / L;
    int l = m - b * L;
    float4 v = ((const float4*)in1)[((size_t)l * Bb + b) * 64 + d4];
    if (in2) {
        float4 w = ((const float4*)in2)[((size_t)l * Bb + b) * 64 + d4];
        v.x += w.x; v.y += w.y; v.z += w.z; v.w += w.w;
    }
    __half2 h0 = __floats2half2_rn(v.x, v.y);
    __half2 h1 = __floats2half2_rn(v.z, v.w);
    uint2 u;
    u.x = *(uint32_t*)&h0;
    u.y = *(uint32_t*)&h1;
    ((uint2*)out)[idx] = u;
}

__global__ void cvtw_kernel(const float* __restrict__ src, int sel) {
    __half* out = g_W16 + (size_t)sel * HD * Dm;
    int idx = blockIdx.x * blockDim.x + threadIdx.x;  // one float4
    float4 v = ((const float4*)src)[idx];
    __half2 h0 = __floats2half2_rn(v.x, v.y);
    __half2 h1 = __floats2half2_rn(v.z, v.w);
    uint2 u;
    u.x = *(uint32_t*)&h0;
    u.y = *(uint32_t*)&h1;
    ((uint2*)out)[idx] = u;
}

// ---------------- projection GEMM (raw mma, direct-register epilogue) ----------
// Out[b,h,l,e] = X[b,l,:] . W[h*256+e,:], f32 accum, f16 store.
// Warp grid: wm = wid&1 (64 m-rows), wn = wid>>1 (32 n-cols).
__global__ __launch_bounds__(256, 2) void proj_kernel(int sel, int L) {
    const __half* X = (sel == 0) ? g_Xq16 : (sel == 1) ? g_Xk16 : g_Xv16;
    const __half* W = g_W16 + (size_t)sel * HD * Dm;
    __half* out = (sel == 0) ? g_Q16 : (sel == 1) ? g_K16 : g_V16;

    __shared__ __half As[2][128][40];
    __shared__ __half Bs[2][128][40];

    int m0 = blockIdx.x * 128, n0 = blockIdx.y * 128;
    int b = m0 / L, l0 = m0 % L;
    int tid = threadIdx.x, wid = tid >> 5, lane = tid & 31;
    int wm = wid & 1, wn = wid >> 1;
    int r = tid >> 1, cseg = (tid & 1) * 16;

    float c[4][4][4];
#pragma unroll
    for (int i = 0; i < 4; i++)
#pragma unroll
        for (int j = 0; j < 4; j++)
            c[i][j][0] = c[i][j][1] = c[i][j][2] = c[i][j][3] = 0.f;

    uint32_t AsB = (uint32_t)__cvta_generic_to_shared(&As[0][0][0]);
    uint32_t BsB = (uint32_t)__cvta_generic_to_shared(&Bs[0][0][0]);
    // A frag: rows wm*64+i*16+(lane&15), col-half select (lane>>4)
    const uint32_t Aoff = (uint32_t)(wm * 64 + (lane & 15)) * 80 + ((lane >> 4) << 4);
    // B frag pair: rows wn*32+(jp+(lane>>4))*8+(lane&7), b0/b1 by (lane>>3)&1
    const uint32_t Boff = (uint32_t)(wn * 32 + ((lane >> 4) << 3) + (lane & 7)) * 80 +
                          (((lane >> 3) & 1) << 4);

#pragma unroll
    for (int pre = 0; pre < 2; pre++) {
        int kc = pre * 32;
        ldpair(&As[pre][r][cseg], X + (size_t)(m0 + r) * 256 + kc + cseg);
        ldpair(&Bs[pre][r][cseg], W + (size_t)(n0 + r) * 256 + kc + cseg);
        CP_COMMIT;
    }

    for (int ic = 0; ic < 8; ic++) {
        int cur = ic & 1;
        if (ic < 7)
            asm volatile("cp.async.wait_group 1;" ::: "memory");
        else
            asm volatile("cp.async.wait_group 0;" ::: "memory");
        __syncthreads();
        uint32_t ab = AsB + cur * 10240, bb = BsB + cur * 10240;
#pragma unroll
        for (int ks = 0; ks < 2; ks++) {
            uint32_t a[4][4];
#pragma unroll
            for (int i = 0; i < 4; i++)
                ldsm4(a[i][0], a[i][1], a[i][2], a[i][3],
                      ab + Aoff + i * 16 * 80 + ks * 32);
#pragma unroll
            for (int jp = 0; jp < 4; jp += 2) {
                uint32_t b0, b1, b2, b3;
                ldsm4(b0, b1, b2, b3, bb + Boff + jp * 8 * 80 + ks * 32);
#pragma unroll
                for (int i = 0; i < 4; i++) {
                    mma16816(c[i][jp], a[i][0], a[i][1], a[i][2], a[i][3], b0, b1);
                    mma16816(c[i][jp + 1], a[i][0], a[i][1], a[i][2], a[i][3], b2, b3);
                }
            }
        }
        __syncthreads();
        if (ic + 2 < 8) {
            int kc = (ic + 2) * 32;
            ldpair(&As[cur][r][cseg], X + (size_t)(m0 + r) * 256 + kc + cseg);
            ldpair(&Bs[cur][r][cseg], W + (size_t)(n0 + r) * 256 + kc + cseg);
        }
        CP_COMMIT;
    }

    // direct-register epilogue (documented C-fragment layout)
    int h = n0 >> 8, e0 = n0 & 255;
    int rq = lane >> 2, t2 = (lane & 3) * 2;
#pragma unroll
    for (int i = 0; i < 4; i++) {
        size_t rowA = (size_t)(b * Hh + h) * L + l0 + wm * 64 + i * 16 + rq;
#pragma unroll
        for (int j = 0; j < 4; j++) {
            int colb = e0 + wn * 32 + j * 8 + t2;
            *(__half2*)(out + rowA * 256 + colb) =
                __floats2half2_rn(c[i][j][0], c[i][j][1]);
            *(__half2*)(out + (rowA + 8) * 256 + colb) =
                __floats2half2_rn(c[i][j][2], c[i][j][3]);
        }
    }
}

// ---------------- attn_mean = (scale/H) * sum_h Q_h K_h^T  (f16, K=1024) ----------
__global__ __launch_bounds__(256, 2) void mean_kernel(float* __restrict__ out) {
    __shared__ __half As[2][128][40];
    __shared__ __half Bs[2][128][40];

    int q0 = blockIdx.x * 128, k0 = blockIdx.y * 128, b = blockIdx.z;
    int tid = threadIdx.x, wid = tid >> 5;
    int wm = wid & 1, wn = wid >> 1;
    int r = tid >> 1, cseg = (tid & 1) * 16;

    wmma::fragment<wmma::accumulator, 16, 16, 16, float> c[4][2];
#pragma unroll
    for (int i = 0; i < 4; i++)
#pragma unroll
        for (int j = 0; j < 2; j++) wmma::fill_fragment(c[i][j], 0.0f);

#pragma unroll
    for (int pre = 0; pre < 2; pre++) {
        int h = pre >> 3, kc = (pre & 7) * 32;
        ldpair(&As[pre][r][cseg],
               g_Q16 + ((size_t)(b * Hh + h) * LQ + q0 + r) * 256 + kc + cseg);
        ldpair(&Bs[pre][r][cseg],
               g_K16 + ((size_t)(b * Hh + h) * LK + k0 + r) * 256 + kc + cseg);
        CP_COMMIT;
    }

    for (int ic = 0; ic < 32; ic++) {
        int cur = ic & 1;
        if (ic < 31)
            asm volatile("cp.async.wait_group 1;" ::: "memory");
        else
            asm volatile("cp.async.wait_group 0;" ::: "memory");
        __syncthreads();
#pragma unroll
        for (int ks = 0; ks < 2; ks++) {
            wmma::fragment<wmma::matrix_b, 16, 16, 16, __half, wmma::col_major> bf[2];
#pragma unroll
            for (int j = 0; j < 2; j++)
                wmma::load_matrix_sync(bf[j], &Bs[cur][wn * 32 + j * 16][ks * 16], 40);
#pragma unroll
            for (int i = 0; i < 4; i++) {
                wmma::fragment<wmma::matrix_a, 16, 16, 16, __half, wmma::row_major> af;
                wmma::load_matrix_sync(af, &As[cur][wm * 64 + i * 16][ks * 16], 40);
#pragma unroll
                for (int j = 0; j < 2; j++)
                    wmma::mma_sync(c[i][j], af, bf[j], c[i][j]);
            }
        }
        __syncthreads();
        if (ic + 2 < 32) {
            int nc = ic + 2;
            int h = nc >> 3, kc = (nc & 7) * 32;
            ldpair(&As[cur][r][cseg],
                   g_Q16 + ((size_t)(b * Hh + h) * LQ + q0 + r) * 256 + kc + cseg);
            ldpair(&Bs[cur][r][cseg],
                   g_K16 + ((size_t)(b * Hh + h) * LK + k0 + r) * 256 + kc + cseg);
        }
        CP_COMMIT;
    }

    const float MSC = 0.015625f;  // (1/16)/4
#pragma unroll
    for (int i = 0; i < 4; i++)
#pragma unroll
        for (int j = 0; j < 2; j++) {
#pragma unroll
            for (int t = 0; t < c[i][j].num_elements; t++) c[i][j].x[t] *= MSC;
            wmma::store_matrix_sync(
                out + ((size_t)b * LQ + q0 + wm * 64 + i * 16) * LK + k0 +
                    wn * 32 + j * 16,
                c[i][j], LK, wmma::mem_row_major);
        }
}

// ---------------- flash attention v4: warp-private k-streams, x4 ldmatrix --------
#define FLASH_SMEM 179200
#define OF_Q 0
#define OF_K 33792
#define OF_V 101376
#define OF_RM 178176
#define OF_RL 178688
#define KROW 528  // bytes per 256-half row (+16B pad)

__device__ __forceinline__ void load_tile64(uint32_t dst, const __half* src,
                                            int tid) {
#pragma unroll
    for (int i = 0; i < 8; i++) {
        int t = tid + i * 256;
        int row = t >> 5, cc = t & 31;
        cp16(dst + row * KROW + cc * 16, src + (size_t)row * 256 + cc * 8);
    }
}

__global__ __launch_bounds__(256, 1) void flash_kernel() {
    extern __shared__ __align__(16) char dynsm[];
    char* sm = dynsm;
    int tid = threadIdx.x, lane = tid & 31, wid = tid >> 5;
    int wm = wid >> 1, wn = wid & 1;
    int q0 = blockIdx.x * 64;
    int bh = blockIdx.y;
    int b = bh >> 2, h = bh & 3;
    const __half* Qg = g_Q16 + ((size_t)bh * LQ + q0) * 256;
    const __half* Kg = g_K16 + (size_t)bh * LK * 256;
    const __half* Vg = g_V16 + (size_t)bh * LK * 256;

    uint32_t sb = (uint32_t)__cvta_generic_to_shared(sm);
    const uint32_t QB = sb + OF_Q, KB = sb + OF_K, VB = sb + OF_V;
    float* redm = (float*)(sm + OF_RM);   // [2][64] stream maxima
    float* redl = (float*)(sm + OF_RL);   // [2][64] stream sums
    float* Osm = (float*)(sm + OF_K);     // epilogue scratch [64][264] (reuses K)

    load_tile64(QB, Qg, tid);
    load_tile64(KB, Kg, tid);
    load_tile64(VB, Vg, tid);
    CP_COMMIT;
    load_tile64(KB + 33792, Kg + 64 * 256, tid);
    load_tile64(VB + 33792, Vg + 64 * 256, tid);
    CP_COMMIT;

    float o[32][4];
#pragma unroll
    for (int j = 0; j < 32; j++) o[j][0] = o[j][1] = o[j][2] = o[j][3] = 0.f;
    float mr0 = -1e30f, mr1 = -1e30f, l0 = 0.f, l1 = 0.f;
    const float SLOG = 0.0901699438f;  // (1/16)*log2(e)

    const uint32_t Aq = QB + ((wm * 16 + (lane & 15)) * 264 + ((lane >> 4) << 3)) * 2;
    // K x4: rows wn*32+(jp+(lane>>4))*8+(lane&7); b0/b1 by (lane>>3)&1
    const uint32_t Kb2 = (uint32_t)(wn * 32 + ((lane >> 4) << 3) + (lane & 7)) * KROW +
                         (((lane >> 3) & 1) << 4);
    // V x4 trans: rows (lane&15); col-pair select by (lane>>4)
    const uint32_t Vb2 = (uint32_t)(wn * 32 + (lane & 15)) * KROW + ((lane >> 4) << 4);

    for (int it = 0; it < LK / 64; it++) {
        int cur = it & 1;
        if (it < LK / 64 - 1)
            asm volatile("cp.async.wait_group 1;" ::: "memory");
        else
            asm volatile("cp.async.wait_group 0;" ::: "memory");
        __syncthreads();

        // S = Q K^T over this warp's 32 k-rows
        uint32_t kb = KB + cur * 33792;
        float s[4][4];
#pragma unroll
        for (int j = 0; j < 4; j++) s[j][0] = s[j][1] = s[j][2] = s[j][3] = 0.f;
#pragma unroll
        for (int dk = 0; dk < 16; dk++) {
            uint32_t a0, a1, a2, a3;
            ldsm4(a0, a1, a2, a3, Aq + dk * 32);
#pragma unroll
            for (int jp = 0; jp < 4; jp += 2) {
                uint32_t b0, b1, b2, b3;
                ldsm4(b0, b1, b2, b3, kb + Kb2 + jp * 8 * KROW + dk * 32);
                mma16816(s[jp], a0, a1, a2, a3, b0, b1);
                mma16816(s[jp + 1], a0, a1, a2, a3, b2, b3);
            }
        }

        // warp-private online softmax (quad shuffles only)
        float pm0 = -1e30f, pm1 = -1e30f;
#pragma unroll
        for (int j = 0; j < 4; j++) {
            s[j][0] *= SLOG; s[j][1] *= SLOG; s[j][2] *= SLOG; s[j][3] *= SLOG;
            pm0 = fmaxf(pm0, fmaxf(s[j][0], s[j][1]));
            pm1 = fmaxf(pm1, fmaxf(s[j][2], s[j][3]));
        }
        pm0 = fmaxf(pm0, __shfl_xor_sync(~0u, pm0, 1));
        pm0 = fmaxf(pm0, __shfl_xor_sync(~0u, pm0, 2));
        pm1 = fmaxf(pm1, __shfl_xor_sync(~0u, pm1, 1));
        pm1 = fmaxf(pm1, __shfl_xor_sync(~0u, pm1, 2));
        float mn0 = fmaxf(mr0, pm0), mn1 = fmaxf(mr1, pm1);
        float al0 = ex2f(mr0 - mn0), al1 = ex2f(mr1 - mn1);
        mr0 = mn0; mr1 = mn1;

        // P = exp(S - m), packed straight into A fragments (C->A layout identity)
        float ps0 = 0.f, ps1 = 0.f;
        uint32_t pa[2][4];
#pragma unroll
        for (int ks = 0; ks < 2; ks++)
#pragma unroll
            for (int tt = 0; tt < 2; tt++) {
                int j = 2 * ks + tt;
                float p0 = ex2f(s[j][0] - mn0), p1 = ex2f(s[j][1] - mn0);
                float p2 = ex2f(s[j][2] - mn1), p3 = ex2f(s[j][3] - mn1);
                ps0 += p0 + p1;
                ps1 += p2 + p3;
                pa[ks][tt * 2] = packh2(p0, p1);
                pa[ks][tt * 2 + 1] = packh2(p2, p3);
            }
        ps0 += __shfl_xor_sync(~0u, ps0, 1);
        ps0 += __shfl_xor_sync(~0u, ps0, 2);
        ps1 += __shfl_xor_sync(~0u, ps1, 1);
        ps1 += __shfl_xor_sync(~0u, ps1, 2);
        l0 = al0 * l0 + ps0;
        l1 = al1 * l1 + ps1;
#pragma unroll
        for (int j = 0; j < 32; j++) {
            o[j][0] *= al0; o[j][1] *= al0; o[j][2] *= al1; o[j][3] *= al1;
        }

        // O += P @ V over this warp's 32 k-rows (full 256-wide O)
        uint32_t vb = VB + cur * 33792;
#pragma unroll
        for (int ks = 0; ks < 2; ks++) {
            uint32_t vrow = vb + Vb2 + ks * 16 * KROW;
#pragma unroll
            for (int jp = 0; jp < 32; jp += 2) {
                uint32_t b0, b1, b2, b3;
                ldsm4t(b0, b1, b2, b3, vrow + jp * 16);
                mma16816(o[jp], pa[ks][0], pa[ks][1], pa[ks][2], pa[ks][3], b0, b1);
                mma16816(o[jp + 1], pa[ks][0], pa[ks][1], pa[ks][2], pa[ks][3], b2, b3);
            }
        }
        __syncthreads();
        if (it + 2 < LK / 64) {
            load_tile64(KB + cur * 33792, Kg + (size_t)(it + 2) * 64 * 256, tid);
            load_tile64(VB + cur * 33792, Vg + (size_t)(it + 2) * 64 * 256, tid);
        }
        CP_COMMIT;
    }

    // ---- epilogue: combine the two k-streams (split-k flash merge) ----
    __syncthreads();  // loop fully done; K/V smem free for reuse
    int row0 = wm * 16 + (lane >> 2), row1 = row0 + 8;  // tile-local q rows
    int t2 = (lane & 3) * 2;
    if ((lane & 3) == 0) {
        redm[wn * 64 + row0] = mr0; redm[wn * 64 + row1] = mr1;
        redl[wn * 64 + row0] = l0;  redl[wn * 64 + row1] = l1;
    }
    __syncthreads();
    float ma0 = redm[row0], mb0 = redm[64 + row0];
    float ma1 = redm[row1], mb1 = redm[64 + row1];
    float mf0 = fmaxf(ma0, mb0), mf1 = fmaxf(ma1, mb1);
    float lf0 = redl[row0] * ex2f(ma0 - mf0) + redl[64 + row0] * ex2f(mb0 - mf0);
    float lf1 = redl[row1] * ex2f(ma1 - mf1) + redl[64 + row1] * ex2f(mb1 - mf1);
    float sc0 = ex2f((wn ? mb0 : ma0) - mf0);
    float sc1 = ex2f((wn ? mb1 : ma1) - mf1);

    if (wn == 1) {
#pragma unroll
        for (int j = 0; j < 32; j++) {
            Osm[row0 * 264 + j * 8 + t2]     = o[j][0] * sc0;
            Osm[row0 * 264 + j * 8 + t2 + 1] = o[j][1] * sc0;
            Osm[row1 * 264 + j * 8 + t2]     = o[j][2] * sc1;
            Osm[row1 * 264 + j * 8 + t2 + 1] = o[j][3] * sc1;
        }
    }
    __syncthreads();
    if (wn == 0) {
        float inv0 = 1.f / lf0, inv1 = 1.f / lf1;
        size_t ob0 = ((size_t)b * LQ + q0 + row0) * HD + h * 256 + t2;
        size_t ob1 = ((size_t)b * LQ + q0 + row1) * HD + h * 256 + t2;
#pragma unroll
        for (int j = 0; j < 32; j++) {
            float x0 = (o[j][0] * sc0 + Osm[row0 * 264 + j * 8 + t2]) * inv0;
            float x1 = (o[j][1] * sc0 + Osm[row0 * 264 + j * 8 + t2 + 1]) * inv0;
            float x2 = (o[j][2] * sc1 + Osm[row1 * 264 + j * 8 + t2]) * inv1;
            float x3 = (o[j][3] * sc1 + Osm[row1 * 264 + j * 8 + t2 + 1]) * inv1;
            *(__half2*)(g_O + ob0 + j * 8) = __floats2half2_rn(x0, x1);
            *(__half2*)(g_O + ob1 + j * 8) = __floats2half2_rn(x2, x3);
        }
    }
}

// ---------------- fc + residual + LayerNorm (f16 GEMM) ----------------
__global__ __launch_bounds__(256) void fc_ln_kernel(const float* __restrict__ Wfc,
                                                    const float* __restrict__ tgt,
                                                    const float* __restrict__ gamma,
                                                    const float* __restrict__ beta,
                                                    float* __restrict__ Y) {
    __shared__ __align__(16) unsigned char smraw[33280];
    __half* As = (__half*)smraw;             // [32][48]
    __half* Bsh = (__half*)(smraw + 3072);   // [256][48]
    float* stage = (float*)smraw;            // [32][260]

    int m0 = blockIdx.x * 32;
    int tid = threadIdx.x, wid = tid >> 5, lane = tid & 31;
    int wm = wid & 1, wn = wid >> 1;

    wmma::fragment<wmma::accumulator, 16, 16, 16, float> c[4];
#pragma unroll
    for (int j = 0; j < 4; j++) wmma::fill_fragment(c[j], 0.0f);

    for (int kc = 0; kc < HD; kc += 32) {
        int r = tid >> 3, cb = (tid & 7) << 2;
        *(uint2*)&As[r * 48 + cb] =
            *(const uint2*)&g_O[(size_t)(m0 + r) * HD + kc + cb];
#pragma unroll
        for (int p = 0; p < 8; p++) {
            int rr = r + p * 32;
            float4 w = *(const float4*)&Wfc[(size_t)rr * HD + kc + cb];
            *(__half2*)&Bsh[rr * 48 + cb] = __floats2half2_rn(w.x, w.y);
            *(__half2*)&Bsh[rr * 48 + cb + 2] = __floats2half2_rn(w.z, w.w);
        }
        __syncthreads();
#pragma unroll
        for (int ks = 0; ks < 2; ks++) {
            wmma::fragment<wmma::matrix_a, 16, 16, 16, __half, wmma::row_major> af;
            wmma::load_matrix_sync(af, &As[(wm * 16) * 48 + ks * 16], 48);
#pragma unroll
            for (int j = 0; j < 4; j++) {
                wmma::fragment<wmma::matrix_b, 16, 16, 16, __half,
                               wmma::col_major> bfr;
                wmma::load_matrix_sync(bfr, &Bsh[(wn * 64 + j * 16) * 48 + ks * 16],
                                       48);
                wmma::mma_sync(c[j], af, bfr, c[j]);
            }
        }
        __syncthreads();
    }

#pragma unroll
    for (int j = 0; j < 4; j++)
        wmma::store_matrix_sync(&stage[(wm * 16) * 260 + wn * 64 + j * 16], c[j],
                                260, wmma::mem_row_major);
    __syncthreads();

#pragma unroll
    for (int s = 0; s < 4; s++) {
        int row = wid * 4 + s;
        int m = m0 + row;
        int b = m >> 10, l = m & 1023;
        const float* trow = tgt + ((size_t)l * Bb + b) * 256;
        float v[8], sum = 0.f, sq = 0.f;
#pragma unroll
        for (int t = 0; t < 8; t++) {
            v[t] = stage[row * 260 + lane * 8 + t] + trow[lane * 8 + t];
            sum += v[t];
            sq += v[t] * v[t];
        }
#pragma unroll
        for (int oo = 16; oo > 0; oo >>= 1) {
            sum += __shfl_xor_sync(~0u, sum, oo);
            sq += __shfl_xor_sync(~0u, sq, oo);
        }
        float mu = sum * (1.0f / 256.0f);
        float var = sq * (1.0f / 256.0f) - mu * mu;
        float rsg = rsqrtf(var + 1e-5f);
        float* yr = Y + ((size_t)l * Bb + b) * 256;
#pragma unroll
        for (int t = 0; t < 8; t++) {
            int d = lane * 8 + t;
            yr[d] = (v[t] - mu) * rsg * gamma[d] + beta[d];
        }
    }
}

// ---------------- launch ----------------
extern "C" void kernel_launch(void* const* d_in, const int* in_sizes, int n_in,
                              void* d_out, int out_size) {
    const float* tgt  = (const float*)d_in[0];
    const float* mem  = (const float*)d_in[1];
    const float* pos  = (const float*)d_in[2];
    const float* qpos = (const float*)d_in[3];
    const float* Wq   = (const float*)d_in[4];
    const float* Wk   = (const float*)d_in[5];
    const float* Wv   = (const float*)d_in[6];
    const float* Wfc  = (const float*)d_in[7];
    const float* ln_g = (const float*)d_in[8];
    const float* ln_b = (const float*)d_in[9];

    float* y_out    = (float*)d_out;                         // [LQ,B,D]
    float* attn_out = (float*)d_out + (size_t)LQ * Bb * Dm;  // [B,1,LQ,LK]

    cudaFuncSetAttribute(flash_kernel,
                         cudaFuncAttributeMaxDynamicSharedMemorySize, FLASH_SMEM);

    // input + weight conversion to f16
    cvtx_kernel<<<(Bb * LQ * 64) / 256, 256>>>(tgt, qpos, LQ, 0);
    cvtx_kernel<<<(Bb * LK * 64) / 256, 256>>>(mem, pos, LK, 1);
    cvtx_kernel<<<(Bb * LK * 64) / 256, 256>>>(mem, (const float*)0, LK, 2);
    cvtw_kernel<<<(HD * Dm / 4) / 256, 256>>>(Wq, 0);
    cvtw_kernel<<<(HD * Dm / 4) / 256, 256>>>(Wk, 1);
    cvtw_kernel<<<(HD * Dm / 4) / 256, 256>>>(Wv, 2);

    // projections (f16, raw mma)
    proj_kernel<<<dim3(Bb * LQ / 128, HD / 128), 256>>>(0, LQ);
    proj_kernel<<<dim3(Bb * LK / 128, HD / 128), 256>>>(1, LK);
    proj_kernel<<<dim3(Bb * LK / 128, HD / 128), 256>>>(2, LK);

    // attn_mean: f16 GEMM over concat heads (K=1024)
    mean_kernel<<<dim3(LQ / 128, LK / 128, Bb), 256>>>(attn_out);

    // flash attention v4 (f16, x4 ldmatrix), writes g_O
    flash_kernel<<<dim3(LQ / 64, Bb * Hh), 256, FLASH_SMEM>>>();

    // fc + residual + layernorm
    fc_ln_kernel<<<(Bb * LQ) / 32, 256>>>(Wfc, tgt, ln_g, ln_b, y_out);
}

// round 11
// speedup vs baseline: 2.7022x; 1.1653x over previous
#include <cuda_runtime.h>
#include <cuda_bf16.h>
#include <cuda_fp16.h>
#include <cstdint>
#include <cstddef>
#include <mma.h>

using namespace nvcuda;

#define Bb 8
#define Hh 4
#define LQ 1024
#define LK 4096
#define Dm 256
#define HD 1024

// ---------------- scratch (device globals; no allocations) ----------------
__device__ __half g_Xq16[(size_t)Bb * LQ * Dm];       //  4 MB [B,Lq,256]
__device__ __half g_Xk16[(size_t)Bb * LK * Dm];       // 16 MB [B,Lk,256]
__device__ __half g_Xv16[(size_t)Bb * LK * Dm];       // 16 MB
__device__ __half g_W16[(size_t)3 * HD * Dm];         // 1.5 MB (Wq,Wk,Wv f16)
__device__ __half g_Q16[(size_t)Bb * Hh * LQ * Dm];   // 16 MB [B,H,Lq,256]
__device__ __half g_K16[(size_t)Bb * Hh * LK * Dm];   // 64 MB
__device__ __half g_V16[(size_t)Bb * Hh * LK * Dm];   // 64 MB
__device__ __half g_O[(size_t)Bb * LQ * HD];          // 16 MB [B*Lq, H*256]

// ---------------- PTX helpers ----------------
__device__ __forceinline__ float ex2f(float x) {
    float r;
    asm("ex2.approx.ftz.f32 %0, %1;" : "=f"(r) : "f"(x));
    return r;
}
__device__ __forceinline__ uint32_t packh2(float x, float y) {
    __half2 h = __floats2half2_rn(x, y);
    return *(uint32_t*)&h;
}
__device__ __forceinline__ void ldsm4(uint32_t& a0, uint32_t& a1, uint32_t& a2,
                                      uint32_t& a3, uint32_t addr) {
    asm volatile("ldmatrix.sync.aligned.m8n8.x4.shared.b16 {%0,%1,%2,%3},[%4];"
                 : "=r"(a0), "=r"(a1), "=r"(a2), "=r"(a3) : "r"(addr));
}
__device__ __forceinline__ void ldsm4t(uint32_t& a0, uint32_t& a1, uint32_t& a2,
                                       uint32_t& a3, uint32_t addr) {
    asm volatile("ldmatrix.sync.aligned.m8n8.x4.trans.shared.b16 {%0,%1,%2,%3},[%4];"
                 : "=r"(a0), "=r"(a1), "=r"(a2), "=r"(a3) : "r"(addr));
}
__device__ __forceinline__ void mma16816(float* d, uint32_t a0, uint32_t a1,
                                         uint32_t a2, uint32_t a3, uint32_t b0,
                                         uint32_t b1) {
    asm volatile(
        "mma.sync.aligned.m16n8k16.row.col.f32.f16.f16.f32 "
        "{%0,%1,%2,%3},{%4,%5,%6,%7},{%8,%9},{%0,%1,%2,%3};"
        : "+f"(d[0]), "+f"(d[1]), "+f"(d[2]), "+f"(d[3])
        : "r"(a0), "r"(a1), "r"(a2), "r"(a3), "r"(b0), "r"(b1));
}
__device__ __forceinline__ void cp16(uint32_t dst, const void* src) {
    asm volatile("cp.async.cg.shared.global [%0],[%1],16;" ::"r"(dst), "l"(src)
                 : "memory");
}
#define CP_COMMIT asm volatile("cp.async.commit_group;" ::: "memory")
__device__ __forceinline__ void ldpair(void* sdst, const __half* g) {
    uint32_t d = (uint32_t)__cvta_generic_to_shared(sdst);
    cp16(d, g);
    cp16(d + 16, g + 8);
}

// ---------------- input converts: [L,B,D]->(+add)->[B,L,D] f16 ----------------
__global__ void cvtx_kernel(const float* __restrict__ in1,
                            const float* __restrict__ in2, int L, int sel) {
    __half* out = (sel == 0) ? g_Xq16 : (sel == 1) ? g_Xk16 : g_Xv16;
    int idx = blockIdx.x * blockDim.x + threadIdx.x;  // one float4
    int d4 = idx & 63;
    int m = idx >> 6;
    int b = m / L;
    int l = m - b * L;
    float4 v = ((const float4*)in1)[((size_t)l * Bb + b) * 64 + d4];
    if (in2) {
        float4 w = ((const float4*)in2)[((size_t)l * Bb + b) * 64 + d4];
        v.x += w.x; v.y += w.y; v.z += w.z; v.w += w.w;
    }
    __half2 h0 = __floats2half2_rn(v.x, v.y);
    __half2 h1 = __floats2half2_rn(v.z, v.w);
    uint2 u;
    u.x = *(uint32_t*)&h0;
    u.y = *(uint32_t*)&h1;
    ((uint2*)out)[idx] = u;
}

__global__ void cvtw_kernel(const float* __restrict__ src, int sel) {
    __half* out = g_W16 + (size_t)sel * HD * Dm;
    int idx = blockIdx.x * blockDim.x + threadIdx.x;  // one float4
    float4 v = ((const float4*)src)[idx];
    __half2 h0 = __floats2half2_rn(v.x, v.y);
    __half2 h1 = __floats2half2_rn(v.z, v.w);
    uint2 u;
    u.x = *(uint32_t*)&h0;
    u.y = *(uint32_t*)&h1;
    ((uint2*)out)[idx] = u;
}

// ---------------- projection GEMM (raw mma, direct-register epilogue) ----------
__global__ __launch_bounds__(256, 2) void proj_kernel(int sel, int L) {
    const __half* X = (sel == 0) ? g_Xq16 : (sel == 1) ? g_Xk16 : g_Xv16;
    const __half* W = g_W16 + (size_t)sel * HD * Dm;
    __half* out = (sel == 0) ? g_Q16 : (sel == 1) ? g_K16 : g_V16;

    __shared__ __half As[2][128][40];
    __shared__ __half Bs[2][128][40];

    int m0 = blockIdx.x * 128, n0 = blockIdx.y * 128;
    int b = m0 / L, l0 = m0 % L;
    int tid = threadIdx.x, wid = tid >> 5, lane = tid & 31;
    int wm = wid & 1, wn = wid >> 1;
    int r = tid >> 1, cseg = (tid & 1) * 16;

    float c[4][4][4];
#pragma unroll
    for (int i = 0; i < 4; i++)
#pragma unroll
        for (int j = 0; j < 4; j++)
            c[i][j][0] = c[i][j][1] = c[i][j][2] = c[i][j][3] = 0.f;

    uint32_t AsB = (uint32_t)__cvta_generic_to_shared(&As[0][0][0]);
    uint32_t BsB = (uint32_t)__cvta_generic_to_shared(&Bs[0][0][0]);
    const uint32_t Aoff = (uint32_t)(wm * 64 + (lane & 15)) * 80 + ((lane >> 4) << 4);
    const uint32_t Boff = (uint32_t)(wn * 32 + ((lane >> 4) << 3) + (lane & 7)) * 80 +
                          (((lane >> 3) & 1) << 4);

#pragma unroll
    for (int pre = 0; pre < 2; pre++) {
        int kc = pre * 32;
        ldpair(&As[pre][r][cseg], X + (size_t)(m0 + r) * 256 + kc + cseg);
        ldpair(&Bs[pre][r][cseg], W + (size_t)(n0 + r) * 256 + kc + cseg);
        CP_COMMIT;
    }

    for (int ic = 0; ic < 8; ic++) {
        int cur = ic & 1;
        if (ic < 7)
            asm volatile("cp.async.wait_group 1;" ::: "memory");
        else
            asm volatile("cp.async.wait_group 0;" ::: "memory");
        __syncthreads();
        uint32_t ab = AsB + cur * 10240, bb = BsB + cur * 10240;
#pragma unroll
        for (int ks = 0; ks < 2; ks++) {
            uint32_t a[4][4];
#pragma unroll
            for (int i = 0; i < 4; i++)
                ldsm4(a[i][0], a[i][1], a[i][2], a[i][3],
                      ab + Aoff + i * 16 * 80 + ks * 32);
#pragma unroll
            for (int jp = 0; jp < 4; jp += 2) {
                uint32_t b0, b1, b2, b3;
                ldsm4(b0, b1, b2, b3, bb + Boff + jp * 8 * 80 + ks * 32);
#pragma unroll
                for (int i = 0; i < 4; i++) {
                    mma16816(c[i][jp], a[i][0], a[i][1], a[i][2], a[i][3], b0, b1);
                    mma16816(c[i][jp + 1], a[i][0], a[i][1], a[i][2], a[i][3], b2, b3);
                }
            }
        }
        __syncthreads();
        if (ic + 2 < 8) {
            int kc = (ic + 2) * 32;
            ldpair(&As[cur][r][cseg], X + (size_t)(m0 + r) * 256 + kc + cseg);
            ldpair(&Bs[cur][r][cseg], W + (size_t)(n0 + r) * 256 + kc + cseg);
        }
        CP_COMMIT;
    }

    int h = n0 >> 8, e0 = n0 & 255;
    int rq = lane >> 2, t2 = (lane & 3) * 2;
#pragma unroll
    for (int i = 0; i < 4; i++) {
        size_t rowA = (size_t)(b * Hh + h) * L + l0 + wm * 64 + i * 16 + rq;
#pragma unroll
        for (int j = 0; j < 4; j++) {
            int colb = e0 + wn * 32 + j * 8 + t2;
            *(__half2*)(out + rowA * 256 + colb) =
                __floats2half2_rn(c[i][j][0], c[i][j][1]);
            *(__half2*)(out + (rowA + 8) * 256 + colb) =
                __floats2half2_rn(c[i][j][2], c[i][j][3]);
        }
    }
}

// ---------------- attn_mean = (scale/H) * sum_h Q_h K_h^T  (f16, K=1024) ----------
__global__ __launch_bounds__(256, 2) void mean_kernel(float* __restrict__ out) {
    __shared__ __half As[2][128][40];
    __shared__ __half Bs[2][128][40];

    int q0 = blockIdx.x * 128, k0 = blockIdx.y * 128, b = blockIdx.z;
    int tid = threadIdx.x, wid = tid >> 5;
    int wm = wid & 1, wn = wid >> 1;
    int r = tid >> 1, cseg = (tid & 1) * 16;

    wmma::fragment<wmma::accumulator, 16, 16, 16, float> c[4][2];
#pragma unroll
    for (int i = 0; i < 4; i++)
#pragma unroll
        for (int j = 0; j < 2; j++) wmma::fill_fragment(c[i][j], 0.0f);

#pragma unroll
    for (int pre = 0; pre < 2; pre++) {
        int h = pre >> 3, kc = (pre & 7) * 32;
        ldpair(&As[pre][r][cseg],
               g_Q16 + ((size_t)(b * Hh + h) * LQ + q0 + r) * 256 + kc + cseg);
        ldpair(&Bs[pre][r][cseg],
               g_K16 + ((size_t)(b * Hh + h) * LK + k0 + r) * 256 + kc + cseg);
        CP_COMMIT;
    }

    for (int ic = 0; ic < 32; ic++) {
        int cur = ic & 1;
        if (ic < 31)
            asm volatile("cp.async.wait_group 1;" ::: "memory");
        else
            asm volatile("cp.async.wait_group 0;" ::: "memory");
        __syncthreads();
#pragma unroll
        for (int ks = 0; ks < 2; ks++) {
            wmma::fragment<wmma::matrix_b, 16, 16, 16, __half, wmma::col_major> bf[2];
#pragma unroll
            for (int j = 0; j < 2; j++)
                wmma::load_matrix_sync(bf[j], &Bs[cur][wn * 32 + j * 16][ks * 16], 40);
#pragma unroll
            for (int i = 0; i < 4; i++) {
                wmma::fragment<wmma::matrix_a, 16, 16, 16, __half, wmma::row_major> af;
                wmma::load_matrix_sync(af, &As[cur][wm * 64 + i * 16][ks * 16], 40);
#pragma unroll
                for (int j = 0; j < 2; j++)
                    wmma::mma_sync(c[i][j], af, bf[j], c[i][j]);
            }
        }
        __syncthreads();
        if (ic + 2 < 32) {
            int nc = ic + 2;
            int h = nc >> 3, kc = (nc & 7) * 32;
            ldpair(&As[cur][r][cseg],
                   g_Q16 + ((size_t)(b * Hh + h) * LQ + q0 + r) * 256 + kc + cseg);
            ldpair(&Bs[cur][r][cseg],
                   g_K16 + ((size_t)(b * Hh + h) * LK + k0 + r) * 256 + kc + cseg);
        }
        CP_COMMIT;
    }

    const float MSC = 0.015625f;  // (1/16)/4
#pragma unroll
    for (int i = 0; i < 4; i++)
#pragma unroll
        for (int j = 0; j < 2; j++) {
#pragma unroll
            for (int t = 0; t < c[i][j].num_elements; t++) c[i][j].x[t] *= MSC;
            wmma::store_matrix_sync(
                out + ((size_t)b * LQ + q0 + wm * 64 + i * 16) * LK + k0 +
                    wn * 32 + j * 16,
                c[i][j], LK, wmma::mem_row_major);
        }
}

// ---------------- flash attention v5: QT=128, warp-owned q-rows, no merge --------
// 8 warps; warp wid owns q-rows [wid*16, wid*16+16). Each iteration processes a
// 64-key tile; each warp computes S(16x64), softmax (warp-private, quad
// shuffles), P in registers (C->A identity), O(16x256) accumulated in registers.
#define FLASH_SMEM 202752
#define OF_Q 0
#define OF_K 67584
#define OF_V 135168
#define KROW 528  // bytes per 256-half row (+16B pad)

__device__ __forceinline__ void load_rows64(uint32_t dst, const __half* src,
                                            int tid) {
#pragma unroll
    for (int i = 0; i < 8; i++) {
        int t = tid + i * 256;
        int row = t >> 5, cc = t & 31;
        cp16(dst + row * KROW + cc * 16, src + (size_t)row * 256 + cc * 8);
    }
}
__device__ __forceinline__ void load_rows128(uint32_t dst, const __half* src,
                                             int tid) {
#pragma unroll
    for (int i = 0; i < 16; i++) {
        int t = tid + i * 256;
        int row = t >> 5, cc = t & 31;
        cp16(dst + row * KROW + cc * 16, src + (size_t)row * 256 + cc * 8);
    }
}

__global__ __launch_bounds__(256, 1) void flash_kernel() {
    extern __shared__ __align__(16) char dynsm[];
    char* sm = dynsm;
    int tid = threadIdx.x, lane = tid & 31, wid = tid >> 5;
    int q0 = blockIdx.x * 128;
    int bh = blockIdx.y;
    int b = bh >> 2, h = bh & 3;
    const __half* Qg = g_Q16 + ((size_t)bh * LQ + q0) * 256;
    const __half* Kg = g_K16 + (size_t)bh * LK * 256;
    const __half* Vg = g_V16 + (size_t)bh * LK * 256;

    uint32_t sb = (uint32_t)__cvta_generic_to_shared(sm);
    const uint32_t QB = sb + OF_Q, KB = sb + OF_K, VB = sb + OF_V;

    load_rows128(QB, Qg, tid);
    load_rows64(KB, Kg, tid);
    load_rows64(VB, Vg, tid);
    CP_COMMIT;
    load_rows64(KB + 33792, Kg + 64 * 256, tid);
    load_rows64(VB + 33792, Vg + 64 * 256, tid);
    CP_COMMIT;

    float o[32][4];
#pragma unroll
    for (int j = 0; j < 32; j++) o[j][0] = o[j][1] = o[j][2] = o[j][3] = 0.f;
    float mr0 = -1e30f, mr1 = -1e30f, l0 = 0.f, l1 = 0.f;
    const float SLOG = 0.0901699438f;  // (1/16)*log2(e)

    const uint32_t Aq = QB + (uint32_t)(wid * 16 + (lane & 15)) * KROW +
                        ((lane >> 4) << 4);
    // K x4 frag pair: rows (jp+(lane>>4))*8+(lane&7); b0/b1 by (lane>>3)&1
    const uint32_t Kb2 = (uint32_t)(((lane >> 4) << 3) + (lane & 7)) * KROW +
                         (((lane >> 3) & 1) << 4);
    // V x4 trans: rows (lane&15) within k-chunk; col-pair select by lane>>4
    const uint32_t Vb2 = (uint32_t)(lane & 15) * KROW + ((lane >> 4) << 4);

    for (int it = 0; it < LK / 64; it++) {
        int cur = it & 1;
        if (it < LK / 64 - 1)
            asm volatile("cp.async.wait_group 1;" ::: "memory");
        else
            asm volatile("cp.async.wait_group 0;" ::: "memory");
        __syncthreads();

        // S = Q K^T : 16 q-rows x 64 keys per warp
        uint32_t kb = KB + cur * 33792;
        float s[8][4];
#pragma unroll
        for (int j = 0; j < 8; j++) s[j][0] = s[j][1] = s[j][2] = s[j][3] = 0.f;
#pragma unroll
        for (int dk = 0; dk < 16; dk++) {
            uint32_t a0, a1, a2, a3;
            ldsm4(a0, a1, a2, a3, Aq + dk * 32);
#pragma unroll
            for (int jp = 0; jp < 8; jp += 2) {
                uint32_t b0, b1, b2, b3;
                ldsm4(b0, b1, b2, b3, kb + Kb2 + jp * 8 * KROW + dk * 32);
                mma16816(s[jp], a0, a1, a2, a3, b0, b1);
                mma16816(s[jp + 1], a0, a1, a2, a3, b2, b3);
            }
        }

        // warp-private online softmax (quad shuffles only)
        float pm0 = -1e30f, pm1 = -1e30f;
#pragma unroll
        for (int j = 0; j < 8; j++) {
            s[j][0] *= SLOG; s[j][1] *= SLOG; s[j][2] *= SLOG; s[j][3] *= SLOG;
            pm0 = fmaxf(pm0, fmaxf(s[j][0], s[j][1]));
            pm1 = fmaxf(pm1, fmaxf(s[j][2], s[j][3]));
        }
        pm0 = fmaxf(pm0, __shfl_xor_sync(~0u, pm0, 1));
        pm0 = fmaxf(pm0, __shfl_xor_sync(~0u, pm0, 2));
        pm1 = fmaxf(pm1, __shfl_xor_sync(~0u, pm1, 1));
        pm1 = fmaxf(pm1, __shfl_xor_sync(~0u, pm1, 2));
        float mn0 = fmaxf(mr0, pm0), mn1 = fmaxf(mr1, pm1);
        float al0 = ex2f(mr0 - mn0), al1 = ex2f(mr1 - mn1);
        mr0 = mn0; mr1 = mn1;

        // P = exp2(S - m) in place, accumulate row sums
        float ps0 = 0.f, ps1 = 0.f;
#pragma unroll
        for (int j = 0; j < 8; j++) {
            s[j][0] = ex2f(s[j][0] - mn0);
            s[j][1] = ex2f(s[j][1] - mn0);
            s[j][2] = ex2f(s[j][2] - mn1);
            s[j][3] = ex2f(s[j][3] - mn1);
            ps0 += s[j][0] + s[j][1];
            ps1 += s[j][2] + s[j][3];
        }
        ps0 += __shfl_xor_sync(~0u, ps0, 1);
        ps0 += __shfl_xor_sync(~0u, ps0, 2);
        ps1 += __shfl_xor_sync(~0u, ps1, 1);
        ps1 += __shfl_xor_sync(~0u, ps1, 2);
        l0 = al0 * l0 + ps0;
        l1 = al1 * l1 + ps1;
#pragma unroll
        for (int j = 0; j < 32; j++) {
            o[j][0] *= al0; o[j][1] *= al0; o[j][2] *= al1; o[j][3] *= al1;
        }

        // O += P @ V  (4 k-chunks of 16; P packed to A-fragments on the fly)
        uint32_t vb = VB + cur * 33792;
#pragma unroll
        for (int ks = 0; ks < 4; ks++) {
            uint32_t pa0 = packh2(s[2 * ks][0], s[2 * ks][1]);
            uint32_t pa1 = packh2(s[2 * ks][2], s[2 * ks][3]);
            uint32_t pa2 = packh2(s[2 * ks + 1][0], s[2 * ks + 1][1]);
            uint32_t pa3 = packh2(s[2 * ks + 1][2], s[2 * ks + 1][3]);
            uint32_t vrow = vb + Vb2 + ks * 16 * KROW;
#pragma unroll
            for (int jp = 0; jp < 32; jp += 2) {
                uint32_t b0, b1, b2, b3;
                ldsm4t(b0, b1, b2, b3, vrow + jp * 16);
                mma16816(o[jp], pa0, pa1, pa2, pa3, b0, b1);
                mma16816(o[jp + 1], pa0, pa1, pa2, pa3, b2, b3);
            }
        }
        __syncthreads();
        if (it + 2 < LK / 64) {
            load_rows64(KB + cur * 33792, Kg + (size_t)(it + 2) * 64 * 256, tid);
            load_rows64(VB + cur * 33792, Vg + (size_t)(it + 2) * 64 * 256, tid);
        }
        CP_COMMIT;
    }

    // ---- epilogue: direct store (warp owns its q-rows end-to-end) ----
    int rq = lane >> 2, t2 = (lane & 3) * 2;
    float inv0 = 1.f / l0, inv1 = 1.f / l1;
    size_t ob0 = ((size_t)b * LQ + q0 + wid * 16 + rq) * HD + h * 256 + t2;
    size_t ob1 = ob0 + (size_t)8 * HD;
#pragma unroll
    for (int j = 0; j < 32; j++) {
        *(__half2*)(g_O + ob0 + j * 8) =
            __floats2half2_rn(o[j][0] * inv0, o[j][1] * inv0);
        *(__half2*)(g_O + ob1 + j * 8) =
            __floats2half2_rn(o[j][2] * inv1, o[j][3] * inv1);
    }
}

// ---------------- fc + residual + LayerNorm (f16 GEMM) ----------------
__global__ __launch_bounds__(256) void fc_ln_kernel(const float* __restrict__ Wfc,
                                                    const float* __restrict__ tgt,
                                                    const float* __restrict__ gamma,
                                                    const float* __restrict__ beta,
                                                    float* __restrict__ Y) {
    __shared__ __align__(16) unsigned char smraw[33280];
    __half* As = (__half*)smraw;             // [32][48]
    __half* Bsh = (__half*)(smraw + 3072);   // [256][48]
    float* stage = (float*)smraw;            // [32][260]

    int m0 = blockIdx.x * 32;
    int tid = threadIdx.x, wid = tid >> 5, lane = tid & 31;
    int wm = wid & 1, wn = wid >> 1;

    wmma::fragment<wmma::accumulator, 16, 16, 16, float> c[4];
#pragma unroll
    for (int j = 0; j < 4; j++) wmma::fill_fragment(c[j], 0.0f);

    for (int kc = 0; kc < HD; kc += 32) {
        int r = tid >> 3, cb = (tid & 7) << 2;
        *(uint2*)&As[r * 48 + cb] =
            *(const uint2*)&g_O[(size_t)(m0 + r) * HD + kc + cb];
#pragma unroll
        for (int p = 0; p < 8; p++) {
            int rr = r + p * 32;
            float4 w = *(const float4*)&Wfc[(size_t)rr * HD + kc + cb];
            *(__half2*)&Bsh[rr * 48 + cb] = __floats2half2_rn(w.x, w.y);
            *(__half2*)&Bsh[rr * 48 + cb + 2] = __floats2half2_rn(w.z, w.w);
        }
        __syncthreads();
#pragma unroll
        for (int ks = 0; ks < 2; ks++) {
            wmma::fragment<wmma::matrix_a, 16, 16, 16, __half, wmma::row_major> af;
            wmma::load_matrix_sync(af, &As[(wm * 16) * 48 + ks * 16], 48);
#pragma unroll
            for (int j = 0; j < 4; j++) {
                wmma::fragment<wmma::matrix_b, 16, 16, 16, __half,
                               wmma::col_major> bfr;
                wmma::load_matrix_sync(bfr, &Bsh[(wn * 64 + j * 16) * 48 + ks * 16],
                                       48);
                wmma::mma_sync(c[j], af, bfr, c[j]);
            }
        }
        __syncthreads();
    }

#pragma unroll
    for (int j = 0; j < 4; j++)
        wmma::store_matrix_sync(&stage[(wm * 16) * 260 + wn * 64 + j * 16], c[j],
                                260, wmma::mem_row_major);
    __syncthreads();

#pragma unroll
    for (int s = 0; s < 4; s++) {
        int row = wid * 4 + s;
        int m = m0 + row;
        int b = m >> 10, l = m & 1023;
        const float* trow = tgt + ((size_t)l * Bb + b) * 256;
        float v[8], sum = 0.f, sq = 0.f;
#pragma unroll
        for (int t = 0; t < 8; t++) {
            v[t] = stage[row * 260 + lane * 8 + t] + trow[lane * 8 + t];
            sum += v[t];
            sq += v[t] * v[t];
        }
#pragma unroll
        for (int oo = 16; oo > 0; oo >>= 1) {
            sum += __shfl_xor_sync(~0u, sum, oo);
            sq += __shfl_xor_sync(~0u, sq, oo);
        }
        float mu = sum * (1.0f / 256.0f);
        float var = sq * (1.0f / 256.0f) - mu * mu;
        float rsg = rsqrtf(var + 1e-5f);
        float* yr = Y + ((size_t)l * Bb + b) * 256;
#pragma unroll
        for (int t = 0; t < 8; t++) {
            int d = lane * 8 + t;
            yr[d] = (v[t] - mu) * rsg * gamma[d] + beta[d];
        }
    }
}

// ---------------- launch ----------------
extern "C" void kernel_launch(void* const* d_in, const int* in_sizes, int n_in,
                              void* d_out, int out_size) {
    const float* tgt  = (const float*)d_in[0];
    const float* mem  = (const float*)d_in[1];
    const float* pos  = (const float*)d_in[2];
    const float* qpos = (const float*)d_in[3];
    const float* Wq   = (const float*)d_in[4];
    const float* Wk   = (const float*)d_in[5];
    const float* Wv   = (const float*)d_in[6];
    const float* Wfc  = (const float*)d_in[7];
    const float* ln_g = (const float*)d_in[8];
    const float* ln_b = (const float*)d_in[9];

    float* y_out    = (float*)d_out;                         // [LQ,B,D]
    float* attn_out = (float*)d_out + (size_t)LQ * Bb * Dm;  // [B,1,LQ,LK]

    cudaFuncSetAttribute(flash_kernel,
                         cudaFuncAttributeMaxDynamicSharedMemorySize, FLASH_SMEM);

    // input + weight conversion to f16
    cvtx_kernel<<<(Bb * LQ * 64) / 256, 256>>>(tgt, qpos, LQ, 0);
    cvtx_kernel<<<(Bb * LK * 64) / 256, 256>>>(mem, pos, LK, 1);
    cvtx_kernel<<<(Bb * LK * 64) / 256, 256>>>(mem, (const float*)0, LK, 2);
    cvtw_kernel<<<(HD * Dm / 4) / 256, 256>>>(Wq, 0);
    cvtw_kernel<<<(HD * Dm / 4) / 256, 256>>>(Wk, 1);
    cvtw_kernel<<<(HD * Dm / 4) / 256, 256>>>(Wv, 2);

    // projections (f16, raw mma)
    proj_kernel<<<dim3(Bb * LQ / 128, HD / 128), 256>>>(0, LQ);
    proj_kernel<<<dim3(Bb * LK / 128, HD / 128), 256>>>(1, LK);
    proj_kernel<<<dim3(Bb * LK / 128, HD / 128), 256>>>(2, LK);

    // attn_mean: f16 GEMM over concat heads (K=1024)
    mean_kernel<<<dim3(LQ / 128, LK / 128, Bb), 256>>>(attn_out);

    // flash attention v5 (f16, QT=128), writes g_O
    flash_kernel<<<dim3(LQ / 128, Bb * Hh), 256, FLASH_SMEM>>>();

    // fc + residual + layernorm
    fc_ln_kernel<<<(Bb * LQ) / 32, 256>>>(Wfc, tgt, ln_g, ln_b, y_out);
}

// round 14
// speedup vs baseline: 2.7187x; 1.0061x over previous
#include <cuda_runtime.h>
#include <cuda_bf16.h>
#include <cuda_fp16.h>
#include <cstdint>
#include <cstddef>
#include <mma.h>

using namespace nvcuda;

#define Bb 8
#define Hh 4
#define LQ 1024
#define LK 4096
#define Dm 256
#define HD 1024

// ---------------- scratch (device globals; no allocations) ----------------
__device__ __half g_Xq16[(size_t)Bb * LQ * Dm];       //  4 MB [B,Lq,256]
__device__ __half g_Xk16[(size_t)Bb * LK * Dm];       // 16 MB [B,Lk,256]
__device__ __half g_Xv16[(size_t)Bb * LK * Dm];       // 16 MB
__device__ __half g_W16[(size_t)3 * HD * Dm];         // 1.5 MB (Wq,Wk,Wv f16)
__device__ __half g_Q16[(size_t)Bb * Hh * LQ * Dm];   // 16 MB [B,H,Lq,256]
__device__ __half g_K16[(size_t)Bb * Hh * LK * Dm];   // 64 MB
__device__ __half g_V16[(size_t)Bb * Hh * LK * Dm];   // 64 MB
__device__ __half g_O[(size_t)Bb * LQ * HD];          // 16 MB [B*Lq, H*256]

// ---------------- PTX helpers ----------------
__device__ __forceinline__ float ex2f(float x) {
    float r;
    asm("ex2.approx.ftz.f32 %0, %1;" : "=f"(r) : "f"(x));
    return r;
}
__device__ __forceinline__ uint32_t packh2(float x, float y) {
    __half2 h = __floats2half2_rn(x, y);
    return *(uint32_t*)&h;
}
__device__ __forceinline__ void ldsm4(uint32_t& a0, uint32_t& a1, uint32_t& a2,
                                      uint32_t& a3, uint32_t addr) {
    asm volatile("ldmatrix.sync.aligned.m8n8.x4.shared.b16 {%0,%1,%2,%3},[%4];"
                 : "=r"(a0), "=r"(a1), "=r"(a2), "=r"(a3) : "r"(addr));
}
__device__ __forceinline__ void ldsm4t(uint32_t& a0, uint32_t& a1, uint32_t& a2,
                                       uint32_t& a3, uint32_t addr) {
    asm volatile("ldmatrix.sync.aligned.m8n8.x4.trans.shared.b16 {%0,%1,%2,%3},[%4];"
                 : "=r"(a0), "=r"(a1), "=r"(a2), "=r"(a3) : "r"(addr));
}
__device__ __forceinline__ void mma16816(float* d, uint32_t a0, uint32_t a1,
                                         uint32_t a2, uint32_t a3, uint32_t b0,
                                         uint32_t b1) {
    asm volatile(
        "mma.sync.aligned.m16n8k16.row.col.f32.f16.f16.f32 "
        "{%0,%1,%2,%3},{%4,%5,%6,%7},{%8,%9},{%0,%1,%2,%3};"
        : "+f"(d[0]), "+f"(d[1]), "+f"(d[2]), "+f"(d[3])
        : "r"(a0), "r"(a1), "r"(a2), "r"(a3), "r"(b0), "r"(b1));
}
__device__ __forceinline__ void cp16(uint32_t dst, const void* src) {
    asm volatile("cp.async.cg.shared.global [%0],[%1],16;" ::"r"(dst), "l"(src)
                 : "memory");
}
#define CP_COMMIT asm volatile("cp.async.commit_group;" ::: "memory")
__device__ __forceinline__ void ldpair(void* sdst, const __half* g) {
    uint32_t d = (uint32_t)__cvta_generic_to_shared(sdst);
    cp16(d, g);
    cp16(d + 16, g + 8);
}

// ---------------- merged input convert: [L,B,D]->(+add)->[B,L,D] f16 ------------
// ranges: Q float4s [0, 524288), K [524288, 2621440), V [2621440, 4718592)
__global__ void cvtx_all_kernel(const float* __restrict__ tgt,
                                const float* __restrict__ mem,
                                const float* __restrict__ pos,
                                const float* __restrict__ qpos) {
    long idx = (long)blockIdx.x * blockDim.x + threadIdx.x;
    const float* in1;
    const float* in2;
    __half* out;
    int L;
    if (idx < 524288L) {
        in1 = tgt; in2 = qpos; out = g_Xq16; L = LQ;
    } else if (idx < 2621440L) {
        idx -= 524288L;
        in1 = mem; in2 = pos; out = g_Xk16; L = LK;
    } else {
        idx -= 2621440L;
        in1 = mem; in2 = (const float*)0; out = g_Xv16; L = LK;
    }
    int d4 = (int)(idx & 63);
    long m = idx >> 6;
    int b = (int)(m / L);
    int l = (int)(m - (long)b * L);
    float4 v = ((const float4*)in1)[((size_t)l * Bb + b) * 64 + d4];
    if (in2) {
        float4 w = ((const float4*)in2)[((size_t)l * Bb + b) * 64 + d4];
        v.x += w.x; v.y += w.y; v.z += w.z; v.w += w.w;
    }
    __half2 h0 = __floats2half2_rn(v.x, v.y);
    __half2 h1 = __floats2half2_rn(v.z, v.w);
    uint2 u;
    u.x = *(uint32_t*)&h0;
    u.y = *(uint32_t*)&h1;
    ((uint2*)out)[idx] = u;
}

__global__ void cvtw_all_kernel(const float* __restrict__ Wq,
                                const float* __restrict__ Wk,
                                const float* __restrict__ Wv) {
    int sel = blockIdx.y;
    const float* src = (sel == 0) ? Wq : (sel == 1) ? Wk : Wv;
    __half* out = g_W16 + (size_t)sel * HD * Dm;
    int idx = blockIdx.x * blockDim.x + threadIdx.x;  // one float4
    float4 v = ((const float4*)src)[idx];
    __half2 h0 = __floats2half2_rn(v.x, v.y);
    __half2 h1 = __floats2half2_rn(v.z, v.w);
    uint2 u;
    u.x = *(uint32_t*)&h0;
    u.y = *(uint32_t*)&h1;
    ((uint2*)out)[idx] = u;
}

// ---------------- merged projection GEMM (raw mma, direct-register epilogue) ----
// blockIdx.x in [0,576): [0,64)=Q m-blocks, [64,320)=K, [320,576)=V
__global__ __launch_bounds__(256, 2) void proj_all_kernel() {
    int bx = blockIdx.x;
    int sel, mblk;
    if (bx < 64) { sel = 0; mblk = bx; }
    else if (bx < 320) { sel = 1; mblk = bx - 64; }
    else { sel = 2; mblk = bx - 320; }
    int L = sel ? LK : LQ;
    const __half* X = (sel == 0) ? g_Xq16 : (sel == 1) ? g_Xk16 : g_Xv16;
    const __half* W = g_W16 + (size_t)sel * HD * Dm;
    __half* out = (sel == 0) ? g_Q16 : (sel == 1) ? g_K16 : g_V16;

    __shared__ __half As[2][128][40];
    __shared__ __half Bs[2][128][40];

    int m0 = mblk * 128, n0 = blockIdx.y * 128;
    int b = m0 / L, l0 = m0 % L;
    int tid = threadIdx.x, wid = tid >> 5, lane = tid & 31;
    int wm = wid & 1, wn = wid >> 1;
    int r = tid >> 1, cseg = (tid & 1) * 16;

    float c[4][4][4];
#pragma unroll
    for (int i = 0; i < 4; i++)
#pragma unroll
        for (int j = 0; j < 4; j++)
            c[i][j][0] = c[i][j][1] = c[i][j][2] = c[i][j][3] = 0.f;

    uint32_t AsB = (uint32_t)__cvta_generic_to_shared(&As[0][0][0]);
    uint32_t BsB = (uint32_t)__cvta_generic_to_shared(&Bs[0][0][0]);
    const uint32_t Aoff = (uint32_t)(wm * 64 + (lane & 15)) * 80 + ((lane >> 4) << 4);
    const uint32_t Boff = (uint32_t)(wn * 32 + ((lane >> 4) << 3) + (lane & 7)) * 80 +
                          (((lane >> 3) & 1) << 4);

#pragma unroll
    for (int pre = 0; pre < 2; pre++) {
        int kc = pre * 32;
        ldpair(&As[pre][r][cseg], X + (size_t)(m0 + r) * 256 + kc + cseg);
        ldpair(&Bs[pre][r][cseg], W + (size_t)(n0 + r) * 256 + kc + cseg);
        CP_COMMIT;
    }

    for (int ic = 0; ic < 8; ic++) {
        int cur = ic & 1;
        if (ic < 7)
            asm volatile("cp.async.wait_group 1;" ::: "memory");
        else
            asm volatile("cp.async.wait_group 0;" ::: "memory");
        __syncthreads();
        uint32_t ab = AsB + cur * 10240, bb = BsB + cur * 10240;
#pragma unroll
        for (int ks = 0; ks < 2; ks++) {
            uint32_t a[4][4];
#pragma unroll
            for (int i = 0; i < 4; i++)
                ldsm4(a[i][0], a[i][1], a[i][2], a[i][3],
                      ab + Aoff + i * 16 * 80 + ks * 32);
#pragma unroll
            for (int jp = 0; jp < 4; jp += 2) {
                uint32_t b0, b1, b2, b3;
                ldsm4(b0, b1, b2, b3, bb + Boff + jp * 8 * 80 + ks * 32);
#pragma unroll
                for (int i = 0; i < 4; i++) {
                    mma16816(c[i][jp], a[i][0], a[i][1], a[i][2], a[i][3], b0, b1);
                    mma16816(c[i][jp + 1], a[i][0], a[i][1], a[i][2], a[i][3], b2, b3);
                }
            }
        }
        __syncthreads();
        if (ic + 2 < 8) {
            int kc = (ic + 2) * 32;
            ldpair(&As[cur][r][cseg], X + (size_t)(m0 + r) * 256 + kc + cseg);
            ldpair(&Bs[cur][r][cseg], W + (size_t)(n0 + r) * 256 + kc + cseg);
        }
        CP_COMMIT;
    }

    int h = n0 >> 8, e0 = n0 & 255;
    int rq = lane >> 2, t2 = (lane & 3) * 2;
#pragma unroll
    for (int i = 0; i < 4; i++) {
        size_t rowA = (size_t)(b * Hh + h) * L + l0 + wm * 64 + i * 16 + rq;
#pragma unroll
        for (int j = 0; j < 4; j++) {
            int colb = e0 + wn * 32 + j * 8 + t2;
            *(__half2*)(out + rowA * 256 + colb) =
                __floats2half2_rn(c[i][j][0], c[i][j][1]);
            *(__half2*)(out + (rowA + 8) * 256 + colb) =
                __floats2half2_rn(c[i][j][2], c[i][j][3]);
        }
    }
}

// ---------------- attn_mean = (scale/H) * sum_h Q_h K_h^T  (f16, K=1024) ----------
__global__ __launch_bounds__(256, 2) void mean_kernel(float* __restrict__ out,
                                                      int zoff) {
    __shared__ __half As[2][128][40];
    __shared__ __half Bs[2][128][40];

    int q0 = blockIdx.x * 128, k0 = blockIdx.y * 128, b = blockIdx.z + zoff;
    int tid = threadIdx.x, wid = tid >> 5;
    int wm = wid & 1, wn = wid >> 1;
    int r = tid >> 1, cseg = (tid & 1) * 16;

    wmma::fragment<wmma::accumulator, 16, 16, 16, float> c[4][2];
#pragma unroll
    for (int i = 0; i < 4; i++)
#pragma unroll
        for (int j = 0; j < 2; j++) wmma::fill_fragment(c[i][j], 0.0f);

#pragma unroll
    for (int pre = 0; pre < 2; pre++) {
        int h = pre >> 3, kc = (pre & 7) * 32;
        ldpair(&As[pre][r][cseg],
               g_Q16 + ((size_t)(b * Hh + h) * LQ + q0 + r) * 256 + kc + cseg);
        ldpair(&Bs[pre][r][cseg],
               g_K16 + ((size_t)(b * Hh + h) * LK + k0 + r) * 256 + kc + cseg);
        CP_COMMIT;
    }

    for (int ic = 0; ic < 32; ic++) {
        int cur = ic & 1;
        if (ic < 31)
            asm volatile("cp.async.wait_group 1;" ::: "memory");
        else
            asm volatile("cp.async.wait_group 0;" ::: "memory");
        __syncthreads();
#pragma unroll
        for (int ks = 0; ks < 2; ks++) {
            wmma::fragment<wmma::matrix_b, 16, 16, 16, __half, wmma::col_major> bf[2];
#pragma unroll
            for (int j = 0; j < 2; j++)
                wmma::load_matrix_sync(bf[j], &Bs[cur][wn * 32 + j * 16][ks * 16], 40);
#pragma unroll
            for (int i = 0; i < 4; i++) {
                wmma::fragment<wmma::matrix_a, 16, 16, 16, __half, wmma::row_major> af;
                wmma::load_matrix_sync(af, &As[cur][wm * 64 + i * 16][ks * 16], 40);
#pragma unroll
                for (int j = 0; j < 2; j++)
                    wmma::mma_sync(c[i][j], af, bf[j], c[i][j]);
            }
        }
        __syncthreads();
        if (ic + 2 < 32) {
            int nc = ic + 2;
            int h = nc >> 3, kc = (nc & 7) * 32;
            ldpair(&As[cur][r][cseg],
                   g_Q16 + ((size_t)(b * Hh + h) * LQ + q0 + r) * 256 + kc + cseg);
            ldpair(&Bs[cur][r][cseg],
                   g_K16 + ((size_t)(b * Hh + h) * LK + k0 + r) * 256 + kc + cseg);
        }
        CP_COMMIT;
    }

    const float MSC = 0.015625f;  // (1/16)/4
#pragma unroll
    for (int i = 0; i < 4; i++)
#pragma unroll
        for (int j = 0; j < 2; j++) {
#pragma unroll
            for (int t = 0; t < c[i][j].num_elements; t++) c[i][j].x[t] *= MSC;
            wmma::store_matrix_sync(
                out + ((size_t)b * LQ + q0 + wm * 64 + i * 16) * LK + k0 +
                    wn * 32 + j * 16,
                c[i][j], LK, wmma::mem_row_major);
        }
}

// ---------------- flash attention v5: QT=128, warp-owned q-rows, no merge --------
#define FLASH_SMEM 202752
#define OF_Q 0
#define OF_K 67584
#define OF_V 135168
#define KROW 528  // bytes per 256-half row (+16B pad)

__device__ __forceinline__ void load_rows64(uint32_t dst, const __half* src,
                                            int tid) {
#pragma unroll
    for (int i = 0; i < 8; i++) {
        int t = tid + i * 256;
        int row = t >> 5, cc = t & 31;
        cp16(dst + row * KROW + cc * 16, src + (size_t)row * 256 + cc * 8);
    }
}
__device__ __forceinline__ void load_rows128(uint32_t dst, const __half* src,
                                             int tid) {
#pragma unroll
    for (int i = 0; i < 16; i++) {
        int t = tid + i * 256;
        int row = t >> 5, cc = t & 31;
        cp16(dst + row * KROW + cc * 16, src + (size_t)row * 256 + cc * 8);
    }
}

__global__ __launch_bounds__(256, 1) void flash_kernel() {
    extern __shared__ __align__(16) char dynsm[];
    char* sm = dynsm;
    int tid = threadIdx.x, lane = tid & 31, wid = tid >> 5;
    int q0 = blockIdx.x * 128;
    int bh = blockIdx.y;
    int b = bh >> 2, h = bh & 3;
    const __half* Qg = g_Q16 + ((size_t)bh * LQ + q0) * 256;
    const __half* Kg = g_K16 + (size_t)bh * LK * 256;
    const __half* Vg = g_V16 + (size_t)bh * LK * 256;

    uint32_t sb = (uint32_t)__cvta_generic_to_shared(sm);
    const uint32_t QB = sb + OF_Q, KB = sb + OF_K, VB = sb + OF_V;

    load_rows128(QB, Qg, tid);
    load_rows64(KB, Kg, tid);
    load_rows64(VB, Vg, tid);
    CP_COMMIT;
    load_rows64(KB + 33792, Kg + 64 * 256, tid);
    load_rows64(VB + 33792, Vg + 64 * 256, tid);
    CP_COMMIT;

    float o[32][4];
#pragma unroll
    for (int j = 0; j < 32; j++) o[j][0] = o[j][1] = o[j][2] = o[j][3] = 0.f;
    float mr0 = -1e30f, mr1 = -1e30f, l0 = 0.f, l1 = 0.f;
    const float SLOG = 0.0901699438f;  // (1/16)*log2(e)

    const uint32_t Aq = QB + (uint32_t)(wid * 16 + (lane & 15)) * KROW +
                        ((lane >> 4) << 4);
    const uint32_t Kb2 = (uint32_t)(((lane >> 4) << 3) + (lane & 7)) * KROW +
                         (((lane >> 3) & 1) << 4);
    const uint32_t Vb2 = (uint32_t)(lane & 15) * KROW + ((lane >> 4) << 4);

    for (int it = 0; it < LK / 64; it++) {
        int cur = it & 1;
        if (it < LK / 64 - 1)
            asm volatile("cp.async.wait_group 1;" ::: "memory");
        else
            asm volatile("cp.async.wait_group 0;" ::: "memory");
        __syncthreads();

        // S = Q K^T : 16 q-rows x 64 keys per warp
        uint32_t kb = KB + cur * 33792;
        float s[8][4];
#pragma unroll
        for (int j = 0; j < 8; j++) s[j][0] = s[j][1] = s[j][2] = s[j][3] = 0.f;
#pragma unroll
        for (int dk = 0; dk < 16; dk++) {
            uint32_t a0, a1, a2, a3;
            ldsm4(a0, a1, a2, a3, Aq + dk * 32);
#pragma unroll
            for (int jp = 0; jp < 8; jp += 2) {
                uint32_t b0, b1, b2, b3;
                ldsm4(b0, b1, b2, b3, kb + Kb2 + jp * 8 * KROW + dk * 32);
                mma16816(s[jp], a0, a1, a2, a3, b0, b1);
                mma16816(s[jp + 1], a0, a1, a2, a3, b2, b3);
            }
        }

        // warp-private online softmax (quad shuffles only)
        float pm0 = -1e30f, pm1 = -1e30f;
#pragma unroll
        for (int j = 0; j < 8; j++) {
            s[j][0] *= SLOG; s[j][1] *= SLOG; s[j][2] *= SLOG; s[j][3] *= SLOG;
            pm0 = fmaxf(pm0, fmaxf(s[j][0], s[j][1]));
            pm1 = fmaxf(pm1, fmaxf(s[j][2], s[j][3]));
        }
        pm0 = fmaxf(pm0, __shfl_xor_sync(~0u, pm0, 1));
        pm0 = fmaxf(pm0, __shfl_xor_sync(~0u, pm0, 2));
        pm1 = fmaxf(pm1, __shfl_xor_sync(~0u, pm1, 1));
        pm1 = fmaxf(pm1, __shfl_xor_sync(~0u, pm1, 2));
        float mn0 = fmaxf(mr0, pm0), mn1 = fmaxf(mr1, pm1);
        float al0 = ex2f(mr0 - mn0), al1 = ex2f(mr1 - mn1);
        mr0 = mn0; mr1 = mn1;

        // P = exp2(S - m) in place, accumulate row sums
        float ps0 = 0.f, ps1 = 0.f;
#pragma unroll
        for (int j = 0; j < 8; j++) {
            s[j][0] = ex2f(s[j][0] - mn0);
            s[j][1] = ex2f(s[j][1] - mn0);
            s[j][2] = ex2f(s[j][2] - mn1);
            s[j][3] = ex2f(s[j][3] - mn1);
            ps0 += s[j][0] + s[j][1];
            ps1 += s[j][2] + s[j][3];
        }
        ps0 += __shfl_xor_sync(~0u, ps0, 1);
        ps0 += __shfl_xor_sync(~0u, ps0, 2);
        ps1 += __shfl_xor_sync(~0u, ps1, 1);
        ps1 += __shfl_xor_sync(~0u, ps1, 2);
        l0 = al0 * l0 + ps0;
        l1 = al1 * l1 + ps1;
#pragma unroll
        for (int j = 0; j < 32; j++) {
            o[j][0] *= al0; o[j][1] *= al0; o[j][2] *= al1; o[j][3] *= al1;
        }

        // O += P @ V  (4 k-chunks of 16; P packed to A-fragments on the fly)
        uint32_t vb = VB + cur * 33792;
#pragma unroll
        for (int ks = 0; ks < 4; ks++) {
            uint32_t pa0 = packh2(s[2 * ks][0], s[2 * ks][1]);
            uint32_t pa1 = packh2(s[2 * ks][2], s[2 * ks][3]);
            uint32_t pa2 = packh2(s[2 * ks + 1][0], s[2 * ks + 1][1]);
            uint32_t pa3 = packh2(s[2 * ks + 1][2], s[2 * ks + 1][3]);
            uint32_t vrow = vb + Vb2 + ks * 16 * KROW;
#pragma unroll
            for (int jp = 0; jp < 32; jp += 2) {
                uint32_t b0, b1, b2, b3;
                ldsm4t(b0, b1, b2, b3, vrow + jp * 16);
                mma16816(o[jp], pa0, pa1, pa2, pa3, b0, b1);
                mma16816(o[jp + 1], pa0, pa1, pa2, pa3, b2, b3);
            }
        }
        __syncthreads();
        if (it + 2 < LK / 64) {
            load_rows64(KB + cur * 33792, Kg + (size_t)(it + 2) * 64 * 256, tid);
            load_rows64(VB + cur * 33792, Vg + (size_t)(it + 2) * 64 * 256, tid);
        }
        CP_COMMIT;
    }

    // ---- epilogue: direct store (warp owns its q-rows end-to-end) ----
    int rq = lane >> 2, t2 = (lane & 3) * 2;
    float inv0 = 1.f / l0, inv1 = 1.f / l1;
    size_t ob0 = ((size_t)b * LQ + q0 + wid * 16 + rq) * HD + h * 256 + t2;
    size_t ob1 = ob0 + (size_t)8 * HD;
#pragma unroll
    for (int j = 0; j < 32; j++) {
        *(__half2*)(g_O + ob0 + j * 8) =
            __floats2half2_rn(o[j][0] * inv0, o[j][1] * inv0);
        *(__half2*)(g_O + ob1 + j * 8) =
            __floats2half2_rn(o[j][2] * inv1, o[j][3] * inv1);
    }
}

// ---------------- fc + residual + LayerNorm (f16 GEMM) ----------------
__global__ __launch_bounds__(256) void fc_ln_kernel(const float* __restrict__ Wfc,
                                                    const float* __restrict__ tgt,
                                                    const float* __restrict__ gamma,
                                                    const float* __restrict__ beta,
                                                    float* __restrict__ Y) {
    __shared__ __align__(16) unsigned char smraw[33280];
    __half* As = (__half*)smraw;             // [32][48]
    __half* Bsh = (__half*)(smraw + 3072);   // [256][48]
    float* stage = (float*)smraw;            // [32][260]

    int m0 = blockIdx.x * 32;
    int tid = threadIdx.x, wid = tid >> 5, lane = tid & 31;
    int wm = wid & 1, wn = wid >> 1;

    wmma::fragment<wmma::accumulator, 16, 16, 16, float> c[4];
#pragma unroll
    for (int j = 0; j < 4; j++) wmma::fill_fragment(c[j], 0.0f);

    for (int kc = 0; kc < HD; kc += 32) {
        int r = tid >> 3, cb = (tid & 7) << 2;
        *(uint2*)&As[r * 48 + cb] =
            *(const uint2*)&g_O[(size_t)(m0 + r) * HD + kc + cb];
#pragma unroll
        for (int p = 0; p < 8; p++) {
            int rr = r + p * 32;
            float4 w = *(const float4*)&Wfc[(size_t)rr * HD + kc + cb];
            *(__half2*)&Bsh[rr * 48 + cb] = __floats2half2_rn(w.x, w.y);
            *(__half2*)&Bsh[rr * 48 + cb + 2] = __floats2half2_rn(w.z, w.w);
        }
        __syncthreads();
#pragma unroll
        for (int ks = 0; ks < 2; ks++) {
            wmma::fragment<wmma::matrix_a, 16, 16, 16, __half, wmma::row_major> af;
            wmma::load_matrix_sync(af, &As[(wm * 16) * 48 + ks * 16], 48);
#pragma unroll
            for (int j = 0; j < 4; j++) {
                wmma::fragment<wmma::matrix_b, 16, 16, 16, __half,
                               wmma::col_major> bfr;
                wmma::load_matrix_sync(bfr, &Bsh[(wn * 64 + j * 16) * 48 + ks * 16],
                                       48);
                wmma::mma_sync(c[j], af, bfr, c[j]);
            }
        }
        __syncthreads();
    }

#pragma unroll
    for (int j = 0; j < 4; j++)
        wmma::store_matrix_sync(&stage[(wm * 16) * 260 + wn * 64 + j * 16], c[j],
                                260, wmma::mem_row_major);
    __syncthreads();

#pragma unroll
    for (int s = 0; s < 4; s++) {
        int row = wid * 4 + s;
        int m = m0 + row;
        int b = m >> 10, l = m & 1023;
        const float* trow = tgt + ((size_t)l * Bb + b) * 256;
        float v[8], sum = 0.f, sq = 0.f;
#pragma unroll
        for (int t = 0; t < 8; t++) {
            v[t] = stage[row * 260 + lane * 8 + t] + trow[lane * 8 + t];
            sum += v[t];
            sq += v[t] * v[t];
        }
#pragma unroll
        for (int oo = 16; oo > 0; oo >>= 1) {
            sum += __shfl_xor_sync(~0u, sum, oo);
            sq += __shfl_xor_sync(~0u, sq, oo);
        }
        float mu = sum * (1.0f / 256.0f);
        float var = sq * (1.0f / 256.0f) - mu * mu;
        float rsg = rsqrtf(var + 1e-5f);
        float* yr = Y + ((size_t)l * Bb + b) * 256;
#pragma unroll
        for (int t = 0; t < 8; t++) {
            int d = lane * 8 + t;
            yr[d] = (v[t] - mu) * rsg * gamma[d] + beta[d];
        }
    }
}

// ---------------- launch ----------------
extern "C" void kernel_launch(void* const* d_in, const int* in_sizes, int n_in,
                              void* d_out, int out_size) {
    const float* tgt  = (const float*)d_in[0];
    const float* mem  = (const float*)d_in[1];
    const float* pos  = (const float*)d_in[2];
    const float* qpos = (const float*)d_in[3];
    const float* Wq   = (const float*)d_in[4];
    const float* Wk   = (const float*)d_in[5];
    const float* Wv   = (const float*)d_in[6];
    const float* Wfc  = (const float*)d_in[7];
    const float* ln_g = (const float*)d_in[8];
    const float* ln_b = (const float*)d_in[9];

    float* y_out    = (float*)d_out;                         // [LQ,B,D]
    float* attn_out = (float*)d_out + (size_t)LQ * Bb * Dm;  // [B,1,LQ,LK]

    cudaFuncSetAttribute(flash_kernel,
                         cudaFuncAttributeMaxDynamicSharedMemorySize, FLASH_SMEM);

    // [0] merged input convert (Q|K|V ranges)
    cvtx_all_kernel<<<18432, 256>>>(tgt, mem, pos, qpos);
    // [1] merged weight convert
    cvtw_all_kernel<<<dim3(256, 3), 256>>>(Wq, Wk, Wv);
    // [2] merged projections (Q|K|V m-block ranges)
    proj_all_kernel<<<dim3(576, 8), 256>>>();
    // [3][4] attn_mean in two z-halves
    mean_kernel<<<dim3(LQ / 128, LK / 128, 4), 256>>>(attn_out, 0);
    mean_kernel<<<dim3(LQ / 128, LK / 128, 4), 256>>>(attn_out, 4);
    // [5] flash attention (profiled launch)
    flash_kernel<<<dim3(LQ / 128, Bb * Hh), 256, FLASH_SMEM>>>();
    // [6] fc + residual + layernorm
    fc_ln_kernel<<<(Bb * LQ) / 32, 256>>>(Wfc, tgt, ln_g, ln_b, y_out);
}

// round 15
// speedup vs baseline: 2.7418x; 1.0085x over previous
#include <cuda_runtime.h>
#include <cuda_bf16.h>
#include <cuda_fp16.h>
#include <cstdint>
#include <cstddef>
#include <mma.h>

using namespace nvcuda;

#define Bb 8
#define Hh 4
#define LQ 1024
#define LK 4096
#define Dm 256
#define HD 1024

// ---------------- scratch (device globals; no allocations) ----------------
__device__ __half g_Xq16[(size_t)Bb * LQ * Dm];       //  4 MB [B,Lq,256]
__device__ __half g_Xk16[(size_t)Bb * LK * Dm];       // 16 MB [B,Lk,256]
__device__ __half g_Xv16[(size_t)Bb * LK * Dm];       // 16 MB
__device__ __half g_W16[(size_t)3 * HD * Dm];         // 1.5 MB (Wq,Wk,Wv f16)
__device__ __half g_Q16[(size_t)Bb * Hh * LQ * Dm];   // 16 MB [B,H,Lq,256]
__device__ __half g_K16[(size_t)Bb * Hh * LK * Dm];   // 64 MB
__device__ __half g_V16[(size_t)Bb * Hh * LK * Dm];   // 64 MB
__device__ __half g_O[(size_t)Bb * LQ * HD];          // 16 MB [B*Lq, H*256]

// ---------------- PTX helpers ----------------
__device__ __forceinline__ float ex2f(float x) {
    float r;
    asm("ex2.approx.ftz.f32 %0, %1;" : "=f"(r) : "f"(x));
    return r;
}
__device__ __forceinline__ uint32_t packh2(float x, float y) {
    __half2 h = __floats2half2_rn(x, y);
    return *(uint32_t*)&h;
}
__device__ __forceinline__ void ldsm4(uint32_t& a0, uint32_t& a1, uint32_t& a2,
                                      uint32_t& a3, uint32_t addr) {
    asm volatile("ldmatrix.sync.aligned.m8n8.x4.shared.b16 {%0,%1,%2,%3},[%4];"
                 : "=r"(a0), "=r"(a1), "=r"(a2), "=r"(a3) : "r"(addr));
}
__device__ __forceinline__ void ldsm4t(uint32_t& a0, uint32_t& a1, uint32_t& a2,
                                       uint32_t& a3, uint32_t addr) {
    asm volatile("ldmatrix.sync.aligned.m8n8.x4.trans.shared.b16 {%0,%1,%2,%3},[%4];"
                 : "=r"(a0), "=r"(a1), "=r"(a2), "=r"(a3) : "r"(addr));
}
__device__ __forceinline__ void mma16816(float* d, uint32_t a0, uint32_t a1,
                                         uint32_t a2, uint32_t a3, uint32_t b0,
                                         uint32_t b1) {
    asm volatile(
        "mma.sync.aligned.m16n8k16.row.col.f32.f16.f16.f32 "
        "{%0,%1,%2,%3},{%4,%5,%6,%7},{%8,%9},{%0,%1,%2,%3};"
        : "+f"(d[0]), "+f"(d[1]), "+f"(d[2]), "+f"(d[3])
        : "r"(a0), "r"(a1), "r"(a2), "r"(a3), "r"(b0), "r"(b1));
}
__device__ __forceinline__ void cp16(uint32_t dst, const void* src) {
    asm volatile("cp.async.cg.shared.global [%0],[%1],16;" ::"r"(dst), "l"(src)
                 : "memory");
}
#define CP_COMMIT asm volatile("cp.async.commit_group;" ::: "memory")
__device__ __forceinline__ void ldpair(void* sdst, const __half* g) {
    uint32_t d = (uint32_t)__cvta_generic_to_shared(sdst);
    cp16(d, g);
    cp16(d + 16, g + 8);
}

// ---------------- merged input convert: [L,B,D]->(+add)->[B,L,D] f16 ------------
// ranges: Q float4s [0, 524288), K [524288, 2621440), V [2621440, 4718592)
__global__ void cvtx_all_kernel(const float* __restrict__ tgt,
                                const float* __restrict__ mem,
                                const float* __restrict__ pos,
                                const float* __restrict__ qpos) {
    long idx = (long)blockIdx.x * blockDim.x + threadIdx.x;
    const float* in1;
    const float* in2;
    __half* out;
    int L;
    if (idx < 524288L) {
        in1 = tgt; in2 = qpos; out = g_Xq16; L = LQ;
    } else if (idx < 2621440L) {
        idx -= 524288L;
        in1 = mem; in2 = pos; out = g_Xk16; L = LK;
    } else {
        idx -= 2621440L;
        in1 = mem; in2 = (const float*)0; out = g_Xv16; L = LK;
    }
    int d4 = (int)(idx & 63);
    long m = idx >> 6;
    int b = (int)(m / L);
    int l = (int)(m - (long)b * L);
    float4 v = ((const float4*)in1)[((size_t)l * Bb + b) * 64 + d4];
    if (in2) {
        float4 w = ((const float4*)in2)[((size_t)l * Bb + b) * 64 + d4];
        v.x += w.x; v.y += w.y; v.z += w.z; v.w += w.w;
    }
    __half2 h0 = __floats2half2_rn(v.x, v.y);
    __half2 h1 = __floats2half2_rn(v.z, v.w);
    uint2 u;
    u.x = *(uint32_t*)&h0;
    u.y = *(uint32_t*)&h1;
    ((uint2*)out)[idx] = u;
}

__global__ void cvtw_all_kernel(const float* __restrict__ Wq,
                                const float* __restrict__ Wk,
                                const float* __restrict__ Wv) {
    int sel = blockIdx.y;
    const float* src = (sel == 0) ? Wq : (sel == 1) ? Wk : Wv;
    __half* out = g_W16 + (size_t)sel * HD * Dm;
    int idx = blockIdx.x * blockDim.x + threadIdx.x;  // one float4
    float4 v = ((const float4*)src)[idx];
    __half2 h0 = __floats2half2_rn(v.x, v.y);
    __half2 h1 = __floats2half2_rn(v.z, v.w);
    uint2 u;
    u.x = *(uint32_t*)&h0;
    u.y = *(uint32_t*)&h1;
    ((uint2*)out)[idx] = u;
}

// ---------------- merged projection GEMM (raw mma, direct-register epilogue) ----
// blockIdx.x in [0,576): [0,64)=Q m-blocks, [64,320)=K, [320,576)=V
__global__ __launch_bounds__(256, 2) void proj_all_kernel() {
    int bx = blockIdx.x;
    int sel, mblk;
    if (bx < 64) { sel = 0; mblk = bx; }
    else if (bx < 320) { sel = 1; mblk = bx - 64; }
    else { sel = 2; mblk = bx - 320; }
    int L = sel ? LK : LQ;
    const __half* X = (sel == 0) ? g_Xq16 : (sel == 1) ? g_Xk16 : g_Xv16;
    const __half* W = g_W16 + (size_t)sel * HD * Dm;
    __half* out = (sel == 0) ? g_Q16 : (sel == 1) ? g_K16 : g_V16;

    __shared__ __half As[2][128][40];
    __shared__ __half Bs[2][128][40];

    int m0 = mblk * 128, n0 = blockIdx.y * 128;
    int b = m0 / L, l0 = m0 % L;
    int tid = threadIdx.x, wid = tid >> 5, lane = tid & 31;
    int wm = wid & 1, wn = wid >> 1;
    int r = tid >> 1, cseg = (tid & 1) * 16;

    float c[4][4][4];
#pragma unroll
    for (int i = 0; i < 4; i++)
#pragma unroll
        for (int j = 0; j < 4; j++)
            c[i][j][0] = c[i][j][1] = c[i][j][2] = c[i][j][3] = 0.f;

    uint32_t AsB = (uint32_t)__cvta_generic_to_shared(&As[0][0][0]);
    uint32_t BsB = (uint32_t)__cvta_generic_to_shared(&Bs[0][0][0]);
    const uint32_t Aoff = (uint32_t)(wm * 64 + (lane & 15)) * 80 + ((lane >> 4) << 4);
    const uint32_t Boff = (uint32_t)(wn * 32 + ((lane >> 4) << 3) + (lane & 7)) * 80 +
                          (((lane >> 3) & 1) << 4);

#pragma unroll
    for (int pre = 0; pre < 2; pre++) {
        int kc = pre * 32;
        ldpair(&As[pre][r][cseg], X + (size_t)(m0 + r) * 256 + kc + cseg);
        ldpair(&Bs[pre][r][cseg], W + (size_t)(n0 + r) * 256 + kc + cseg);
        CP_COMMIT;
    }

    for (int ic = 0; ic < 8; ic++) {
        int cur = ic & 1;
        if (ic < 7)
            asm volatile("cp.async.wait_group 1;" ::: "memory");
        else
            asm volatile("cp.async.wait_group 0;" ::: "memory");
        __syncthreads();
        uint32_t ab = AsB + cur * 10240, bb = BsB + cur * 10240;
#pragma unroll
        for (int ks = 0; ks < 2; ks++) {
            uint32_t a[4][4];
#pragma unroll
            for (int i = 0; i < 4; i++)
                ldsm4(a[i][0], a[i][1], a[i][2], a[i][3],
                      ab + Aoff + i * 16 * 80 + ks * 32);
#pragma unroll
            for (int jp = 0; jp < 4; jp += 2) {
                uint32_t b0, b1, b2, b3;
                ldsm4(b0, b1, b2, b3, bb + Boff + jp * 8 * 80 + ks * 32);
#pragma unroll
                for (int i = 0; i < 4; i++) {
                    mma16816(c[i][jp], a[i][0], a[i][1], a[i][2], a[i][3], b0, b1);
                    mma16816(c[i][jp + 1], a[i][0], a[i][1], a[i][2], a[i][3], b2, b3);
                }
            }
        }
        __syncthreads();
        if (ic + 2 < 8) {
            int kc = (ic + 2) * 32;
            ldpair(&As[cur][r][cseg], X + (size_t)(m0 + r) * 256 + kc + cseg);
            ldpair(&Bs[cur][r][cseg], W + (size_t)(n0 + r) * 256 + kc + cseg);
        }
        CP_COMMIT;
    }

    int h = n0 >> 8, e0 = n0 & 255;
    int rq = lane >> 2, t2 = (lane & 3) * 2;
#pragma unroll
    for (int i = 0; i < 4; i++) {
        size_t rowA = (size_t)(b * Hh + h) * L + l0 + wm * 64 + i * 16 + rq;
#pragma unroll
        for (int j = 0; j < 4; j++) {
            int colb = e0 + wn * 32 + j * 8 + t2;
            *(__half2*)(out + rowA * 256 + colb) =
                __floats2half2_rn(c[i][j][0], c[i][j][1]);
            *(__half2*)(out + (rowA + 8) * 256 + colb) =
                __floats2half2_rn(c[i][j][2], c[i][j][3]);
        }
    }
}

// ---------------- attn_mean = (scale/H) * sum_h Q_h K_h^T  (raw mma, K=1024) ------
// Same mainloop structure as proj_all_kernel (non-trans ldsm4 + paired-n B loads);
// iterates (h, kc) chunks; fp32 direct-register epilogue.
__global__ __launch_bounds__(256, 2) void mean_kernel(float* __restrict__ out,
                                                      int zoff) {
    __shared__ __half As[2][128][40];
    __shared__ __half Bs[2][128][40];

    int q0 = blockIdx.x * 128, k0 = blockIdx.y * 128, b = blockIdx.z + zoff;
    int tid = threadIdx.x, wid = tid >> 5, lane = tid & 31;
    int wm = wid & 1, wn = wid >> 1;
    int r = tid >> 1, cseg = (tid & 1) * 16;

    float c[4][4][4];
#pragma unroll
    for (int i = 0; i < 4; i++)
#pragma unroll
        for (int j = 0; j < 4; j++)
            c[i][j][0] = c[i][j][1] = c[i][j][2] = c[i][j][3] = 0.f;

    uint32_t AsB = (uint32_t)__cvta_generic_to_shared(&As[0][0][0]);
    uint32_t BsB = (uint32_t)__cvta_generic_to_shared(&Bs[0][0][0]);
    const uint32_t Aoff = (uint32_t)(wm * 64 + (lane & 15)) * 80 + ((lane >> 4) << 4);
    const uint32_t Boff = (uint32_t)(wn * 32 + ((lane >> 4) << 3) + (lane & 7)) * 80 +
                          (((lane >> 3) & 1) << 4);

#pragma unroll
    for (int pre = 0; pre < 2; pre++) {
        int h = pre >> 3, kc = (pre & 7) * 32;
        ldpair(&As[pre][r][cseg],
               g_Q16 + ((size_t)(b * Hh + h) * LQ + q0 + r) * 256 + kc + cseg);
        ldpair(&Bs[pre][r][cseg],
               g_K16 + ((size_t)(b * Hh + h) * LK + k0 + r) * 256 + kc + cseg);
        CP_COMMIT;
    }

    for (int ic = 0; ic < 32; ic++) {
        int cur = ic & 1;
        if (ic < 31)
            asm volatile("cp.async.wait_group 1;" ::: "memory");
        else
            asm volatile("cp.async.wait_group 0;" ::: "memory");
        __syncthreads();
        uint32_t ab = AsB + cur * 10240, bb = BsB + cur * 10240;
#pragma unroll
        for (int ks = 0; ks < 2; ks++) {
            uint32_t a[4][4];
#pragma unroll
            for (int i = 0; i < 4; i++)
                ldsm4(a[i][0], a[i][1], a[i][2], a[i][3],
                      ab + Aoff + i * 16 * 80 + ks * 32);
#pragma unroll
            for (int jp = 0; jp < 4; jp += 2) {
                uint32_t b0, b1, b2, b3;
                ldsm4(b0, b1, b2, b3, bb + Boff + jp * 8 * 80 + ks * 32);
#pragma unroll
                for (int i = 0; i < 4; i++) {
                    mma16816(c[i][jp], a[i][0], a[i][1], a[i][2], a[i][3], b0, b1);
                    mma16816(c[i][jp + 1], a[i][0], a[i][1], a[i][2], a[i][3], b2, b3);
                }
            }
        }
        __syncthreads();
        if (ic + 2 < 32) {
            int nc = ic + 2;
            int h = nc >> 3, kc = (nc & 7) * 32;
            ldpair(&As[cur][r][cseg],
                   g_Q16 + ((size_t)(b * Hh + h) * LQ + q0 + r) * 256 + kc + cseg);
            ldpair(&Bs[cur][r][cseg],
                   g_K16 + ((size_t)(b * Hh + h) * LK + k0 + r) * 256 + kc + cseg);
        }
        CP_COMMIT;
    }

    // fp32 direct-register epilogue (documented C-fragment layout), float2 stores
    const float MSC = 0.015625f;  // (1/16)/4
    int rq = lane >> 2, t2 = (lane & 3) * 2;
#pragma unroll
    for (int i = 0; i < 4; i++) {
        float* po0 = out + ((size_t)b * LQ + q0 + wm * 64 + i * 16 + rq) * LK + k0;
        float* po1 = po0 + (size_t)8 * LK;
#pragma unroll
        for (int j = 0; j < 4; j++) {
            int colb = wn * 32 + j * 8 + t2;
            float2 u0, u1;
            u0.x = c[i][j][0] * MSC; u0.y = c[i][j][1] * MSC;
            u1.x = c[i][j][2] * MSC; u1.y = c[i][j][3] * MSC;
            *(float2*)(po0 + colb) = u0;
            *(float2*)(po1 + colb) = u1;
        }
    }
}

// ---------------- flash attention v5: QT=128, warp-owned q-rows, no merge --------
#define FLASH_SMEM 202752
#define OF_Q 0
#define OF_K 67584
#define OF_V 135168
#define KROW 528  // bytes per 256-half row (+16B pad)

__device__ __forceinline__ void load_rows64(uint32_t dst, const __half* src,
                                            int tid) {
#pragma unroll
    for (int i = 0; i < 8; i++) {
        int t = tid + i * 256;
        int row = t >> 5, cc = t & 31;
        cp16(dst + row * KROW + cc * 16, src + (size_t)row * 256 + cc * 8);
    }
}
__device__ __forceinline__ void load_rows128(uint32_t dst, const __half* src,
                                             int tid) {
#pragma unroll
    for (int i = 0; i < 16; i++) {
        int t = tid + i * 256;
        int row = t >> 5, cc = t & 31;
        cp16(dst + row * KROW + cc * 16, src + (size_t)row * 256 + cc * 8);
    }
}

__global__ __launch_bounds__(256, 1) void flash_kernel() {
    extern __shared__ __align__(16) char dynsm[];
    char* sm = dynsm;
    int tid = threadIdx.x, lane = tid & 31, wid = tid >> 5;
    int q0 = blockIdx.x * 128;
    int bh = blockIdx.y;
    int b = bh >> 2, h = bh & 3;
    const __half* Qg = g_Q16 + ((size_t)bh * LQ + q0) * 256;
    const __half* Kg = g_K16 + (size_t)bh * LK * 256;
    const __half* Vg = g_V16 + (size_t)bh * LK * 256;

    uint32_t sb = (uint32_t)__cvta_generic_to_shared(sm);
    const uint32_t QB = sb + OF_Q, KB = sb + OF_K, VB = sb + OF_V;

    load_rows128(QB, Qg, tid);
    load_rows64(KB, Kg, tid);
    load_rows64(VB, Vg, tid);
    CP_COMMIT;
    load_rows64(KB + 33792, Kg + 64 * 256, tid);
    load_rows64(VB + 33792, Vg + 64 * 256, tid);
    CP_COMMIT;

    float o[32][4];
#pragma unroll
    for (int j = 0; j < 32; j++) o[j][0] = o[j][1] = o[j][2] = o[j][3] = 0.f;
    float mr0 = -1e30f, mr1 = -1e30f, l0 = 0.f, l1 = 0.f;
    const float SLOG = 0.0901699438f;  // (1/16)*log2(e)

    const uint32_t Aq = QB + (uint32_t)(wid * 16 + (lane & 15)) * KROW +
                        ((lane >> 4) << 4);
    const uint32_t Kb2 = (uint32_t)(((lane >> 4) << 3) + (lane & 7)) * KROW +
                         (((lane >> 3) & 1) << 4);
    const uint32_t Vb2 = (uint32_t)(lane & 15) * KROW + ((lane >> 4) << 4);

    for (int it = 0; it < LK / 64; it++) {
        int cur = it & 1;
        if (it < LK / 64 - 1)
            asm volatile("cp.async.wait_group 1;" ::: "memory");
        else
            asm volatile("cp.async.wait_group 0;" ::: "memory");
        __syncthreads();

        // S = Q K^T : 16 q-rows x 64 keys per warp
        uint32_t kb = KB + cur * 33792;
        float s[8][4];
#pragma unroll
        for (int j = 0; j < 8; j++) s[j][0] = s[j][1] = s[j][2] = s[j][3] = 0.f;
#pragma unroll
        for (int dk = 0; dk < 16; dk++) {
            uint32_t a0, a1, a2, a3;
            ldsm4(a0, a1, a2, a3, Aq + dk * 32);
#pragma unroll
            for (int jp = 0; jp < 8; jp += 2) {
                uint32_t b0, b1, b2, b3;
                ldsm4(b0, b1, b2, b3, kb + Kb2 + jp * 8 * KROW + dk * 32);
                mma16816(s[jp], a0, a1, a2, a3, b0, b1);
                mma16816(s[jp + 1], a0, a1, a2, a3, b2, b3);
            }
        }

        // warp-private online softmax (quad shuffles only)
        float pm0 = -1e30f, pm1 = -1e30f;
#pragma unroll
        for (int j = 0; j < 8; j++) {
            s[j][0] *= SLOG; s[j][1] *= SLOG; s[j][2] *= SLOG; s[j][3] *= SLOG;
            pm0 = fmaxf(pm0, fmaxf(s[j][0], s[j][1]));
            pm1 = fmaxf(pm1, fmaxf(s[j][2], s[j][3]));
        }
        pm0 = fmaxf(pm0, __shfl_xor_sync(~0u, pm0, 1));
        pm0 = fmaxf(pm0, __shfl_xor_sync(~0u, pm0, 2));
        pm1 = fmaxf(pm1, __shfl_xor_sync(~0u, pm1, 1));
        pm1 = fmaxf(pm1, __shfl_xor_sync(~0u, pm1, 2));
        float mn0 = fmaxf(mr0, pm0), mn1 = fmaxf(mr1, pm1);
        float al0 = ex2f(mr0 - mn0), al1 = ex2f(mr1 - mn1);
        mr0 = mn0; mr1 = mn1;

        // P = exp2(S - m) in place, accumulate row sums
        float ps0 = 0.f, ps1 = 0.f;
#pragma unroll
        for (int j = 0; j < 8; j++) {
            s[j][0] = ex2f(s[j][0] - mn0);
            s[j][1] = ex2f(s[j][1] - mn0);
            s[j][2] = ex2f(s[j][2] - mn1);
            s[j][3] = ex2f(s[j][3] - mn1);
            ps0 += s[j][0] + s[j][1];
            ps1 += s[j][2] + s[j][3];
        }
        ps0 += __shfl_xor_sync(~0u, ps0, 1);
        ps0 += __shfl_xor_sync(~0u, ps0, 2);
        ps1 += __shfl_xor_sync(~0u, ps1, 1);
        ps1 += __shfl_xor_sync(~0u, ps1, 2);
        l0 = al0 * l0 + ps0;
        l1 = al1 * l1 + ps1;
#pragma unroll
        for (int j = 0; j < 32; j++) {
            o[j][0] *= al0; o[j][1] *= al0; o[j][2] *= al1; o[j][3] *= al1;
        }

        // O += P @ V  (4 k-chunks of 16; P packed to A-fragments on the fly)
        uint32_t vb = VB + cur * 33792;
#pragma unroll
        for (int ks = 0; ks < 4; ks++) {
            uint32_t pa0 = packh2(s[2 * ks][0], s[2 * ks][1]);
            uint32_t pa1 = packh2(s[2 * ks][2], s[2 * ks][3]);
            uint32_t pa2 = packh2(s[2 * ks + 1][0], s[2 * ks + 1][1]);
            uint32_t pa3 = packh2(s[2 * ks + 1][2], s[2 * ks + 1][3]);
            uint32_t vrow = vb + Vb2 + ks * 16 * KROW;
#pragma unroll
            for (int jp = 0; jp < 32; jp += 2) {
                uint32_t b0, b1, b2, b3;
                ldsm4t(b0, b1, b2, b3, vrow + jp * 16);
                mma16816(o[jp], pa0, pa1, pa2, pa3, b0, b1);
                mma16816(o[jp + 1], pa0, pa1, pa2, pa3, b2, b3);
            }
        }
        __syncthreads();
        if (it + 2 < LK / 64) {
            load_rows64(KB + cur * 33792, Kg + (size_t)(it + 2) * 64 * 256, tid);
            load_rows64(VB + cur * 33792, Vg + (size_t)(it + 2) * 64 * 256, tid);
        }
        CP_COMMIT;
    }

    // ---- epilogue: direct store (warp owns its q-rows end-to-end) ----
    int rq = lane >> 2, t2 = (lane & 3) * 2;
    float inv0 = 1.f / l0, inv1 = 1.f / l1;
    size_t ob0 = ((size_t)b * LQ + q0 + wid * 16 + rq) * HD + h * 256 + t2;
    size_t ob1 = ob0 + (size_t)8 * HD;
#pragma unroll
    for (int j = 0; j < 32; j++) {
        *(__half2*)(g_O + ob0 + j * 8) =
            __floats2half2_rn(o[j][0] * inv0, o[j][1] * inv0);
        *(__half2*)(g_O + ob1 + j * 8) =
            __floats2half2_rn(o[j][2] * inv1, o[j][3] * inv1);
    }
}

// ---------------- fc + residual + LayerNorm (f16 GEMM) ----------------
__global__ __launch_bounds__(256) void fc_ln_kernel(const float* __restrict__ Wfc,
                                                    const float* __restrict__ tgt,
                                                    const float* __restrict__ gamma,
                                                    const float* __restrict__ beta,
                                                    float* __restrict__ Y) {
    __shared__ __align__(16) unsigned char smraw[33280];
    __half* As = (__half*)smraw;             // [32][48]
    __half* Bsh = (__half*)(smraw + 3072);   // [256][48]
    float* stage = (float*)smraw;            // [32][260]

    int m0 = blockIdx.x * 32;
    int tid = threadIdx.x, wid = tid >> 5, lane = tid & 31;
    int wm = wid & 1, wn = wid >> 1;

    wmma::fragment<wmma::accumulator, 16, 16, 16, float> c[4];
#pragma unroll
    for (int j = 0; j < 4; j++) wmma::fill_fragment(c[j], 0.0f);

    for (int kc = 0; kc < HD; kc += 32) {
        int r = tid >> 3, cb = (tid & 7) << 2;
        *(uint2*)&As[r * 48 + cb] =
            *(const uint2*)&g_O[(size_t)(m0 + r) * HD + kc + cb];
#pragma unroll
        for (int p = 0; p < 8; p++) {
            int rr = r + p * 32;
            float4 w = *(const float4*)&Wfc[(size_t)rr * HD + kc + cb];
            *(__half2*)&Bsh[rr * 48 + cb] = __floats2half2_rn(w.x, w.y);
            *(__half2*)&Bsh[rr * 48 + cb + 2] = __floats2half2_rn(w.z, w.w);
        }
        __syncthreads();
#pragma unroll
        for (int ks = 0; ks < 2; ks++) {
            wmma::fragment<wmma::matrix_a, 16, 16, 16, __half, wmma::row_major> af;
            wmma::load_matrix_sync(af, &As[(wm * 16) * 48 + ks * 16], 48);
#pragma unroll
            for (int j = 0; j < 4; j++) {
                wmma::fragment<wmma::matrix_b, 16, 16, 16, __half,
                               wmma::col_major> bfr;
                wmma::load_matrix_sync(bfr, &Bsh[(wn * 64 + j * 16) * 48 + ks * 16],
                                       48);
                wmma::mma_sync(c[j], af, bfr, c[j]);
            }
        }
        __syncthreads();
    }

#pragma unroll
    for (int j = 0; j < 4; j++)
        wmma::store_matrix_sync(&stage[(wm * 16) * 260 + wn * 64 + j * 16], c[j],
                                260, wmma::mem_row_major);
    __syncthreads();

#pragma unroll
    for (int s = 0; s < 4; s++) {
        int row = wid * 4 + s;
        int m = m0 + row;
        int b = m >> 10, l = m & 1023;
        const float* trow = tgt + ((size_t)l * Bb + b) * 256;
        float v[8], sum = 0.f, sq = 0.f;
#pragma unroll
        for (int t = 0; t < 8; t++) {
            v[t] = stage[row * 260 + lane * 8 + t] + trow[lane * 8 + t];
            sum += v[t];
            sq += v[t] * v[t];
        }
#pragma unroll
        for (int oo = 16; oo > 0; oo >>= 1) {
            sum += __shfl_xor_sync(~0u, sum, oo);
            sq += __shfl_xor_sync(~0u, sq, oo);
        }
        float mu = sum * (1.0f / 256.0f);
        float var = sq * (1.0f / 256.0f) - mu * mu;
        float rsg = rsqrtf(var + 1e-5f);
        float* yr = Y + ((size_t)l * Bb + b) * 256;
#pragma unroll
        for (int t = 0; t < 8; t++) {
            int d = lane * 8 + t;
            yr[d] = (v[t] - mu) * rsg * gamma[d] + beta[d];
        }
    }
}

// ---------------- launch ----------------
extern "C" void kernel_launch(void* const* d_in, const int* in_sizes, int n_in,
                              void* d_out, int out_size) {
    const float* tgt  = (const float*)d_in[0];
    const float* mem  = (const float*)d_in[1];
    const float* pos  = (const float*)d_in[2];
    const float* qpos = (const float*)d_in[3];
    const float* Wq   = (const float*)d_in[4];
    const float* Wk   = (const float*)d_in[5];
    const float* Wv   = (const float*)d_in[6];
    const float* Wfc  = (const float*)d_in[7];
    const float* ln_g = (const float*)d_in[8];
    const float* ln_b = (const float*)d_in[9];

    float* y_out    = (float*)d_out;                         // [LQ,B,D]
    float* attn_out = (float*)d_out + (size_t)LQ * Bb * Dm;  // [B,1,LQ,LK]

    cudaFuncSetAttribute(flash_kernel,
                         cudaFuncAttributeMaxDynamicSharedMemorySize, FLASH_SMEM);

    // [0] merged input convert (Q|K|V ranges)
    cvtx_all_kernel<<<18432, 256>>>(tgt, mem, pos, qpos);
    // [1] merged weight convert
    cvtw_all_kernel<<<dim3(256, 3), 256>>>(Wq, Wk, Wv);
    // [2] merged projections (Q|K|V m-block ranges)
    proj_all_kernel<<<dim3(576, 8), 256>>>();
    // [3][4] attn_mean in two z-halves (raw mma)
    mean_kernel<<<dim3(LQ / 128, LK / 128, 4), 256>>>(attn_out, 0);
    mean_kernel<<<dim3(LQ / 128, LK / 128, 4), 256>>>(attn_out, 4);
    // [5] flash attention
    flash_kernel<<<dim3(LQ / 128, Bb * Hh), 256, FLASH_SMEM>>>();
    // [6] fc + residual + layernorm
    fc_ln_kernel<<<(Bb * LQ) / 32, 256>>>(Wfc, tgt, ln_g, ln_b, y_out);
}